// round 2
// baseline (speedup 1.0000x reference)
#include <cuda_runtime.h>
#include <math.h>

// ---------------------------------------------------------------------------
// Problem dims
// ---------------------------------------------------------------------------
#define BB 512
#define SS 79
#define EE 1024
#define HH 16
#define DD 64
#define CC 32
#define MM 256
#define BS (BB*SS)          // 40448
#define SC (SS*CC)          // 2528
#define S2 (SS*SS)          // 6241

// ---------------------------------------------------------------------------
// Scratch (device globals; no runtime allocation allowed)
// ---------------------------------------------------------------------------
__device__ __align__(128) float g_wqs [EE*EE];          // scaled w_q
__device__ __align__(128) float g_wsum[HH*DD];          // sum_e w_a[h,d,e]
__device__ __align__(128) float g_q   [(size_t)BS*EE];  // q (already * wsum)
__device__ __align__(128) float g_k   [(size_t)BS*EE];
__device__ __align__(128) float g_v   [(size_t)BS*EE];
__device__ __align__(128) float g_attn[(size_t)BB*HH*S2];
__device__ __align__(128) float g_comp[(size_t)BB*SC];
__device__ __align__(128) float g_pos [(size_t)BB*MM];
__device__ __align__(128) float g_head[(size_t)BB*HH*MM];
__device__ __align__(128) float g_ao  [(size_t)BS*EE];

// ---------------------------------------------------------------------------
// w_a row-sum:  wsum[h*64+d] = sum_e w_a[h][d][e]
// ---------------------------------------------------------------------------
__global__ void wsum_kernel(const float* __restrict__ wa, float* __restrict__ wsum)
{
    int i = blockIdx.x * blockDim.x + threadIdx.x;
    if (i < HH*DD) {
        const float* p = wa + (size_t)i * DD;
        float s = 0.f;
        #pragma unroll
        for (int e = 0; e < DD; e++) s += p[e];
        wsum[i] = s;
    }
}

// wqs[r][c] = w_q[r][c] * wsum[c]   (c = h*64+d, same layout as wsum)
__global__ void scale_wq_kernel(const float* __restrict__ wq,
                                const float* __restrict__ wsum,
                                float* __restrict__ wqs)
{
    int idx = blockIdx.x * blockDim.x + threadIdx.x;
    if (idx < EE*EE) {
        int c = idx & (EE-1);
        wqs[idx] = wq[idx] * wsum[c];
    }
}

// ---------------------------------------------------------------------------
// Fast SGEMM: C[M,N] = A[M,K] @ B[K,N], all row-major.
// Requires M%128==0, N%128==0, K%8==0.  128x128 tile, 256 threads, 8x8 micro.
// ---------------------------------------------------------------------------
__global__ __launch_bounds__(256, 2)
void sgemm128(const float* __restrict__ A, const float* __restrict__ B,
              float* __restrict__ C, int M, int N, int K)
{
    __shared__ float As[8][128];
    __shared__ float Bs[8][128];

    const int tid = threadIdx.x;
    const long long brow = blockIdx.y, bcol = blockIdx.x;
    A += brow * 128 * K;
    B += bcol * 128;
    C += brow * 128 * N + bcol * 128;

    const int arow = tid >> 1, acol = (tid & 1) * 4;
    const int brw  = tid >> 5, bcl  = (tid & 31) * 4;
    const int tx = tid & 15, ty = tid >> 4;

    float acc[8][8];
    #pragma unroll
    for (int i = 0; i < 8; i++)
        #pragma unroll
        for (int j = 0; j < 8; j++) acc[i][j] = 0.f;

    for (int k0 = 0; k0 < K; k0 += 8) {
        float4 a = *(const float4*)(A + (long long)arow * K + k0 + acol);
        As[acol+0][arow] = a.x;
        As[acol+1][arow] = a.y;
        As[acol+2][arow] = a.z;
        As[acol+3][arow] = a.w;
        float4 b = *(const float4*)(B + (long long)(k0 + brw) * N + bcl);
        *(float4*)(&Bs[brw][bcl]) = b;
        __syncthreads();

        #pragma unroll
        for (int k = 0; k < 8; k++) {
            float ra[8], rb[8];
            #pragma unroll
            for (int i = 0; i < 8; i++) ra[i] = As[k][ty*8 + i];
            #pragma unroll
            for (int j = 0; j < 8; j++) rb[j] = Bs[k][tx*8 + j];
            #pragma unroll
            for (int i = 0; i < 8; i++)
                #pragma unroll
                for (int j = 0; j < 8; j++) acc[i][j] += ra[i] * rb[j];
        }
        __syncthreads();
    }

    #pragma unroll
    for (int i = 0; i < 8; i++) {
        float* crow = C + (long long)(ty*8 + i) * N + tx*8;
        #pragma unroll
        for (int j = 0; j < 8; j += 4) {
            float4 v = make_float4(acc[i][j], acc[i][j+1], acc[i][j+2], acc[i][j+3]);
            *(float4*)(crow + j) = v;
        }
    }
}

// ---------------------------------------------------------------------------
// Generic strided/batched SGEMM with optional bias + SiLU epilogue.
// 64x64x16 tiles, 256 threads, 4x4 micro-tile. Fully bounds-checked.
// ---------------------------------------------------------------------------
__global__ __launch_bounds__(256)
void sgemm_gen(const float* __restrict__ A, const float* __restrict__ B,
               float* __restrict__ C,
               int M, int N, int K, int lda, int ldb, int ldc,
               long long aBatch, long long bBatch, long long cBatch,
               const float* __restrict__ bias, long long biasBatch, int act)
{
    __shared__ float As[16][64];
    __shared__ float Bs[16][64];

    const int bz = blockIdx.z;
    A += (long long)bz * aBatch;
    B += (long long)bz * bBatch;
    C += (long long)bz * cBatch;
    const float* biasp = bias ? bias + (long long)bz * biasBatch : nullptr;

    const int row0 = blockIdx.y * 64, col0 = blockIdx.x * 64;
    const int tid = threadIdx.x;
    const int tx = tid & 15, ty = tid >> 4;

    float acc[4][4] = {};

    for (int k0 = 0; k0 < K; k0 += 16) {
        #pragma unroll
        for (int i = 0; i < 4; i++) {
            int lin = tid + i * 256;
            int ar = lin >> 4, ac = lin & 15;
            int gr = row0 + ar, gc = k0 + ac;
            As[ac][ar] = (gr < M && gc < K) ? A[(long long)gr * lda + gc] : 0.f;
        }
        #pragma unroll
        for (int i = 0; i < 4; i++) {
            int lin = tid + i * 256;
            int br = lin >> 6, bc = lin & 63;
            int gr = k0 + br, gc = col0 + bc;
            Bs[br][bc] = (gr < K && gc < N) ? B[(long long)gr * ldb + gc] : 0.f;
        }
        __syncthreads();
        #pragma unroll
        for (int k = 0; k < 16; k++) {
            float ra[4], rb[4];
            #pragma unroll
            for (int i = 0; i < 4; i++) ra[i] = As[k][ty*4 + i];
            #pragma unroll
            for (int j = 0; j < 4; j++) rb[j] = Bs[k][tx*4 + j];
            #pragma unroll
            for (int i = 0; i < 4; i++)
                #pragma unroll
                for (int j = 0; j < 4; j++) acc[i][j] += ra[i] * rb[j];
        }
        __syncthreads();
    }

    #pragma unroll
    for (int i = 0; i < 4; i++) {
        int gr = row0 + ty*4 + i;
        if (gr >= M) continue;
        #pragma unroll
        for (int j = 0; j < 4; j++) {
            int gc = col0 + tx*4 + j;
            if (gc >= N) continue;
            float v = acc[i][j];
            if (biasp) v += biasp[gc];
            if (act == 1) v = v / (1.f + __expf(-v));   // SiLU
            C[(long long)gr * ldc + gc] = v;
        }
    }
}

// ---------------------------------------------------------------------------
// Scores: attn[b,h,t,T] += (q'[b,t,h,:] . k[b,T,h,:]) / 8
// (q' already contains the folded w_a row-sum.)  One block per (b,h).
// ---------------------------------------------------------------------------
__global__ __launch_bounds__(256)
void score_kernel(const float* __restrict__ q, const float* __restrict__ k,
                  float* __restrict__ attn)
{
    __shared__ float qs[SS][65];
    __shared__ float ks[SS][65];

    const int h = blockIdx.x, b = blockIdx.y;
    const int tid = threadIdx.x;
    const float* qb = q + (long long)b * SS * EE + h * DD;
    const float* kb = k + (long long)b * SS * EE + h * DD;

    for (int idx = tid; idx < SS*DD; idx += 256) {
        int r = idx >> 6, c = idx & 63;
        qs[r][c] = qb[(long long)r * EE + c];
        ks[r][c] = kb[(long long)r * EE + c];
    }
    __syncthreads();

    float* ab = attn + (long long)(b * HH + h) * S2;
    for (int idx = tid; idx < S2; idx += 256) {
        int t = idx / SS, T = idx - t * SS;
        float s = 0.f;
        #pragma unroll
        for (int d = 0; d < DD; d++) s += qs[t][d] * ks[T][d];
        ab[idx] = fmaf(s, 0.125f, ab[idx]);
    }
}

// ---------------------------------------------------------------------------
// Softmax over last dim (79). One warp per row.
// ---------------------------------------------------------------------------
__global__ __launch_bounds__(256)
void softmax_kernel(float* __restrict__ attn, int nrows)
{
    int warp = (blockIdx.x * blockDim.x + threadIdx.x) >> 5;
    int lane = threadIdx.x & 31;
    if (warp >= nrows) return;
    float* row = attn + (long long)warp * SS;

    bool v1 = (lane + 32) < SS, v2 = (lane + 64) < SS;
    float x0 = row[lane];
    float x1 = v1 ? row[lane + 32] : -3.0e38f;
    float x2 = v2 ? row[lane + 64] : -3.0e38f;

    float m = fmaxf(x0, fmaxf(x1, x2));
    #pragma unroll
    for (int o = 16; o > 0; o >>= 1) m = fmaxf(m, __shfl_xor_sync(0xffffffffu, m, o));

    float e0 = __expf(x0 - m);
    float e1 = v1 ? __expf(x1 - m) : 0.f;
    float e2 = v2 ? __expf(x2 - m) : 0.f;
    float s = e0 + e1 + e2;
    #pragma unroll
    for (int o = 16; o > 0; o >>= 1) s += __shfl_xor_sync(0xffffffffu, s, o);

    float inv = 1.f / s;
    row[lane] = e0 * inv;
    if (v1) row[lane + 32] = e1 * inv;
    if (v2) row[lane + 64] = e2 * inv;
}

// ---------------------------------------------------------------------------
// P @ V:  ao[b,t,h,d] = sum_T p[b,h,t,T] * v[b,T,h,d].  One block per (b,h).
// ---------------------------------------------------------------------------
__global__ __launch_bounds__(256)
void pv_kernel(const float* __restrict__ attn, const float* __restrict__ v,
               float* __restrict__ ao)
{
    __shared__ float vs[SS*DD];     // 20224 B
    __shared__ float ps[S2];        // 24964 B

    const int h = blockIdx.x, b = blockIdx.y;
    const int tid = threadIdx.x;

    const float* vb = v + (long long)b * SS * EE + h * DD;
    for (int idx = tid; idx < SS*DD; idx += 256) {
        int r = idx >> 6, c = idx & 63;
        vs[idx] = vb[(long long)r * EE + c];
    }
    const float* ab = attn + (long long)(b * HH + h) * S2;
    for (int idx = tid; idx < S2; idx += 256) ps[idx] = ab[idx];
    __syncthreads();

    const int d = tid & 63, tg = tid >> 6;
    float* ob = ao + (long long)b * SS * EE + h * DD;
    for (int t = tg; t < SS; t += 4) {
        float s = 0.f;
        const float* pr = ps + t * SS;
        #pragma unroll
        for (int T = 0; T < SS; T++) s += pr[T] * vs[T*DD + d];
        ob[(long long)t * EE + d] = s;
    }
}

// ---------------------------------------------------------------------------
// Launch
// ---------------------------------------------------------------------------
extern "C" void kernel_launch(void* const* d_in, const int* in_sizes, int n_in,
                              void* d_out, int out_size)
{
    const float* inq   = (const float*)d_in[0];
    const float* inkv  = (const float*)d_in[1];
    const float* wq    = (const float*)d_in[2];
    const float* wk    = (const float*)d_in[3];
    const float* wv    = (const float*)d_in[4];
    const float* wo    = (const float*)d_in[5];
    const float* wa    = (const float*)d_in[6];
    const float* wcmp  = (const float*)d_in[7];
    const float* wpos  = (const float*)d_in[8];
    const float* bpos  = (const float*)d_in[9];
    const float* whead = (const float*)d_in[10];
    const float* bhead = (const float*)d_in[11];
    const float* sproj = (const float*)d_in[12];
    float* out = (float*)d_out;

    // CRITICAL: resolve device addresses of __device__ globals. Passing the
    // symbol directly from host code hands kernels the HOST shadow address,
    // which on GB300 (ATS) is silently dereferenceable -> wrong data, no fault.
    float *q, *k, *v, *attn, *ao, *wqs, *wsum, *comp, *pos, *head;
    cudaGetSymbolAddress((void**)&q,    g_q);
    cudaGetSymbolAddress((void**)&k,    g_k);
    cudaGetSymbolAddress((void**)&v,    g_v);
    cudaGetSymbolAddress((void**)&attn, g_attn);
    cudaGetSymbolAddress((void**)&ao,   g_ao);
    cudaGetSymbolAddress((void**)&wqs,  g_wqs);
    cudaGetSymbolAddress((void**)&wsum, g_wsum);
    cudaGetSymbolAddress((void**)&comp, g_comp);
    cudaGetSymbolAddress((void**)&pos,  g_pos);
    cudaGetSymbolAddress((void**)&head, g_head);

    // 0. fold w_a row-sums into w_q
    wsum_kernel<<<1, 1024>>>(wa, wsum);
    scale_wq_kernel<<<(EE*EE + 255)/256, 256>>>(wq, wsum, wqs);

    // 1. projections (big GEMMs): q uses scaled w_q so q already carries w_a
    sgemm128<<<dim3(EE/128, BS/128), 256>>>(inq,  wqs, q, BS, EE, EE);
    sgemm128<<<dim3(EE/128, BS/128), 256>>>(inkv, wk,  k, BS, EE, EE);
    sgemm128<<<dim3(EE/128, BS/128), 256>>>(inkv, wv,  v, BS, EE, EE);

    // 2. smolgen: comp [BS, C]
    sgemm_gen<<<dim3(1, (BS+63)/64, 1), 256>>>(
        inq, wcmp, comp, BS, CC, EE, EE, CC, CC,
        0, 0, 0, nullptr, 0, 0);

    // 3. pos = silu(comp[B, S*C] @ w_pos + b_pos)  [B, M]
    sgemm_gen<<<dim3(MM/64, BB/64, 1), 256>>>(
        comp, wpos, pos, BB, MM, SC, SC, MM, MM,
        0, 0, 0, bpos, 0, 1);

    // 4. head[b,h,:] = silu(pos @ w_head[h] + b_head[h])   (batched over h)
    sgemm_gen<<<dim3(MM/64, BB/64, HH), 256>>>(
        pos, whead, head, BB, MM, MM, MM, MM, HH*MM,
        0, (long long)MM*MM, MM, bhead, MM, 1);

    // 5. supp -> attn buffer: attn[b,h,:] = head[b,h,:] @ shared_proj
    sgemm_gen<<<dim3((S2+63)/64, BB/64, HH), 256>>>(
        head, sproj, attn, BB, S2, MM, HH*MM, S2, HH*S2,
        MM, 0, S2, nullptr, 0, 0);

    // 6. scores (+= into supp)
    score_kernel<<<dim3(HH, BB), 256>>>(q, k, attn);

    // 7. softmax
    {
        int nrows = BB*HH*SS;
        softmax_kernel<<<(nrows*32 + 255)/256, 256>>>(attn, nrows);
    }

    // 8. P @ V
    pv_kernel<<<dim3(HH, BB), 256>>>(attn, v, ao);

    // 9. output projection
    sgemm128<<<dim3(EE/128, BS/128), 256>>>(ao, wo, out, BS, EE, EE);
}

// round 4
// speedup vs baseline: 2.2080x; 2.2080x over previous
#include <cuda_runtime.h>
#include <cuda_bf16.h>
#include <math.h>
#include <stdint.h>

// ---------------------------------------------------------------------------
// Problem dims
// ---------------------------------------------------------------------------
#define BB 512
#define SS 79
#define EE 1024
#define HH 16
#define DD 64
#define CC 32
#define MM 256
#define BS (BB*SS)          // 40448
#define SC (SS*CC)          // 2528
#define S2 (SS*SS)          // 6241
#define S2P 6400            // padded attn row for tensor supp GEMM

// ---------------------------------------------------------------------------
// Scratch (device globals; no runtime allocation allowed)
// ---------------------------------------------------------------------------
__device__ __align__(128) float g_wqs [EE*EE];
__device__ __align__(128) float g_wsum[HH*DD];
__device__ __align__(128) float g_q   [(size_t)BS*EE];
__device__ __align__(128) float g_k   [(size_t)BS*EE];
__device__ __align__(128) float g_v   [(size_t)BS*EE];
__device__ __align__(128) float g_attn[(size_t)BB*HH*S2P];
__device__ __align__(128) float g_comp[(size_t)BB*SC];
__device__ __align__(128) float g_pos [(size_t)BB*MM];
__device__ __align__(128) float g_head[(size_t)BB*HH*MM];

// bf16 split buffers
__device__ __align__(128) __nv_bfloat16 g_a1_hi[(size_t)BS*EE];
__device__ __align__(128) __nv_bfloat16 g_a1_lo[(size_t)BS*EE];
__device__ __align__(128) __nv_bfloat16 g_a2_hi[(size_t)BS*EE];
__device__ __align__(128) __nv_bfloat16 g_a2_lo[(size_t)BS*EE];
__device__ __align__(128) __nv_bfloat16 g_wqT_hi[EE*EE];
__device__ __align__(128) __nv_bfloat16 g_wqT_lo[EE*EE];
__device__ __align__(128) __nv_bfloat16 g_wkT_hi[EE*EE];
__device__ __align__(128) __nv_bfloat16 g_wkT_lo[EE*EE];
__device__ __align__(128) __nv_bfloat16 g_wvT_hi[EE*EE];
__device__ __align__(128) __nv_bfloat16 g_wvT_lo[EE*EE];
__device__ __align__(128) __nv_bfloat16 g_woT_hi[EE*EE];
__device__ __align__(128) __nv_bfloat16 g_woT_lo[EE*EE];
__device__ __align__(128) __nv_bfloat16 g_hb_hi[BB*HH*MM];
__device__ __align__(128) __nv_bfloat16 g_hb_lo[BB*HH*MM];
__device__ __align__(128) __nv_bfloat16 g_spT_hi[S2P*MM];
__device__ __align__(128) __nv_bfloat16 g_spT_lo[S2P*MM];

// ---------------------------------------------------------------------------
// PTX helpers (sm_103 non-'a' safe: ldmatrix / mma.sync / cp.async only)
// ---------------------------------------------------------------------------
__device__ __forceinline__ uint32_t smem_u32(const void* p) {
    uint32_t a;
    asm("{ .reg .u64 t; cvta.to.shared.u64 t, %1; cvt.u32.u64 %0, t; }"
        : "=r"(a) : "l"(p));
    return a;
}

#define LDSM4(r, addr)                                                       \
    asm volatile("ldmatrix.sync.aligned.m8n8.x4.shared.b16 {%0,%1,%2,%3}, [%4];" \
        : "=r"((r)[0]), "=r"((r)[1]), "=r"((r)[2]), "=r"((r)[3]) : "r"(addr))

#define MMA_BF16(c, a, b0, b1)                                               \
    asm volatile("mma.sync.aligned.m16n8k16.row.col.f32.bf16.bf16.f32 "      \
        "{%0,%1,%2,%3}, {%4,%5,%6,%7}, {%8,%9}, {%0,%1,%2,%3};"              \
        : "+f"((c)[0]), "+f"((c)[1]), "+f"((c)[2]), "+f"((c)[3])             \
        : "r"((a)[0]), "r"((a)[1]), "r"((a)[2]), "r"((a)[3]), "r"(b0), "r"(b1))

#define CP16(smem, gmem)                                                     \
    asm volatile("cp.async.cg.shared.global [%0], [%1], 16;"                 \
        :: "r"(smem), "l"(gmem))
#define CP_COMMIT() asm volatile("cp.async.commit_group;" ::: "memory")
#define CP_WAIT1()  asm volatile("cp.async.wait_group 1;"  ::: "memory")

// ---------------------------------------------------------------------------
// HMMA split-bf16 GEMM:  C[M,N](fp32) = A[M,K] @ B_T[N,K]
// BM=128, BN=128, BK=32. 256 threads, warp tile 32x64 (warps 4x2).
// passes==3: Ah*Bh + Ah*Bl + Al*Bh.   passes==1: Ah*Bh only.
// Requires M%128==0, N%128==0, K%32==0. Smem rows strided 80B (conflict-free).
// ---------------------------------------------------------------------------
#define HG_STAGE 40960
#define HG_SMEM  (2*HG_STAGE)

__global__ void __launch_bounds__(256, 2)
hgemm(const __nv_bfloat16* __restrict__ Ahi, const __nv_bfloat16* __restrict__ Alo,
      const __nv_bfloat16* __restrict__ Bhi, const __nv_bfloat16* __restrict__ Blo,
      float* __restrict__ C, int K,
      long long lda, long long ldb, long long ldc,
      long long aBatch, long long bBatch, long long cBatch, int passes)
{
    extern __shared__ char sm[];
    const uint32_t sbase = smem_u32(sm);

    const int tid = threadIdx.x;
    const long long brow = blockIdx.y, bcol = blockIdx.x, bz = blockIdx.z;
    const __nv_bfloat16* Arow_h = Ahi + bz*aBatch + brow*128*lda;
    const __nv_bfloat16* Arow_l = Alo + bz*aBatch + brow*128*lda;
    const __nv_bfloat16* Brow_h = Bhi + bz*bBatch + bcol*128*ldb;
    const __nv_bfloat16* Brow_l = Blo + bz*bBatch + bcol*128*ldb;
    C += bz*cBatch;

    const int warp = tid >> 5, lane = tid & 31;
    const int wm = warp >> 1, wn = warp & 1;

    // ldmatrix per-thread addressing (A: row-major m x k; B_T: row-major n x k)
    const int      arow_t = wm*32 + ((lane>>3)&1)*8 + (lane&7);
    const uint32_t akoff  = ((lane>>4)&1)*16;
    const int      nrow_t = wn*64 + ((lane>>4)&1)*8 + (lane&7);
    const uint32_t bkoff  = ((lane>>3)&1)*16;

    // load mapping: 512 16B-chunks per 128x32 buffer; 2 chunks/thread
    const int ld_r0 = (tid + 0)   >> 2, ld_c0 = (tid + 0)   & 3;
    const int ld_r1 = (tid + 256) >> 2, ld_c1 = (tid + 256) & 3;

    float acc[2][8][4];
    #pragma unroll
    for (int i = 0; i < 2; i++)
        #pragma unroll
        for (int j = 0; j < 8; j++)
            #pragma unroll
            for (int l = 0; l < 4; l++) acc[i][j][l] = 0.f;

    const int nIter = K >> 5;

    // ---- stage loader ----
    #define LOAD_STAGE(s, it) do {                                           \
        uint32_t st = sbase + (uint32_t)(s)*HG_STAGE;                        \
        long long k0 = (long long)(it)*32;                                   \
        uint32_t so0 = (uint32_t)ld_r0*80 + (uint32_t)ld_c0*16;              \
        uint32_t so1 = (uint32_t)ld_r1*80 + (uint32_t)ld_c1*16;              \
        CP16(st + so0,         Arow_h + (long long)ld_r0*lda + k0 + ld_c0*8);\
        CP16(st + so1,         Arow_h + (long long)ld_r1*lda + k0 + ld_c1*8);\
        CP16(st + 20480 + so0, Brow_h + (long long)ld_r0*ldb + k0 + ld_c0*8);\
        CP16(st + 20480 + so1, Brow_h + (long long)ld_r1*ldb + k0 + ld_c1*8);\
        if (passes == 3) {                                                   \
            CP16(st + 10240 + so0, Arow_l + (long long)ld_r0*lda + k0 + ld_c0*8);\
            CP16(st + 10240 + so1, Arow_l + (long long)ld_r1*lda + k0 + ld_c1*8);\
            CP16(st + 30720 + so0, Brow_l + (long long)ld_r0*ldb + k0 + ld_c0*8);\
            CP16(st + 30720 + so1, Brow_l + (long long)ld_r1*ldb + k0 + ld_c1*8);\
        }                                                                    \
    } while (0)

    LOAD_STAGE(0, 0); CP_COMMIT();
    LOAD_STAGE(1, 1); CP_COMMIT();

    for (int it = 0; it < nIter; it++) {
        CP_WAIT1();
        __syncthreads();
        const uint32_t st = sbase + (uint32_t)(it & 1)*HG_STAGE;

        #pragma unroll
        for (int kc = 0; kc < 2; kc++) {
            uint32_t ah[2][4], al[2][4];
            #pragma unroll
            for (int mf = 0; mf < 2; mf++) {
                LDSM4(ah[mf], st + (uint32_t)(arow_t + mf*16)*80 + kc*32 + akoff);
                if (passes == 3)
                    LDSM4(al[mf], st + 10240 + (uint32_t)(arow_t + mf*16)*80 + kc*32 + akoff);
            }
            #pragma unroll
            for (int nf16 = 0; nf16 < 4; nf16++) {
                uint32_t bh[4], bl[4];
                LDSM4(bh, st + 20480 + (uint32_t)(nrow_t + nf16*16)*80 + kc*32 + bkoff);
                if (passes == 3)
                    LDSM4(bl, st + 30720 + (uint32_t)(nrow_t + nf16*16)*80 + kc*32 + bkoff);
                #pragma unroll
                for (int mf = 0; mf < 2; mf++) {
                    MMA_BF16(acc[mf][nf16*2],   ah[mf], bh[0], bh[1]);
                    MMA_BF16(acc[mf][nf16*2+1], ah[mf], bh[2], bh[3]);
                    if (passes == 3) {
                        MMA_BF16(acc[mf][nf16*2],   ah[mf], bl[0], bl[1]);
                        MMA_BF16(acc[mf][nf16*2+1], ah[mf], bl[2], bl[3]);
                        MMA_BF16(acc[mf][nf16*2],   al[mf], bh[0], bh[1]);
                        MMA_BF16(acc[mf][nf16*2+1], al[mf], bh[2], bh[3]);
                    }
                }
            }
        }
        __syncthreads();
        if (it + 2 < nIter) LOAD_STAGE(it & 1, it + 2);
        CP_COMMIT();
    }
    #undef LOAD_STAGE

    // epilogue
    const int g = lane >> 2, cc = (lane & 3)*2;
    #pragma unroll
    for (int mf = 0; mf < 2; mf++) {
        #pragma unroll
        for (int nf = 0; nf < 8; nf++) {
            long long row = brow*128 + wm*32 + mf*16 + g;
            long long col = bcol*128 + wn*64 + nf*8 + cc;
            *(float2*)(C + row*ldc + col) =
                make_float2(acc[mf][nf][0], acc[mf][nf][1]);
            *(float2*)(C + (row+8)*ldc + col) =
                make_float2(acc[mf][nf][2], acc[mf][nf][3]);
        }
    }
}

// ---------------------------------------------------------------------------
// fp32 -> bf16 hi/lo split (elementwise, float4-wide)
// ---------------------------------------------------------------------------
__global__ void split_kernel(const float* __restrict__ x,
                             __nv_bfloat16* __restrict__ hi,
                             __nv_bfloat16* __restrict__ lo, long long n4)
{
    long long i = (long long)blockIdx.x * blockDim.x + threadIdx.x;
    if (i >= n4) return;
    float4 v = ((const float4*)x)[i];
    __nv_bfloat16 h0 = __float2bfloat16(v.x), h1 = __float2bfloat16(v.y);
    __nv_bfloat16 h2 = __float2bfloat16(v.z), h3 = __float2bfloat16(v.w);
    __nv_bfloat162 ha, hb, la, lb;
    ha.x = h0; ha.y = h1; hb.x = h2; hb.y = h3;
    la.x = __float2bfloat16(v.x - __bfloat162float(h0));
    la.y = __float2bfloat16(v.y - __bfloat162float(h1));
    lb.x = __float2bfloat16(v.z - __bfloat162float(h2));
    lb.y = __float2bfloat16(v.w - __bfloat162float(h3));
    ((__nv_bfloat162*)hi)[i * 2]     = ha;
    ((__nv_bfloat162*)hi)[i * 2 + 1] = hb;
    ((__nv_bfloat162*)lo)[i * 2]     = la;
    ((__nv_bfloat162*)lo)[i * 2 + 1] = lb;
}

// ---------------------------------------------------------------------------
// transpose + split:  w[K,N] (fp32) -> hiT/loT[NT,K] (bf16), pad rows zeroed
// ---------------------------------------------------------------------------
__global__ void splitT_kernel(const float* __restrict__ w,
                              __nv_bfloat16* __restrict__ hiT,
                              __nv_bfloat16* __restrict__ loT,
                              int K, int N, int NT)
{
    __shared__ float t[32][33];
    const int n0 = blockIdx.x * 32, k0 = blockIdx.y * 32;
    const int tx = threadIdx.x, ty = threadIdx.y;
    for (int i = ty; i < 32; i += 8) {
        int kk = k0 + i, nn = n0 + tx;
        t[i][tx] = (kk < K && nn < N) ? w[(long long)kk * N + nn] : 0.f;
    }
    __syncthreads();
    for (int i = ty; i < 32; i += 8) {
        int nn = n0 + i, kk = k0 + tx;
        if (nn < NT && kk < K) {
            float v = t[tx][i];
            __nv_bfloat16 h = __float2bfloat16(v);
            hiT[(long long)nn * K + kk] = h;
            loT[(long long)nn * K + kk] = __float2bfloat16(v - __bfloat162float(h));
        }
    }
}

// ---------------------------------------------------------------------------
// w_a row-sum + fold (with 1/sqrt(d)) into w_q
// ---------------------------------------------------------------------------
__global__ void wsum_kernel(const float* __restrict__ wa, float* __restrict__ wsum)
{
    int i = blockIdx.x * blockDim.x + threadIdx.x;
    if (i < HH*DD) {
        const float* p = wa + (size_t)i * DD;
        float s = 0.f;
        #pragma unroll
        for (int e = 0; e < DD; e++) s += p[e];
        wsum[i] = s * 0.125f;           // fold 1/sqrt(64)
    }
}
__global__ void scale_wq_kernel(const float* __restrict__ wq,
                                const float* __restrict__ wsum,
                                float* __restrict__ wqs)
{
    int idx = blockIdx.x * blockDim.x + threadIdx.x;
    if (idx < EE*EE) wqs[idx] = wq[idx] * wsum[idx & (EE-1)];
}

// ---------------------------------------------------------------------------
// Generic strided/batched SGEMM with optional bias + SiLU (small smolgen ops)
// ---------------------------------------------------------------------------
__global__ __launch_bounds__(256)
void sgemm_gen(const float* __restrict__ A, const float* __restrict__ B,
               float* __restrict__ C,
               int M, int N, int K, int lda, int ldb, int ldc,
               long long aBatch, long long bBatch, long long cBatch,
               const float* __restrict__ bias, long long biasBatch, int act)
{
    __shared__ float As[16][64];
    __shared__ float Bs[16][64];

    const int bz = blockIdx.z;
    A += (long long)bz * aBatch;
    B += (long long)bz * bBatch;
    C += (long long)bz * cBatch;
    const float* biasp = bias ? bias + (long long)bz * biasBatch : nullptr;

    const int row0 = blockIdx.y * 64, col0 = blockIdx.x * 64;
    const int tid = threadIdx.x;
    const int tx = tid & 15, ty = tid >> 4;

    float acc[4][4] = {};

    for (int k0 = 0; k0 < K; k0 += 16) {
        #pragma unroll
        for (int i = 0; i < 4; i++) {
            int lin = tid + i * 256;
            int ar = lin >> 4, ac = lin & 15;
            int gr = row0 + ar, gc = k0 + ac;
            As[ac][ar] = (gr < M && gc < K) ? A[(long long)gr * lda + gc] : 0.f;
        }
        #pragma unroll
        for (int i = 0; i < 4; i++) {
            int lin = tid + i * 256;
            int br = lin >> 6, bc = lin & 63;
            int gr = k0 + br, gc = col0 + bc;
            Bs[br][bc] = (gr < K && gc < N) ? B[(long long)gr * ldb + gc] : 0.f;
        }
        __syncthreads();
        #pragma unroll
        for (int k = 0; k < 16; k++) {
            float ra[4], rb[4];
            #pragma unroll
            for (int i = 0; i < 4; i++) ra[i] = As[k][ty*4 + i];
            #pragma unroll
            for (int j = 0; j < 4; j++) rb[j] = Bs[k][tx*4 + j];
            #pragma unroll
            for (int i = 0; i < 4; i++)
                #pragma unroll
                for (int j = 0; j < 4; j++) acc[i][j] += ra[i] * rb[j];
        }
        __syncthreads();
    }

    #pragma unroll
    for (int i = 0; i < 4; i++) {
        int gr = row0 + ty*4 + i;
        if (gr >= M) continue;
        #pragma unroll
        for (int j = 0; j < 4; j++) {
            int gc = col0 + tx*4 + j;
            if (gc >= N) continue;
            float v = acc[i][j];
            if (biasp) v += biasp[gc];
            if (act == 1) v = v / (1.f + __expf(-v));
            C[(long long)gr * ldc + gc] = v;
        }
    }
}

// ---------------------------------------------------------------------------
// Scores: attn[b,h,t,T] += q . k   (scale already folded into w_q)
// ---------------------------------------------------------------------------
__global__ __launch_bounds__(256)
void score_kernel(const float* __restrict__ q, const float* __restrict__ k,
                  float* __restrict__ attn)
{
    __shared__ float qs[SS][65];
    __shared__ float ks[SS][65];

    const int h = blockIdx.x, b = blockIdx.y;
    const int tid = threadIdx.x;
    const float* qb = q + (long long)b * SS * EE + h * DD;
    const float* kb = k + (long long)b * SS * EE + h * DD;

    for (int idx = tid; idx < SS*DD; idx += 256) {
        int r = idx >> 6, c = idx & 63;
        qs[r][c] = qb[(long long)r * EE + c];
        ks[r][c] = kb[(long long)r * EE + c];
    }
    __syncthreads();

    float* ab = attn + (long long)(b * HH + h) * S2P;
    for (int idx = tid; idx < S2; idx += 256) {
        int t = idx / SS, T = idx - t * SS;
        float s = 0.f;
        #pragma unroll
        for (int d = 0; d < DD; d++) s += qs[t][d] * ks[T][d];
        ab[idx] += s;
    }
}

// ---------------------------------------------------------------------------
// Softmax over last dim (79). One warp per row. Padded attn layout.
// ---------------------------------------------------------------------------
__global__ __launch_bounds__(256)
void softmax_kernel(float* __restrict__ attn, int nrows)
{
    int r = (blockIdx.x * blockDim.x + threadIdx.x) >> 5;
    int lane = threadIdx.x & 31;
    if (r >= nrows) return;
    int bh = r / SS, t = r - bh * SS;
    float* row = attn + (long long)bh * S2P + t * SS;

    bool v1 = (lane + 32) < SS, v2 = (lane + 64) < SS;
    float x0 = row[lane];
    float x1 = v1 ? row[lane + 32] : -3.0e38f;
    float x2 = v2 ? row[lane + 64] : -3.0e38f;

    float m = fmaxf(x0, fmaxf(x1, x2));
    #pragma unroll
    for (int o = 16; o > 0; o >>= 1) m = fmaxf(m, __shfl_xor_sync(0xffffffffu, m, o));

    float e0 = __expf(x0 - m);
    float e1 = v1 ? __expf(x1 - m) : 0.f;
    float e2 = v2 ? __expf(x2 - m) : 0.f;
    float s = e0 + e1 + e2;
    #pragma unroll
    for (int o = 16; o > 0; o >>= 1) s += __shfl_xor_sync(0xffffffffu, s, o);

    float inv = 1.f / s;
    row[lane] = e0 * inv;
    if (v1) row[lane + 32] = e1 * inv;
    if (v2) row[lane + 64] = e2 * inv;
}

// ---------------------------------------------------------------------------
// P @ V -> split bf16 hi/lo directly (feeds out-proj GEMM; no fp32 ao buffer)
// ---------------------------------------------------------------------------
__global__ __launch_bounds__(256)
void pv_kernel(const float* __restrict__ attn, const float* __restrict__ v,
               __nv_bfloat16* __restrict__ aoh, __nv_bfloat16* __restrict__ aol)
{
    __shared__ float vs[SS*DD];
    __shared__ float ps[S2];

    const int h = blockIdx.x, b = blockIdx.y;
    const int tid = threadIdx.x;

    const float* vb = v + (long long)b * SS * EE + h * DD;
    for (int idx = tid; idx < SS*DD; idx += 256) {
        int r = idx >> 6, c = idx & 63;
        vs[idx] = vb[(long long)r * EE + c];
    }
    const float* ab = attn + (long long)(b * HH + h) * S2P;
    for (int idx = tid; idx < S2; idx += 256) ps[idx] = ab[idx];
    __syncthreads();

    const int d = tid & 63, tg = tid >> 6;
    const long long base = (long long)b * SS * EE + h * DD + d;
    for (int t = tg; t < SS; t += 4) {
        float s = 0.f;
        const float* pr = ps + t * SS;
        #pragma unroll
        for (int T = 0; T < SS; T++) s += pr[T] * vs[T*DD + d];
        __nv_bfloat16 hi = __float2bfloat16(s);
        aoh[base + (long long)t * EE] = hi;
        aol[base + (long long)t * EE] = __float2bfloat16(s - __bfloat162float(hi));
    }
}

// ---------------------------------------------------------------------------
// Launch
// ---------------------------------------------------------------------------
extern "C" void kernel_launch(void* const* d_in, const int* in_sizes, int n_in,
                              void* d_out, int out_size)
{
    const float* inq   = (const float*)d_in[0];
    const float* inkv  = (const float*)d_in[1];
    const float* wq    = (const float*)d_in[2];
    const float* wk    = (const float*)d_in[3];
    const float* wv    = (const float*)d_in[4];
    const float* wo    = (const float*)d_in[5];
    const float* wa    = (const float*)d_in[6];
    const float* wcmp  = (const float*)d_in[7];
    const float* wpos  = (const float*)d_in[8];
    const float* bpos  = (const float*)d_in[9];
    const float* whead = (const float*)d_in[10];
    const float* bhead = (const float*)d_in[11];
    const float* sproj = (const float*)d_in[12];
    float* out = (float*)d_out;

    // Resolve device addresses (host shadow symbols are ATS-dereferenceable traps)
    float *q, *k, *v, *attn, *wqs, *wsum, *comp, *pos, *head;
    cudaGetSymbolAddress((void**)&q,    g_q);
    cudaGetSymbolAddress((void**)&k,    g_k);
    cudaGetSymbolAddress((void**)&v,    g_v);
    cudaGetSymbolAddress((void**)&attn, g_attn);
    cudaGetSymbolAddress((void**)&wqs,  g_wqs);
    cudaGetSymbolAddress((void**)&wsum, g_wsum);
    cudaGetSymbolAddress((void**)&comp, g_comp);
    cudaGetSymbolAddress((void**)&pos,  g_pos);
    cudaGetSymbolAddress((void**)&head, g_head);

    __nv_bfloat16 *a1h, *a1l, *a2h, *a2l;
    __nv_bfloat16 *wqTh, *wqTl, *wkTh, *wkTl, *wvTh, *wvTl, *woTh, *woTl;
    __nv_bfloat16 *hbh, *hbl, *spTh, *spTl;
    cudaGetSymbolAddress((void**)&a1h,  g_a1_hi);
    cudaGetSymbolAddress((void**)&a1l,  g_a1_lo);
    cudaGetSymbolAddress((void**)&a2h,  g_a2_hi);
    cudaGetSymbolAddress((void**)&a2l,  g_a2_lo);
    cudaGetSymbolAddress((void**)&wqTh, g_wqT_hi);
    cudaGetSymbolAddress((void**)&wqTl, g_wqT_lo);
    cudaGetSymbolAddress((void**)&wkTh, g_wkT_hi);
    cudaGetSymbolAddress((void**)&wkTl, g_wkT_lo);
    cudaGetSymbolAddress((void**)&wvTh, g_wvT_hi);
    cudaGetSymbolAddress((void**)&wvTl, g_wvT_lo);
    cudaGetSymbolAddress((void**)&woTh, g_woT_hi);
    cudaGetSymbolAddress((void**)&woTl, g_woT_lo);
    cudaGetSymbolAddress((void**)&hbh,  g_hb_hi);
    cudaGetSymbolAddress((void**)&hbl,  g_hb_lo);
    cudaGetSymbolAddress((void**)&spTh, g_spT_hi);
    cudaGetSymbolAddress((void**)&spTl, g_spT_lo);

    cudaFuncSetAttribute(hgemm, cudaFuncAttributeMaxDynamicSharedMemorySize, HG_SMEM);

    // 0. fold w_a (and 1/sqrt d) into w_q; split/transpose weights; split inputs
    wsum_kernel<<<1, 1024>>>(wa, wsum);
    scale_wq_kernel<<<(EE*EE + 255)/256, 256>>>(wq, wsum, wqs);

    splitT_kernel<<<dim3(32, 32), dim3(32, 8)>>>(wqs, wqTh, wqTl, EE, EE, EE);
    splitT_kernel<<<dim3(32, 32), dim3(32, 8)>>>(wk,  wkTh, wkTl, EE, EE, EE);
    splitT_kernel<<<dim3(32, 32), dim3(32, 8)>>>(wv,  wvTh, wvTl, EE, EE, EE);
    splitT_kernel<<<dim3(32, 32), dim3(32, 8)>>>(wo,  woTh, woTl, EE, EE, EE);

    {
        long long n4 = (long long)BS * EE / 4;
        split_kernel<<<(unsigned)((n4 + 255)/256), 256>>>(inq,  a1h, a1l, n4);
        split_kernel<<<(unsigned)((n4 + 255)/256), 256>>>(inkv, a2h, a2l, n4);
    }

    // 1. projections on tensor cores (3-pass split bf16)
    hgemm<<<dim3(EE/128, BS/128, 1), 256, HG_SMEM>>>(
        a1h, a1l, wqTh, wqTl, q, EE, EE, EE, EE, 0, 0, 0, 3);
    hgemm<<<dim3(EE/128, BS/128, 1), 256, HG_SMEM>>>(
        a2h, a2l, wkTh, wkTl, k, EE, EE, EE, EE, 0, 0, 0, 3);
    hgemm<<<dim3(EE/128, BS/128, 1), 256, HG_SMEM>>>(
        a2h, a2l, wvTh, wvTl, v, EE, EE, EE, EE, 0, 0, 0, 3);

    // 2. smolgen small chain (fp32)
    sgemm_gen<<<dim3(1, (BS+63)/64, 1), 256>>>(
        inq, wcmp, comp, BS, CC, EE, EE, CC, CC, 0, 0, 0, nullptr, 0, 0);
    sgemm_gen<<<dim3(MM/64, BB/64, 1), 256>>>(
        comp, wpos, pos, BB, MM, SC, SC, MM, MM, 0, 0, 0, bpos, 0, 1);
    sgemm_gen<<<dim3(MM/64, BB/64, HH), 256>>>(
        pos, whead, head, BB, MM, MM, MM, MM, HH*MM,
        0, (long long)MM*MM, MM, bhead, MM, 1);

    // 3. supp on tensor cores (single-pass bf16; supp tiny vs scores)
    {
        long long n4 = (long long)BB * HH * MM / 4;
        split_kernel<<<(unsigned)((n4 + 255)/256), 256>>>(head, hbh, hbl, n4);
    }
    splitT_kernel<<<dim3(S2P/32, MM/32), dim3(32, 8)>>>(sproj, spTh, spTl, MM, S2, S2P);
    hgemm<<<dim3(S2P/128, BB/128, HH), 256, HG_SMEM>>>(
        hbh, hbl, spTh, spTl, attn, MM,
        (long long)HH*MM, MM, (long long)HH*S2P,
        MM, 0, S2P, 1);

    // 4. scores (+= into supp), softmax, P@V (writes split bf16 directly)
    score_kernel<<<dim3(HH, BB), 256>>>(q, k, attn);
    {
        int nrows = BB*HH*SS;
        softmax_kernel<<<(nrows*32 + 255)/256, 256>>>(attn, nrows);
    }
    pv_kernel<<<dim3(HH, BB), 256>>>(attn, v, a1h, a1l);

    // 5. output projection on tensor cores
    hgemm<<<dim3(EE/128, BS/128, 1), 256, HG_SMEM>>>(
        a1h, a1l, woTh, woTl, out, EE, EE, EE, EE, 0, 0, 0, 3);
}

// round 5
// speedup vs baseline: 2.9144x; 1.3200x over previous
#include <cuda_runtime.h>
#include <cuda_bf16.h>
#include <math.h>
#include <stdint.h>

// ---------------------------------------------------------------------------
// Problem dims
// ---------------------------------------------------------------------------
#define BB 512
#define SS 79
#define EE 1024
#define HH 16
#define DD 64
#define CC 32
#define MM 256
#define BS (BB*SS)          // 40448
#define SC (SS*CC)          // 2528
#define S2 (SS*SS)          // 6241
#define S2P 6400            // padded attn row for tensor supp GEMM

// ---------------------------------------------------------------------------
// Scratch (device globals; no runtime allocation allowed)
// ---------------------------------------------------------------------------
__device__ __align__(128) float g_wqs [EE*EE];
__device__ __align__(128) float g_wsum[HH*DD];
__device__ __align__(128) float g_q   [(size_t)BS*EE];
__device__ __align__(128) float g_k   [(size_t)BS*EE];
__device__ __align__(128) float g_v   [(size_t)BS*EE];
__device__ __align__(128) float g_attn[(size_t)BB*HH*S2P];
__device__ __align__(128) float g_comp[(size_t)BB*SC];
__device__ __align__(128) float g_pos [(size_t)BB*MM];
__device__ __align__(128) float g_head[(size_t)BB*HH*MM];

// bf16 split buffers
__device__ __align__(128) __nv_bfloat16 g_a1_hi[(size_t)BS*EE];
__device__ __align__(128) __nv_bfloat16 g_a1_lo[(size_t)BS*EE];
__device__ __align__(128) __nv_bfloat16 g_a2_hi[(size_t)BS*EE];
__device__ __align__(128) __nv_bfloat16 g_a2_lo[(size_t)BS*EE];
__device__ __align__(128) __nv_bfloat16 g_wqT_hi[EE*EE];
__device__ __align__(128) __nv_bfloat16 g_wqT_lo[EE*EE];
__device__ __align__(128) __nv_bfloat16 g_wkT_hi[EE*EE];
__device__ __align__(128) __nv_bfloat16 g_wkT_lo[EE*EE];
__device__ __align__(128) __nv_bfloat16 g_wvT_hi[EE*EE];
__device__ __align__(128) __nv_bfloat16 g_wvT_lo[EE*EE];
__device__ __align__(128) __nv_bfloat16 g_woT_hi[EE*EE];
__device__ __align__(128) __nv_bfloat16 g_woT_lo[EE*EE];
__device__ __align__(128) __nv_bfloat16 g_hb_hi[BB*HH*MM];
__device__ __align__(128) __nv_bfloat16 g_hb_lo[BB*HH*MM];
__device__ __align__(128) __nv_bfloat16 g_spT_hi[S2P*MM];
__device__ __align__(128) __nv_bfloat16 g_spT_lo[S2P*MM];

// ---------------------------------------------------------------------------
// PTX helpers (sm_103 non-'a' safe: ldmatrix / mma.sync / cp.async only)
// ---------------------------------------------------------------------------
__device__ __forceinline__ uint32_t smem_u32(const void* p) {
    uint32_t a;
    asm("{ .reg .u64 t; cvta.to.shared.u64 t, %1; cvt.u32.u64 %0, t; }"
        : "=r"(a) : "l"(p));
    return a;
}

#define LDSM4(r, addr)                                                       \
    asm volatile("ldmatrix.sync.aligned.m8n8.x4.shared.b16 {%0,%1,%2,%3}, [%4];" \
        : "=r"((r)[0]), "=r"((r)[1]), "=r"((r)[2]), "=r"((r)[3]) : "r"(addr))

#define MMA_BF16(c, a, b0, b1)                                               \
    asm volatile("mma.sync.aligned.m16n8k16.row.col.f32.bf16.bf16.f32 "      \
        "{%0,%1,%2,%3}, {%4,%5,%6,%7}, {%8,%9}, {%0,%1,%2,%3};"              \
        : "+f"((c)[0]), "+f"((c)[1]), "+f"((c)[2]), "+f"((c)[3])             \
        : "r"((a)[0]), "r"((a)[1]), "r"((a)[2]), "r"((a)[3]), "r"(b0), "r"(b1))

#define CP16(smem, gmem)                                                     \
    asm volatile("cp.async.cg.shared.global [%0], [%1], 16;"                 \
        :: "r"(smem), "l"(gmem))
#define CP_COMMIT() asm volatile("cp.async.commit_group;" ::: "memory")
#define CP_WAIT1()  asm volatile("cp.async.wait_group 1;"  ::: "memory")

// ---------------------------------------------------------------------------
// HMMA split-bf16 GEMM:  C[M,N](fp32) = A[M,K] @ B_T[N,K]
// BM=128, BN=128, BK=32. 256 threads, warp tile 32x64 (warps 4x2).
// passes==3: Ah*Bh + Ah*Bl + Al*Bh.   passes==1: Ah*Bh only.
// ---------------------------------------------------------------------------
#define HG_STAGE 40960
#define HG_SMEM  (2*HG_STAGE)

__global__ void __launch_bounds__(256, 2)
hgemm(const __nv_bfloat16* __restrict__ Ahi, const __nv_bfloat16* __restrict__ Alo,
      const __nv_bfloat16* __restrict__ Bhi, const __nv_bfloat16* __restrict__ Blo,
      float* __restrict__ C, int K,
      long long lda, long long ldb, long long ldc,
      long long aBatch, long long bBatch, long long cBatch, int passes)
{
    extern __shared__ char sm[];
    const uint32_t sbase = smem_u32(sm);

    const int tid = threadIdx.x;
    const long long brow = blockIdx.y, bcol = blockIdx.x, bz = blockIdx.z;
    const __nv_bfloat16* Arow_h = Ahi + bz*aBatch + brow*128*lda;
    const __nv_bfloat16* Arow_l = Alo + bz*aBatch + brow*128*lda;
    const __nv_bfloat16* Brow_h = Bhi + bz*bBatch + bcol*128*ldb;
    const __nv_bfloat16* Brow_l = Blo + bz*bBatch + bcol*128*ldb;
    C += bz*cBatch;

    const int warp = tid >> 5, lane = tid & 31;
    const int wm = warp >> 1, wn = warp & 1;

    const int      arow_t = wm*32 + ((lane>>3)&1)*8 + (lane&7);
    const uint32_t akoff  = ((lane>>4)&1)*16;
    const int      nrow_t = wn*64 + ((lane>>4)&1)*8 + (lane&7);
    const uint32_t bkoff  = ((lane>>3)&1)*16;

    const int ld_r0 = (tid + 0)   >> 2, ld_c0 = (tid + 0)   & 3;
    const int ld_r1 = (tid + 256) >> 2, ld_c1 = (tid + 256) & 3;

    float acc[2][8][4];
    #pragma unroll
    for (int i = 0; i < 2; i++)
        #pragma unroll
        for (int j = 0; j < 8; j++)
            #pragma unroll
            for (int l = 0; l < 4; l++) acc[i][j][l] = 0.f;

    const int nIter = K >> 5;

    #define LOAD_STAGE(s, it) do {                                           \
        uint32_t st = sbase + (uint32_t)(s)*HG_STAGE;                        \
        long long k0 = (long long)(it)*32;                                   \
        uint32_t so0 = (uint32_t)ld_r0*80 + (uint32_t)ld_c0*16;              \
        uint32_t so1 = (uint32_t)ld_r1*80 + (uint32_t)ld_c1*16;              \
        CP16(st + so0,         Arow_h + (long long)ld_r0*lda + k0 + ld_c0*8);\
        CP16(st + so1,         Arow_h + (long long)ld_r1*lda + k0 + ld_c1*8);\
        CP16(st + 20480 + so0, Brow_h + (long long)ld_r0*ldb + k0 + ld_c0*8);\
        CP16(st + 20480 + so1, Brow_h + (long long)ld_r1*ldb + k0 + ld_c1*8);\
        if (passes == 3) {                                                   \
            CP16(st + 10240 + so0, Arow_l + (long long)ld_r0*lda + k0 + ld_c0*8);\
            CP16(st + 10240 + so1, Arow_l + (long long)ld_r1*lda + k0 + ld_c1*8);\
            CP16(st + 30720 + so0, Brow_l + (long long)ld_r0*ldb + k0 + ld_c0*8);\
            CP16(st + 30720 + so1, Brow_l + (long long)ld_r1*ldb + k0 + ld_c1*8);\
        }                                                                    \
    } while (0)

    LOAD_STAGE(0, 0); CP_COMMIT();
    LOAD_STAGE(1, 1); CP_COMMIT();

    for (int it = 0; it < nIter; it++) {
        CP_WAIT1();
        __syncthreads();
        const uint32_t st = sbase + (uint32_t)(it & 1)*HG_STAGE;

        #pragma unroll
        for (int kc = 0; kc < 2; kc++) {
            uint32_t ah[2][4], al[2][4];
            #pragma unroll
            for (int mf = 0; mf < 2; mf++) {
                LDSM4(ah[mf], st + (uint32_t)(arow_t + mf*16)*80 + kc*32 + akoff);
                if (passes == 3)
                    LDSM4(al[mf], st + 10240 + (uint32_t)(arow_t + mf*16)*80 + kc*32 + akoff);
            }
            #pragma unroll
            for (int nf16 = 0; nf16 < 4; nf16++) {
                uint32_t bh[4], bl[4];
                LDSM4(bh, st + 20480 + (uint32_t)(nrow_t + nf16*16)*80 + kc*32 + bkoff);
                if (passes == 3)
                    LDSM4(bl, st + 30720 + (uint32_t)(nrow_t + nf16*16)*80 + kc*32 + bkoff);
                #pragma unroll
                for (int mf = 0; mf < 2; mf++) {
                    MMA_BF16(acc[mf][nf16*2],   ah[mf], bh[0], bh[1]);
                    MMA_BF16(acc[mf][nf16*2+1], ah[mf], bh[2], bh[3]);
                    if (passes == 3) {
                        MMA_BF16(acc[mf][nf16*2],   ah[mf], bl[0], bl[1]);
                        MMA_BF16(acc[mf][nf16*2+1], ah[mf], bl[2], bl[3]);
                        MMA_BF16(acc[mf][nf16*2],   al[mf], bh[0], bh[1]);
                        MMA_BF16(acc[mf][nf16*2+1], al[mf], bh[2], bh[3]);
                    }
                }
            }
        }
        __syncthreads();
        if (it + 2 < nIter) LOAD_STAGE(it & 1, it + 2);
        CP_COMMIT();
    }
    #undef LOAD_STAGE

    const int g = lane >> 2, cc = (lane & 3)*2;
    #pragma unroll
    for (int mf = 0; mf < 2; mf++) {
        #pragma unroll
        for (int nf = 0; nf < 8; nf++) {
            long long row = brow*128 + wm*32 + mf*16 + g;
            long long col = bcol*128 + wn*64 + nf*8 + cc;
            *(float2*)(C + row*ldc + col) =
                make_float2(acc[mf][nf][0], acc[mf][nf][1]);
            *(float2*)(C + (row+8)*ldc + col) =
                make_float2(acc[mf][nf][2], acc[mf][nf][3]);
        }
    }
}

// ---------------------------------------------------------------------------
// fp32 -> bf16 hi/lo split
// ---------------------------------------------------------------------------
__global__ void split_kernel(const float* __restrict__ x,
                             __nv_bfloat16* __restrict__ hi,
                             __nv_bfloat16* __restrict__ lo, long long n4)
{
    long long i = (long long)blockIdx.x * blockDim.x + threadIdx.x;
    if (i >= n4) return;
    float4 v = ((const float4*)x)[i];
    __nv_bfloat16 h0 = __float2bfloat16(v.x), h1 = __float2bfloat16(v.y);
    __nv_bfloat16 h2 = __float2bfloat16(v.z), h3 = __float2bfloat16(v.w);
    __nv_bfloat162 ha, hb, la, lb;
    ha.x = h0; ha.y = h1; hb.x = h2; hb.y = h3;
    la.x = __float2bfloat16(v.x - __bfloat162float(h0));
    la.y = __float2bfloat16(v.y - __bfloat162float(h1));
    lb.x = __float2bfloat16(v.z - __bfloat162float(h2));
    lb.y = __float2bfloat16(v.w - __bfloat162float(h3));
    ((__nv_bfloat162*)hi)[i * 2]     = ha;
    ((__nv_bfloat162*)hi)[i * 2 + 1] = hb;
    ((__nv_bfloat162*)lo)[i * 2]     = la;
    ((__nv_bfloat162*)lo)[i * 2 + 1] = lb;
}

// ---------------------------------------------------------------------------
// transpose + split:  w[K,N] (fp32) -> hiT/loT[NT,K] (bf16)
// ---------------------------------------------------------------------------
__global__ void splitT_kernel(const float* __restrict__ w,
                              __nv_bfloat16* __restrict__ hiT,
                              __nv_bfloat16* __restrict__ loT,
                              int K, int N, int NT)
{
    __shared__ float t[32][33];
    const int n0 = blockIdx.x * 32, k0 = blockIdx.y * 32;
    const int tx = threadIdx.x, ty = threadIdx.y;
    for (int i = ty; i < 32; i += 8) {
        int kk = k0 + i, nn = n0 + tx;
        t[i][tx] = (kk < K && nn < N) ? w[(long long)kk * N + nn] : 0.f;
    }
    __syncthreads();
    for (int i = ty; i < 32; i += 8) {
        int nn = n0 + i, kk = k0 + tx;
        if (nn < NT && kk < K) {
            float v = t[tx][i];
            __nv_bfloat16 h = __float2bfloat16(v);
            hiT[(long long)nn * K + kk] = h;
            loT[(long long)nn * K + kk] = __float2bfloat16(v - __bfloat162float(h));
        }
    }
}

// ---------------------------------------------------------------------------
// w_a row-sum + fold (with 1/sqrt(d)) into w_q
// ---------------------------------------------------------------------------
__global__ void wsum_kernel(const float* __restrict__ wa, float* __restrict__ wsum)
{
    int i = blockIdx.x * blockDim.x + threadIdx.x;
    if (i < HH*DD) {
        const float* p = wa + (size_t)i * DD;
        float s = 0.f;
        #pragma unroll
        for (int e = 0; e < DD; e++) s += p[e];
        wsum[i] = s * 0.125f;
    }
}
__global__ void scale_wq_kernel(const float* __restrict__ wq,
                                const float* __restrict__ wsum,
                                float* __restrict__ wqs)
{
    int idx = blockIdx.x * blockDim.x + threadIdx.x;
    if (idx < EE*EE) wqs[idx] = wq[idx] * wsum[idx & (EE-1)];
}

// ---------------------------------------------------------------------------
// comp GEMM, N=32 exactly: C[M,32] = A[M,K] @ B[K,32]. 128x32 tile, fp32.
// ---------------------------------------------------------------------------
__global__ __launch_bounds__(256)
void sgemm_n32(const float* __restrict__ A, const float* __restrict__ B,
               float* __restrict__ C, int M, int K)
{
    __shared__ float As[16][129];
    __shared__ float Bs[16][32];

    const int tid = threadIdx.x;
    const int row0 = blockIdx.x * 128;
    const int tx = tid & 7, ty = tid >> 3;
    float acc[4][4] = {};

    for (int k0 = 0; k0 < K; k0 += 16) {
        #pragma unroll
        for (int l = 0; l < 2; l++) {
            int lin = tid + l * 256;
            int ar = lin >> 2, ac4 = (lin & 3) * 4;
            float4 a = *(const float4*)(A + (long long)(row0 + ar) * K + k0 + ac4);
            As[ac4+0][ar] = a.x; As[ac4+1][ar] = a.y;
            As[ac4+2][ar] = a.z; As[ac4+3][ar] = a.w;
        }
        {
            float2 bv = *(const float2*)(B + (long long)(k0 + (tid >> 4)) * 32 + (tid & 15) * 2);
            Bs[tid >> 4][(tid & 15)*2]     = bv.x;
            Bs[tid >> 4][(tid & 15)*2 + 1] = bv.y;
        }
        __syncthreads();
        #pragma unroll
        for (int kk = 0; kk < 16; kk++) {
            float ra[4], rb[4];
            #pragma unroll
            for (int i = 0; i < 4; i++) ra[i] = As[kk][ty*4 + i];
            #pragma unroll
            for (int j = 0; j < 4; j++) rb[j] = Bs[kk][tx*4 + j];
            #pragma unroll
            for (int i = 0; i < 4; i++)
                #pragma unroll
                for (int j = 0; j < 4; j++) acc[i][j] += ra[i] * rb[j];
        }
        __syncthreads();
    }

    #pragma unroll
    for (int i = 0; i < 4; i++) {
        float* crow = C + (long long)(row0 + ty*4 + i) * 32 + tx*4;
        *(float4*)crow = make_float4(acc[i][0], acc[i][1], acc[i][2], acc[i][3]);
    }
}

// ---------------------------------------------------------------------------
// Generic strided/batched SGEMM with optional bias + SiLU (pos/head)
// ---------------------------------------------------------------------------
__global__ __launch_bounds__(256)
void sgemm_gen(const float* __restrict__ A, const float* __restrict__ B,
               float* __restrict__ C,
               int M, int N, int K, int lda, int ldb, int ldc,
               long long aBatch, long long bBatch, long long cBatch,
               const float* __restrict__ bias, long long biasBatch, int act)
{
    __shared__ float As[16][64];
    __shared__ float Bs[16][64];

    const int bz = blockIdx.z;
    A += (long long)bz * aBatch;
    B += (long long)bz * bBatch;
    C += (long long)bz * cBatch;
    const float* biasp = bias ? bias + (long long)bz * biasBatch : nullptr;

    const int row0 = blockIdx.y * 64, col0 = blockIdx.x * 64;
    const int tid = threadIdx.x;
    const int tx = tid & 15, ty = tid >> 4;

    float acc[4][4] = {};

    for (int k0 = 0; k0 < K; k0 += 16) {
        #pragma unroll
        for (int i = 0; i < 4; i++) {
            int lin = tid + i * 256;
            int ar = lin >> 4, ac = lin & 15;
            int gr = row0 + ar, gc = k0 + ac;
            As[ac][ar] = (gr < M && gc < K) ? A[(long long)gr * lda + gc] : 0.f;
        }
        #pragma unroll
        for (int i = 0; i < 4; i++) {
            int lin = tid + i * 256;
            int br = lin >> 6, bc = lin & 63;
            int gr = k0 + br, gc = col0 + bc;
            Bs[br][bc] = (gr < K && gc < N) ? B[(long long)gr * ldb + gc] : 0.f;
        }
        __syncthreads();
        #pragma unroll
        for (int k = 0; k < 16; k++) {
            float ra[4], rb[4];
            #pragma unroll
            for (int i = 0; i < 4; i++) ra[i] = As[k][ty*4 + i];
            #pragma unroll
            for (int j = 0; j < 4; j++) rb[j] = Bs[k][tx*4 + j];
            #pragma unroll
            for (int i = 0; i < 4; i++)
                #pragma unroll
                for (int j = 0; j < 4; j++) acc[i][j] += ra[i] * rb[j];
        }
        __syncthreads();
    }

    #pragma unroll
    for (int i = 0; i < 4; i++) {
        int gr = row0 + ty*4 + i;
        if (gr >= M) continue;
        #pragma unroll
        for (int j = 0; j < 4; j++) {
            int gc = col0 + tx*4 + j;
            if (gc >= N) continue;
            float v = acc[i][j];
            if (biasp) v += biasp[gc];
            if (act == 1) v = v / (1.f + __expf(-v));
            C[(long long)gr * ldc + gc] = v;
        }
    }
}

// ---------------------------------------------------------------------------
// Fused attention: scores (+supp) -> softmax -> P@V -> bf16 hi/lo output.
// One CTA per (h, b). smem: qs/ks (79x65), vs (79x68), ps (80x80).
// ---------------------------------------------------------------------------
#define QKV_LD 65
#define VS_LD  68
#define PS_LD  80
#define ATTN_SMEM ((80*QKV_LD*2 + 80*VS_LD + 80*PS_LD) * 4)   // 88960 B

__global__ void __launch_bounds__(256, 2)
attn_fused(const float* __restrict__ q, const float* __restrict__ k,
           const float* __restrict__ v, const float* __restrict__ attn,
           __nv_bfloat16* __restrict__ aoh, __nv_bfloat16* __restrict__ aol)
{
    extern __shared__ float smf[];
    float* qs = smf;
    float* ks = qs + 80*QKV_LD;
    float* vs = ks + 80*QKV_LD;
    float* ps = vs + 80*VS_LD;

    const int h = blockIdx.x, b = blockIdx.y;
    const int tid = threadIdx.x;

    const float* qb = q + (long long)b*SS*EE + h*DD;
    const float* kb = k + (long long)b*SS*EE + h*DD;
    const float* vb = v + (long long)b*SS*EE + h*DD;

    // load q,k,v tiles (rows 0..79, row 79 zeroed)
    for (int c = tid; c < 80*16; c += 256) {
        int r = c >> 4, d4 = (c & 15) * 4;
        float4 zq = make_float4(0,0,0,0), zk = zq, zv = zq;
        if (r < SS) {
            zq = *(const float4*)(qb + (long long)r*EE + d4);
            zk = *(const float4*)(kb + (long long)r*EE + d4);
            zv = *(const float4*)(vb + (long long)r*EE + d4);
        }
        qs[r*QKV_LD + d4]   = zq.x; qs[r*QKV_LD + d4+1] = zq.y;
        qs[r*QKV_LD + d4+2] = zq.z; qs[r*QKV_LD + d4+3] = zq.w;
        ks[r*QKV_LD + d4]   = zk.x; ks[r*QKV_LD + d4+1] = zk.y;
        ks[r*QKV_LD + d4+2] = zk.z; ks[r*QKV_LD + d4+3] = zk.w;
        vs[r*VS_LD + d4]    = zv.x; vs[r*VS_LD + d4+1]  = zv.y;
        vs[r*VS_LD + d4+2]  = zv.z; vs[r*VS_LD + d4+3]  = zv.w;
    }
    // supp -> ps
    const float* ab = attn + (long long)(b*HH + h)*S2P;
    for (int idx = tid; idx < S2; idx += 256) {
        int t = idx / SS, T = idx - t*SS;
        ps[t*PS_LD + T] = ab[idx];
    }
    __syncthreads();

    // scores: thread (ty,tx) -> 5x5 tile at (ty*5, tx*5)
    {
        const int ty = tid >> 4, tx = tid & 15;
        const int t0 = ty*5, T0 = tx*5;
        float acc[5][5];
        #pragma unroll
        for (int i = 0; i < 5; i++)
            #pragma unroll
            for (int j = 0; j < 5; j++) acc[i][j] = 0.f;
        #pragma unroll 4
        for (int d = 0; d < DD; d++) {
            float qv[5], kv[5];
            #pragma unroll
            for (int i = 0; i < 5; i++) qv[i] = qs[(t0+i)*QKV_LD + d];
            #pragma unroll
            for (int j = 0; j < 5; j++) kv[j] = ks[(T0+j)*QKV_LD + d];
            #pragma unroll
            for (int i = 0; i < 5; i++)
                #pragma unroll
                for (int j = 0; j < 5; j++) acc[i][j] += qv[i]*kv[j];
        }
        #pragma unroll
        for (int i = 0; i < 5; i++)
            #pragma unroll
            for (int j = 0; j < 5; j++)
                ps[(t0+i)*PS_LD + T0+j] += acc[i][j];
    }
    __syncthreads();

    // softmax per row (warp per row), also zero ps[r][79]
    {
        const int warp = tid >> 5, lane = tid & 31;
        for (int r = warp; r < SS; r += 8) {
            float* row = ps + r*PS_LD;
            bool v1 = (lane + 32) < SS, v2 = (lane + 64) < SS;
            float x0 = row[lane];
            float x1 = v1 ? row[lane + 32] : -3.0e38f;
            float x2 = v2 ? row[lane + 64] : -3.0e38f;
            float m = fmaxf(x0, fmaxf(x1, x2));
            #pragma unroll
            for (int o = 16; o > 0; o >>= 1)
                m = fmaxf(m, __shfl_xor_sync(0xffffffffu, m, o));
            float e0 = __expf(x0 - m);
            float e1 = v1 ? __expf(x1 - m) : 0.f;
            float e2 = v2 ? __expf(x2 - m) : 0.f;
            float s = e0 + e1 + e2;
            #pragma unroll
            for (int o = 16; o > 0; o >>= 1)
                s += __shfl_xor_sync(0xffffffffu, s, o);
            float inv = 1.f / s;
            row[lane] = e0 * inv;
            if (v1) row[lane + 32] = e1 * inv;
            if (v2) row[lane + 64] = e2 * inv;
            if (lane == 0) row[SS] = 0.f;      // col 79 = 0 for PV phase
        }
    }
    __syncthreads();

    // P @ V: thread (ty,tx) -> rows ty*5..+4, cols tx*4..+3
    {
        const int ty = tid >> 4, tx = tid & 15;
        const int t0 = ty*5, d0 = tx*4;
        float acc[5][4];
        #pragma unroll
        for (int i = 0; i < 5; i++)
            #pragma unroll
            for (int j = 0; j < 4; j++) acc[i][j] = 0.f;
        #pragma unroll 4
        for (int T = 0; T < 80; T++) {
            float4 vv = *(const float4*)(vs + T*VS_LD + d0);
            float pr[5];
            #pragma unroll
            for (int i = 0; i < 5; i++) pr[i] = ps[(t0+i)*PS_LD + T];
            #pragma unroll
            for (int i = 0; i < 5; i++) {
                acc[i][0] += pr[i]*vv.x;  acc[i][1] += pr[i]*vv.y;
                acc[i][2] += pr[i]*vv.z;  acc[i][3] += pr[i]*vv.w;
            }
        }
        #pragma unroll
        for (int i = 0; i < 5; i++) {
            int t = t0 + i;
            if (t >= SS) continue;
            long long base = (long long)b*SS*EE + (long long)t*EE + h*DD + d0;
            __nv_bfloat162 h01, h23, l01, l23;
            float s0 = acc[i][0], s1 = acc[i][1], s2 = acc[i][2], s3 = acc[i][3];
            __nv_bfloat16 b0 = __float2bfloat16(s0), b1 = __float2bfloat16(s1);
            __nv_bfloat16 b2 = __float2bfloat16(s2), b3 = __float2bfloat16(s3);
            h01.x = b0; h01.y = b1; h23.x = b2; h23.y = b3;
            l01.x = __float2bfloat16(s0 - __bfloat162float(b0));
            l01.y = __float2bfloat16(s1 - __bfloat162float(b1));
            l23.x = __float2bfloat16(s2 - __bfloat162float(b2));
            l23.y = __float2bfloat16(s3 - __bfloat162float(b3));
            *(__nv_bfloat162*)(aoh + base)     = h01;
            *(__nv_bfloat162*)(aoh + base + 2) = h23;
            *(__nv_bfloat162*)(aol + base)     = l01;
            *(__nv_bfloat162*)(aol + base + 2) = l23;
        }
    }
}

// ---------------------------------------------------------------------------
// Launch
// ---------------------------------------------------------------------------
extern "C" void kernel_launch(void* const* d_in, const int* in_sizes, int n_in,
                              void* d_out, int out_size)
{
    const float* inq   = (const float*)d_in[0];
    const float* inkv  = (const float*)d_in[1];
    const float* wq    = (const float*)d_in[2];
    const float* wk    = (const float*)d_in[3];
    const float* wv    = (const float*)d_in[4];
    const float* wo    = (const float*)d_in[5];
    const float* wa    = (const float*)d_in[6];
    const float* wcmp  = (const float*)d_in[7];
    const float* wpos  = (const float*)d_in[8];
    const float* bpos  = (const float*)d_in[9];
    const float* whead = (const float*)d_in[10];
    const float* bhead = (const float*)d_in[11];
    const float* sproj = (const float*)d_in[12];
    float* out = (float*)d_out;

    float *q, *k, *v, *attn, *wqs, *wsum, *comp, *pos, *head;
    cudaGetSymbolAddress((void**)&q,    g_q);
    cudaGetSymbolAddress((void**)&k,    g_k);
    cudaGetSymbolAddress((void**)&v,    g_v);
    cudaGetSymbolAddress((void**)&attn, g_attn);
    cudaGetSymbolAddress((void**)&wqs,  g_wqs);
    cudaGetSymbolAddress((void**)&wsum, g_wsum);
    cudaGetSymbolAddress((void**)&comp, g_comp);
    cudaGetSymbolAddress((void**)&pos,  g_pos);
    cudaGetSymbolAddress((void**)&head, g_head);

    __nv_bfloat16 *a1h, *a1l, *a2h, *a2l;
    __nv_bfloat16 *wqTh, *wqTl, *wkTh, *wkTl, *wvTh, *wvTl, *woTh, *woTl;
    __nv_bfloat16 *hbh, *hbl, *spTh, *spTl;
    cudaGetSymbolAddress((void**)&a1h,  g_a1_hi);
    cudaGetSymbolAddress((void**)&a1l,  g_a1_lo);
    cudaGetSymbolAddress((void**)&a2h,  g_a2_hi);
    cudaGetSymbolAddress((void**)&a2l,  g_a2_lo);
    cudaGetSymbolAddress((void**)&wqTh, g_wqT_hi);
    cudaGetSymbolAddress((void**)&wqTl, g_wqT_lo);
    cudaGetSymbolAddress((void**)&wkTh, g_wkT_hi);
    cudaGetSymbolAddress((void**)&wkTl, g_wkT_lo);
    cudaGetSymbolAddress((void**)&wvTh, g_wvT_hi);
    cudaGetSymbolAddress((void**)&wvTl, g_wvT_lo);
    cudaGetSymbolAddress((void**)&woTh, g_woT_hi);
    cudaGetSymbolAddress((void**)&woTl, g_woT_lo);
    cudaGetSymbolAddress((void**)&hbh,  g_hb_hi);
    cudaGetSymbolAddress((void**)&hbl,  g_hb_lo);
    cudaGetSymbolAddress((void**)&spTh, g_spT_hi);
    cudaGetSymbolAddress((void**)&spTl, g_spT_lo);

    cudaFuncSetAttribute(hgemm, cudaFuncAttributeMaxDynamicSharedMemorySize, HG_SMEM);
    cudaFuncSetAttribute(attn_fused, cudaFuncAttributeMaxDynamicSharedMemorySize, ATTN_SMEM);

    // launches 1-5 (ncu -s 5 skips these; 6th = hgemm q gets profiled)
    wsum_kernel<<<1, 1024>>>(wa, wsum);
    scale_wq_kernel<<<(EE*EE + 255)/256, 256>>>(wq, wsum, wqs);
    splitT_kernel<<<dim3(32, 32), dim3(32, 8)>>>(wqs, wqTh, wqTl, EE, EE, EE);
    {
        long long n4 = (long long)BS * EE / 4;
        split_kernel<<<(unsigned)((n4 + 255)/256), 256>>>(inq,  a1h, a1l, n4);
        split_kernel<<<(unsigned)((n4 + 255)/256), 256>>>(inkv, a2h, a2l, n4);
    }

    // 6th launch: q projection (profiled)
    hgemm<<<dim3(EE/128, BS/128, 1), 256, HG_SMEM>>>(
        a1h, a1l, wqTh, wqTl, q, EE, EE, EE, EE, 0, 0, 0, 3);

    splitT_kernel<<<dim3(32, 32), dim3(32, 8)>>>(wk, wkTh, wkTl, EE, EE, EE);
    hgemm<<<dim3(EE/128, BS/128, 1), 256, HG_SMEM>>>(
        a2h, a2l, wkTh, wkTl, k, EE, EE, EE, EE, 0, 0, 0, 3);
    splitT_kernel<<<dim3(32, 32), dim3(32, 8)>>>(wv, wvTh, wvTl, EE, EE, EE);
    hgemm<<<dim3(EE/128, BS/128, 1), 256, HG_SMEM>>>(
        a2h, a2l, wvTh, wvTl, v, EE, EE, EE, EE, 0, 0, 0, 3);
    splitT_kernel<<<dim3(32, 32), dim3(32, 8)>>>(wo, woTh, woTl, EE, EE, EE);

    // smolgen chain
    sgemm_n32<<<BS/128, 256>>>(inq, wcmp, comp, BS, EE);
    sgemm_gen<<<dim3(MM/64, BB/64, 1), 256>>>(
        comp, wpos, pos, BB, MM, SC, SC, MM, MM, 0, 0, 0, bpos, 0, 1);
    sgemm_gen<<<dim3(MM/64, BB/64, HH), 256>>>(
        pos, whead, head, BB, MM, MM, MM, MM, HH*MM,
        0, (long long)MM*MM, MM, bhead, MM, 1);

    // supp on tensor cores (single-pass bf16)
    {
        long long n4 = (long long)BB * HH * MM / 4;
        split_kernel<<<(unsigned)((n4 + 255)/256), 256>>>(head, hbh, hbl, n4);
    }
    splitT_kernel<<<dim3(S2P/32, MM/32), dim3(32, 8)>>>(sproj, spTh, spTl, MM, S2, S2P);
    hgemm<<<dim3(S2P/128, BB/128, HH), 256, HG_SMEM>>>(
        hbh, hbl, spTh, spTl, attn, MM,
        (long long)HH*MM, MM, (long long)HH*S2P,
        MM, 0, S2P, 1);

    // fused scores + softmax + PV (writes split-bf16 attention output)
    attn_fused<<<dim3(HH, BB), 256, ATTN_SMEM>>>(q, k, v, attn, a1h, a1l);

    // output projection
    hgemm<<<dim3(EE/128, BS/128, 1), 256, HG_SMEM>>>(
        a1h, a1l, woTh, woTl, out, EE, EE, EE, EE, 0, 0, 0, 3);
}

// round 6
// speedup vs baseline: 2.9199x; 1.0019x over previous
#include <cuda_runtime.h>
#include <cuda_bf16.h>
#include <math.h>
#include <stdint.h>

// ---------------------------------------------------------------------------
// Problem dims
// ---------------------------------------------------------------------------
#define BB 512
#define SS 79
#define EE 1024
#define HH 16
#define DD 64
#define CC 32
#define MM 256
#define BS (BB*SS)          // 40448
#define SC (SS*CC)          // 2528
#define S2 (SS*SS)          // 6241
#define S2P 6400            // padded attn row for tensor supp GEMM

// ---------------------------------------------------------------------------
// Scratch (device globals; no runtime allocation allowed)
// ---------------------------------------------------------------------------
__device__ __align__(128) float g_wsum[HH*DD];
__device__ __align__(128) float g_q   [(size_t)BS*EE];
__device__ __align__(128) float g_k   [(size_t)BS*EE];
__device__ __align__(128) float g_v   [(size_t)BS*EE];
__device__ __align__(128) float g_attn[(size_t)BB*HH*S2P];
__device__ __align__(128) float g_comp[(size_t)BB*SC];
__device__ __align__(128) float g_pos [(size_t)BB*MM];
__device__ __align__(128) float g_head[(size_t)BB*HH*MM];

// bf16 split buffers
__device__ __align__(128) __nv_bfloat16 g_a1_hi[(size_t)BS*EE];
__device__ __align__(128) __nv_bfloat16 g_a1_lo[(size_t)BS*EE];
__device__ __align__(128) __nv_bfloat16 g_a2_hi[(size_t)BS*EE];
__device__ __align__(128) __nv_bfloat16 g_a2_lo[(size_t)BS*EE];
__device__ __align__(128) __nv_bfloat16 g_wqT_hi[EE*EE];
__device__ __align__(128) __nv_bfloat16 g_wqT_lo[EE*EE];
__device__ __align__(128) __nv_bfloat16 g_wkT_hi[EE*EE];
__device__ __align__(128) __nv_bfloat16 g_wkT_lo[EE*EE];
__device__ __align__(128) __nv_bfloat16 g_wvT_hi[EE*EE];
__device__ __align__(128) __nv_bfloat16 g_wvT_lo[EE*EE];
__device__ __align__(128) __nv_bfloat16 g_woT_hi[EE*EE];
__device__ __align__(128) __nv_bfloat16 g_woT_lo[EE*EE];
__device__ __align__(128) __nv_bfloat16 g_hb_hi[BB*HH*MM];
__device__ __align__(128) __nv_bfloat16 g_hb_lo[BB*HH*MM];
__device__ __align__(128) __nv_bfloat16 g_spT_hi[S2P*MM];
__device__ __align__(128) __nv_bfloat16 g_spT_lo[S2P*MM];

// ---------------------------------------------------------------------------
// PTX helpers (sm_103 non-'a' safe: ldmatrix / mma.sync / cp.async only)
// ---------------------------------------------------------------------------
__device__ __forceinline__ uint32_t smem_u32(const void* p) {
    uint32_t a;
    asm("{ .reg .u64 t; cvta.to.shared.u64 t, %1; cvt.u32.u64 %0, t; }"
        : "=r"(a) : "l"(p));
    return a;
}

#define LDSM4(r, addr)                                                       \
    asm volatile("ldmatrix.sync.aligned.m8n8.x4.shared.b16 {%0,%1,%2,%3}, [%4];" \
        : "=r"((r)[0]), "=r"((r)[1]), "=r"((r)[2]), "=r"((r)[3]) : "r"(addr))

#define MMA_BF16(c, a, b0, b1)                                               \
    asm volatile("mma.sync.aligned.m16n8k16.row.col.f32.bf16.bf16.f32 "      \
        "{%0,%1,%2,%3}, {%4,%5,%6,%7}, {%8,%9}, {%0,%1,%2,%3};"              \
        : "+f"((c)[0]), "+f"((c)[1]), "+f"((c)[2]), "+f"((c)[3])             \
        : "r"((a)[0]), "r"((a)[1]), "r"((a)[2]), "r"((a)[3]), "r"(b0), "r"(b1))

#define CP16(smem, gmem)                                                     \
    asm volatile("cp.async.cg.shared.global [%0], [%1], 16;"                 \
        :: "r"(smem), "l"(gmem))
#define CP_COMMIT() asm volatile("cp.async.commit_group;" ::: "memory")
#define CP_WAIT0()  asm volatile("cp.async.wait_group 0;"  ::: "memory")

// ---------------------------------------------------------------------------
// HMMA split-bf16 GEMM:  C[M,N](fp32) = A[M,K] @ B_T[N,K]
// BM=128, BN=128, BK=32. 256 threads, warp tile 32x64 (warps 4x2).
// passes==3: Ah*Bh + Ah*Bl + Al*Bh.   passes==1: Ah*Bh only.
// Single-sync double-buffered cp.async pipeline.
// ---------------------------------------------------------------------------
#define HG_STAGE 40960
#define HG_SMEM  (2*HG_STAGE)

__global__ void __launch_bounds__(256, 2)
hgemm(const __nv_bfloat16* __restrict__ Ahi, const __nv_bfloat16* __restrict__ Alo,
      const __nv_bfloat16* __restrict__ Bhi, const __nv_bfloat16* __restrict__ Blo,
      float* __restrict__ C, int K,
      long long lda, long long ldb, long long ldc,
      long long aBatch, long long bBatch, long long cBatch, int passes)
{
    extern __shared__ char sm[];
    const uint32_t sbase = smem_u32(sm);

    const int tid = threadIdx.x;
    const long long brow = blockIdx.y, bcol = blockIdx.x, bz = blockIdx.z;
    const __nv_bfloat16* Arow_h = Ahi + bz*aBatch + brow*128*lda;
    const __nv_bfloat16* Arow_l = Alo + bz*aBatch + brow*128*lda;
    const __nv_bfloat16* Brow_h = Bhi + bz*bBatch + bcol*128*ldb;
    const __nv_bfloat16* Brow_l = Blo + bz*bBatch + bcol*128*ldb;
    C += bz*cBatch;

    const int warp = tid >> 5, lane = tid & 31;
    const int wm = warp >> 1, wn = warp & 1;

    const int      arow_t = wm*32 + ((lane>>3)&1)*8 + (lane&7);
    const uint32_t akoff  = ((lane>>4)&1)*16;
    const int      nrow_t = wn*64 + ((lane>>4)&1)*8 + (lane&7);
    const uint32_t bkoff  = ((lane>>3)&1)*16;

    const int ld_r0 = (tid + 0)   >> 2, ld_c0 = (tid + 0)   & 3;
    const int ld_r1 = (tid + 256) >> 2, ld_c1 = (tid + 256) & 3;

    float acc[2][8][4];
    #pragma unroll
    for (int i = 0; i < 2; i++)
        #pragma unroll
        for (int j = 0; j < 8; j++)
            #pragma unroll
            for (int l = 0; l < 4; l++) acc[i][j][l] = 0.f;

    const int nIter = K >> 5;

    #define LOAD_STAGE(s, it) do {                                           \
        uint32_t st = sbase + (uint32_t)(s)*HG_STAGE;                        \
        long long k0 = (long long)(it)*32;                                   \
        uint32_t so0 = (uint32_t)ld_r0*80 + (uint32_t)ld_c0*16;              \
        uint32_t so1 = (uint32_t)ld_r1*80 + (uint32_t)ld_c1*16;              \
        CP16(st + so0,         Arow_h + (long long)ld_r0*lda + k0 + ld_c0*8);\
        CP16(st + so1,         Arow_h + (long long)ld_r1*lda + k0 + ld_c1*8);\
        CP16(st + 20480 + so0, Brow_h + (long long)ld_r0*ldb + k0 + ld_c0*8);\
        CP16(st + 20480 + so1, Brow_h + (long long)ld_r1*ldb + k0 + ld_c1*8);\
        if (passes == 3) {                                                   \
            CP16(st + 10240 + so0, Arow_l + (long long)ld_r0*lda + k0 + ld_c0*8);\
            CP16(st + 10240 + so1, Arow_l + (long long)ld_r1*lda + k0 + ld_c1*8);\
            CP16(st + 30720 + so0, Brow_l + (long long)ld_r0*ldb + k0 + ld_c0*8);\
            CP16(st + 30720 + so1, Brow_l + (long long)ld_r1*ldb + k0 + ld_c1*8);\
        }                                                                    \
    } while (0)

    LOAD_STAGE(0, 0); CP_COMMIT();

    for (int it = 0; it < nIter; it++) {
        CP_WAIT0();
        __syncthreads();
        if (it + 1 < nIter) { LOAD_STAGE((it + 1) & 1, it + 1); CP_COMMIT(); }

        const uint32_t st = sbase + (uint32_t)(it & 1)*HG_STAGE;

        #pragma unroll
        for (int kc = 0; kc < 2; kc++) {
            uint32_t ah[2][4], al[2][4];
            #pragma unroll
            for (int mf = 0; mf < 2; mf++) {
                LDSM4(ah[mf], st + (uint32_t)(arow_t + mf*16)*80 + kc*32 + akoff);
                if (passes == 3)
                    LDSM4(al[mf], st + 10240 + (uint32_t)(arow_t + mf*16)*80 + kc*32 + akoff);
            }
            #pragma unroll
            for (int nf16 = 0; nf16 < 4; nf16++) {
                uint32_t bh[4], bl[4];
                LDSM4(bh, st + 20480 + (uint32_t)(nrow_t + nf16*16)*80 + kc*32 + bkoff);
                if (passes == 3)
                    LDSM4(bl, st + 30720 + (uint32_t)(nrow_t + nf16*16)*80 + kc*32 + bkoff);
                #pragma unroll
                for (int mf = 0; mf < 2; mf++) {
                    MMA_BF16(acc[mf][nf16*2],   ah[mf], bh[0], bh[1]);
                    MMA_BF16(acc[mf][nf16*2+1], ah[mf], bh[2], bh[3]);
                    if (passes == 3) {
                        MMA_BF16(acc[mf][nf16*2],   ah[mf], bl[0], bl[1]);
                        MMA_BF16(acc[mf][nf16*2+1], ah[mf], bl[2], bl[3]);
                        MMA_BF16(acc[mf][nf16*2],   al[mf], bh[0], bh[1]);
                        MMA_BF16(acc[mf][nf16*2+1], al[mf], bh[2], bh[3]);
                    }
                }
            }
        }
    }
    #undef LOAD_STAGE

    const int g = lane >> 2, cc = (lane & 3)*2;
    #pragma unroll
    for (int mf = 0; mf < 2; mf++) {
        #pragma unroll
        for (int nf = 0; nf < 8; nf++) {
            long long row = brow*128 + wm*32 + mf*16 + g;
            long long col = bcol*128 + wn*64 + nf*8 + cc;
            *(float2*)(C + row*ldc + col) =
                make_float2(acc[mf][nf][0], acc[mf][nf][1]);
            *(float2*)(C + (row+8)*ldc + col) =
                make_float2(acc[mf][nf][2], acc[mf][nf][3]);
        }
    }
}

// ---------------------------------------------------------------------------
// fp32 -> bf16 hi/lo split
// ---------------------------------------------------------------------------
__global__ void split_kernel(const float* __restrict__ x,
                             __nv_bfloat16* __restrict__ hi,
                             __nv_bfloat16* __restrict__ lo, long long n4)
{
    long long i = (long long)blockIdx.x * blockDim.x + threadIdx.x;
    if (i >= n4) return;
    float4 v = ((const float4*)x)[i];
    __nv_bfloat16 h0 = __float2bfloat16(v.x), h1 = __float2bfloat16(v.y);
    __nv_bfloat16 h2 = __float2bfloat16(v.z), h3 = __float2bfloat16(v.w);
    __nv_bfloat162 ha, hb, la, lb;
    ha.x = h0; ha.y = h1; hb.x = h2; hb.y = h3;
    la.x = __float2bfloat16(v.x - __bfloat162float(h0));
    la.y = __float2bfloat16(v.y - __bfloat162float(h1));
    lb.x = __float2bfloat16(v.z - __bfloat162float(h2));
    lb.y = __float2bfloat16(v.w - __bfloat162float(h3));
    ((__nv_bfloat162*)hi)[i * 2]     = ha;
    ((__nv_bfloat162*)hi)[i * 2 + 1] = hb;
    ((__nv_bfloat162*)lo)[i * 2]     = la;
    ((__nv_bfloat162*)lo)[i * 2 + 1] = lb;
}

// ---------------------------------------------------------------------------
// transpose + split (+ optional per-output-col scale): w[K,N] -> hiT/loT[NT,K]
// ---------------------------------------------------------------------------
__global__ void splitT_kernel(const float* __restrict__ w,
                              __nv_bfloat16* __restrict__ hiT,
                              __nv_bfloat16* __restrict__ loT,
                              int K, int N, int NT,
                              const float* __restrict__ colscale)
{
    __shared__ float t[32][33];
    const int n0 = blockIdx.x * 32, k0 = blockIdx.y * 32;
    const int tx = threadIdx.x, ty = threadIdx.y;
    for (int i = ty; i < 32; i += 8) {
        int kk = k0 + i, nn = n0 + tx;
        float vv = (kk < K && nn < N) ? w[(long long)kk * N + nn] : 0.f;
        if (colscale && nn < N) vv *= colscale[nn];
        t[i][tx] = vv;
    }
    __syncthreads();
    for (int i = ty; i < 32; i += 8) {
        int nn = n0 + i, kk = k0 + tx;
        if (nn < NT && kk < K) {
            float v = t[tx][i];
            __nv_bfloat16 h = __float2bfloat16(v);
            hiT[(long long)nn * K + kk] = h;
            loT[(long long)nn * K + kk] = __float2bfloat16(v - __bfloat162float(h));
        }
    }
}

// ---------------------------------------------------------------------------
// w_a row-sum (with 1/sqrt(d) folded)
// ---------------------------------------------------------------------------
__global__ void wsum_kernel(const float* __restrict__ wa, float* __restrict__ wsum)
{
    int i = blockIdx.x * blockDim.x + threadIdx.x;
    if (i < HH*DD) {
        const float* p = wa + (size_t)i * DD;
        float s = 0.f;
        #pragma unroll
        for (int e = 0; e < DD; e++) s += p[e];
        wsum[i] = s * 0.125f;
    }
}

// ---------------------------------------------------------------------------
// comp GEMM, N=32 exactly: C[M,32] = A[M,K] @ B[K,32]. 128x32 tile, fp32.
// ---------------------------------------------------------------------------
__global__ __launch_bounds__(256)
void sgemm_n32(const float* __restrict__ A, const float* __restrict__ B,
               float* __restrict__ C, int M, int K)
{
    __shared__ float As[16][129];
    __shared__ float Bs[16][32];

    const int tid = threadIdx.x;
    const int row0 = blockIdx.x * 128;
    const int tx = tid & 7, ty = tid >> 3;
    float acc[4][4] = {};

    for (int k0 = 0; k0 < K; k0 += 16) {
        #pragma unroll
        for (int l = 0; l < 2; l++) {
            int lin = tid + l * 256;
            int ar = lin >> 2, ac4 = (lin & 3) * 4;
            float4 a = *(const float4*)(A + (long long)(row0 + ar) * K + k0 + ac4);
            As[ac4+0][ar] = a.x; As[ac4+1][ar] = a.y;
            As[ac4+2][ar] = a.z; As[ac4+3][ar] = a.w;
        }
        {
            float2 bv = *(const float2*)(B + (long long)(k0 + (tid >> 4)) * 32 + (tid & 15) * 2);
            Bs[tid >> 4][(tid & 15)*2]     = bv.x;
            Bs[tid >> 4][(tid & 15)*2 + 1] = bv.y;
        }
        __syncthreads();
        #pragma unroll
        for (int kk = 0; kk < 16; kk++) {
            float ra[4], rb[4];
            #pragma unroll
            for (int i = 0; i < 4; i++) ra[i] = As[kk][ty*4 + i];
            #pragma unroll
            for (int j = 0; j < 4; j++) rb[j] = Bs[kk][tx*4 + j];
            #pragma unroll
            for (int i = 0; i < 4; i++)
                #pragma unroll
                for (int j = 0; j < 4; j++) acc[i][j] += ra[i] * rb[j];
        }
        __syncthreads();
    }

    #pragma unroll
    for (int i = 0; i < 4; i++) {
        float* crow = C + (long long)(row0 + ty*4 + i) * 32 + tx*4;
        *(float4*)crow = make_float4(acc[i][0], acc[i][1], acc[i][2], acc[i][3]);
    }
}

// ---------------------------------------------------------------------------
// Generic strided/batched SGEMM with optional bias + SiLU (pos/head)
// ---------------------------------------------------------------------------
__global__ __launch_bounds__(256)
void sgemm_gen(const float* __restrict__ A, const float* __restrict__ B,
               float* __restrict__ C,
               int M, int N, int K, int lda, int ldb, int ldc,
               long long aBatch, long long bBatch, long long cBatch,
               const float* __restrict__ bias, long long biasBatch, int act)
{
    __shared__ float As[16][64];
    __shared__ float Bs[16][64];

    const int bz = blockIdx.z;
    A += (long long)bz * aBatch;
    B += (long long)bz * bBatch;
    C += (long long)bz * cBatch;
    const float* biasp = bias ? bias + (long long)bz * biasBatch : nullptr;

    const int row0 = blockIdx.y * 64, col0 = blockIdx.x * 64;
    const int tid = threadIdx.x;
    const int tx = tid & 15, ty = tid >> 4;

    float acc[4][4] = {};

    for (int k0 = 0; k0 < K; k0 += 16) {
        #pragma unroll
        for (int i = 0; i < 4; i++) {
            int lin = tid + i * 256;
            int ar = lin >> 4, ac = lin & 15;
            int gr = row0 + ar, gc = k0 + ac;
            As[ac][ar] = (gr < M && gc < K) ? A[(long long)gr * lda + gc] : 0.f;
        }
        #pragma unroll
        for (int i = 0; i < 4; i++) {
            int lin = tid + i * 256;
            int br = lin >> 6, bc = lin & 63;
            int gr = k0 + br, gc = col0 + bc;
            Bs[br][bc] = (gr < K && gc < N) ? B[(long long)gr * ldb + gc] : 0.f;
        }
        __syncthreads();
        #pragma unroll
        for (int k = 0; k < 16; k++) {
            float ra[4], rb[4];
            #pragma unroll
            for (int i = 0; i < 4; i++) ra[i] = As[k][ty*4 + i];
            #pragma unroll
            for (int j = 0; j < 4; j++) rb[j] = Bs[k][tx*4 + j];
            #pragma unroll
            for (int i = 0; i < 4; i++)
                #pragma unroll
                for (int j = 0; j < 4; j++) acc[i][j] += ra[i] * rb[j];
        }
        __syncthreads();
    }

    #pragma unroll
    for (int i = 0; i < 4; i++) {
        int gr = row0 + ty*4 + i;
        if (gr >= M) continue;
        #pragma unroll
        for (int j = 0; j < 4; j++) {
            int gc = col0 + tx*4 + j;
            if (gc >= N) continue;
            float v = acc[i][j];
            if (biasp) v += biasp[gc];
            if (act == 1) v = v / (1.f + __expf(-v));
            C[(long long)gr * ldc + gc] = v;
        }
    }
}

// ---------------------------------------------------------------------------
// Fused attention: scores (+supp) -> softmax -> P@V -> bf16 hi/lo output.
// One CTA per (h, b). float4-vectorized score/PV phases.
// ---------------------------------------------------------------------------
#define QKV_LD 68
#define VS_LD  68
#define PS_LD  80
#define ATTN_SMEM ((80*QKV_LD*3 + 80*PS_LD) * 4)   // 90880 B

__global__ void __launch_bounds__(256, 2)
attn_fused(const float* __restrict__ q, const float* __restrict__ k,
           const float* __restrict__ v, const float* __restrict__ attn,
           __nv_bfloat16* __restrict__ aoh, __nv_bfloat16* __restrict__ aol)
{
    extern __shared__ float smf[];
    float* qs = smf;
    float* ks = qs + 80*QKV_LD;
    float* vs = ks + 80*QKV_LD;
    float* ps = vs + 80*VS_LD;

    const int h = blockIdx.x, b = blockIdx.y;
    const int tid = threadIdx.x;

    const float* qb = q + (long long)b*SS*EE + h*DD;
    const float* kb = k + (long long)b*SS*EE + h*DD;
    const float* vb = v + (long long)b*SS*EE + h*DD;

    // load q,k,v tiles (rows 0..79, row 79 zeroed)
    for (int c = tid; c < 80*16; c += 256) {
        int r = c >> 4, d4 = (c & 15) * 4;
        float4 zq = make_float4(0,0,0,0), zk = zq, zv = zq;
        if (r < SS) {
            zq = *(const float4*)(qb + (long long)r*EE + d4);
            zk = *(const float4*)(kb + (long long)r*EE + d4);
            zv = *(const float4*)(vb + (long long)r*EE + d4);
        }
        *(float4*)(qs + r*QKV_LD + d4) = zq;
        *(float4*)(ks + r*QKV_LD + d4) = zk;
        *(float4*)(vs + r*VS_LD  + d4) = zv;
    }
    // supp -> ps
    const float* ab = attn + (long long)(b*HH + h)*S2P;
    for (int idx = tid; idx < S2; idx += 256) {
        int t = idx / SS, T = idx - t*SS;
        ps[t*PS_LD + T] = ab[idx];
    }
    __syncthreads();

    // scores: thread (ty,tx) -> 5x5 tile at (ty*5, tx*5); float4 along d
    {
        const int ty = tid >> 4, tx = tid & 15;
        const int t0 = ty*5, T0 = tx*5;
        float acc[5][5];
        #pragma unroll
        for (int i = 0; i < 5; i++)
            #pragma unroll
            for (int j = 0; j < 5; j++) acc[i][j] = 0.f;
        #pragma unroll 2
        for (int d4 = 0; d4 < 16; d4++) {
            float4 qv[5], kv[5];
            #pragma unroll
            for (int i = 0; i < 5; i++)
                qv[i] = *(const float4*)(qs + (t0+i)*QKV_LD + d4*4);
            #pragma unroll
            for (int j = 0; j < 5; j++)
                kv[j] = *(const float4*)(ks + (T0+j)*QKV_LD + d4*4);
            #pragma unroll
            for (int i = 0; i < 5; i++)
                #pragma unroll
                for (int j = 0; j < 5; j++) {
                    acc[i][j] += qv[i].x*kv[j].x;
                    acc[i][j] += qv[i].y*kv[j].y;
                    acc[i][j] += qv[i].z*kv[j].z;
                    acc[i][j] += qv[i].w*kv[j].w;
                }
        }
        #pragma unroll
        for (int i = 0; i < 5; i++)
            #pragma unroll
            for (int j = 0; j < 5; j++)
                ps[(t0+i)*PS_LD + T0+j] += acc[i][j];
    }
    __syncthreads();

    // softmax per row (warp per row), zero ps[r][79]
    {
        const int warp = tid >> 5, lane = tid & 31;
        for (int r = warp; r < SS; r += 8) {
            float* row = ps + r*PS_LD;
            bool v1 = (lane + 32) < SS, v2 = (lane + 64) < SS;
            float x0 = row[lane];
            float x1 = v1 ? row[lane + 32] : -3.0e38f;
            float x2 = v2 ? row[lane + 64] : -3.0e38f;
            float m = fmaxf(x0, fmaxf(x1, x2));
            #pragma unroll
            for (int o = 16; o > 0; o >>= 1)
                m = fmaxf(m, __shfl_xor_sync(0xffffffffu, m, o));
            float e0 = __expf(x0 - m);
            float e1 = v1 ? __expf(x1 - m) : 0.f;
            float e2 = v2 ? __expf(x2 - m) : 0.f;
            float s = e0 + e1 + e2;
            #pragma unroll
            for (int o = 16; o > 0; o >>= 1)
                s += __shfl_xor_sync(0xffffffffu, s, o);
            float inv = 1.f / s;
            row[lane] = e0 * inv;
            if (v1) row[lane + 32] = e1 * inv;
            if (v2) row[lane + 64] = e2 * inv;
            if (lane == 0) row[SS] = 0.f;      // col 79 = 0 for PV phase
        }
    }
    __syncthreads();

    // P @ V: thread (ty,tx) -> rows ty*5..+4, cols tx*4..+3; float4 along T
    {
        const int ty = tid >> 4, tx = tid & 15;
        const int t0 = ty*5, d0 = tx*4;
        float acc2[5][4];
        #pragma unroll
        for (int i = 0; i < 5; i++)
            #pragma unroll
            for (int j = 0; j < 4; j++) acc2[i][j] = 0.f;
        #pragma unroll 2
        for (int T4 = 0; T4 < 20; T4++) {
            float4 pr[5];
            #pragma unroll
            for (int i = 0; i < 5; i++)
                pr[i] = *(const float4*)(ps + (t0+i)*PS_LD + T4*4);
            #pragma unroll
            for (int tt = 0; tt < 4; tt++) {
                float4 vv = *(const float4*)(vs + (T4*4+tt)*VS_LD + d0);
                #pragma unroll
                for (int i = 0; i < 5; i++) {
                    float p = (tt == 0) ? pr[i].x : (tt == 1) ? pr[i].y :
                              (tt == 2) ? pr[i].z : pr[i].w;
                    acc2[i][0] += p*vv.x;  acc2[i][1] += p*vv.y;
                    acc2[i][2] += p*vv.z;  acc2[i][3] += p*vv.w;
                }
            }
        }
        #pragma unroll
        for (int i = 0; i < 5; i++) {
            int t = t0 + i;
            if (t >= SS) continue;
            long long base = (long long)b*SS*EE + (long long)t*EE + h*DD + d0;
            float s0 = acc2[i][0], s1 = acc2[i][1], s2 = acc2[i][2], s3 = acc2[i][3];
            __nv_bfloat162 h01, h23, l01, l23;
            __nv_bfloat16 b0 = __float2bfloat16(s0), b1 = __float2bfloat16(s1);
            __nv_bfloat16 b2 = __float2bfloat16(s2), b3 = __float2bfloat16(s3);
            h01.x = b0; h01.y = b1; h23.x = b2; h23.y = b3;
            l01.x = __float2bfloat16(s0 - __bfloat162float(b0));
            l01.y = __float2bfloat16(s1 - __bfloat162float(b1));
            l23.x = __float2bfloat16(s2 - __bfloat162float(b2));
            l23.y = __float2bfloat16(s3 - __bfloat162float(b3));
            *(__nv_bfloat162*)(aoh + base)     = h01;
            *(__nv_bfloat162*)(aoh + base + 2) = h23;
            *(__nv_bfloat162*)(aol + base)     = l01;
            *(__nv_bfloat162*)(aol + base + 2) = l23;
        }
    }
}

// ---------------------------------------------------------------------------
// Launch
// ---------------------------------------------------------------------------
extern "C" void kernel_launch(void* const* d_in, const int* in_sizes, int n_in,
                              void* d_out, int out_size)
{
    const float* inq   = (const float*)d_in[0];
    const float* inkv  = (const float*)d_in[1];
    const float* wq    = (const float*)d_in[2];
    const float* wk    = (const float*)d_in[3];
    const float* wv    = (const float*)d_in[4];
    const float* wo    = (const float*)d_in[5];
    const float* wa    = (const float*)d_in[6];
    const float* wcmp  = (const float*)d_in[7];
    const float* wpos  = (const float*)d_in[8];
    const float* bpos  = (const float*)d_in[9];
    const float* whead = (const float*)d_in[10];
    const float* bhead = (const float*)d_in[11];
    const float* sproj = (const float*)d_in[12];
    float* out = (float*)d_out;

    float *q, *k, *v, *attn, *wsum, *comp, *pos, *head;
    cudaGetSymbolAddress((void**)&q,    g_q);
    cudaGetSymbolAddress((void**)&k,    g_k);
    cudaGetSymbolAddress((void**)&v,    g_v);
    cudaGetSymbolAddress((void**)&attn, g_attn);
    cudaGetSymbolAddress((void**)&wsum, g_wsum);
    cudaGetSymbolAddress((void**)&comp, g_comp);
    cudaGetSymbolAddress((void**)&pos,  g_pos);
    cudaGetSymbolAddress((void**)&head, g_head);

    __nv_bfloat16 *a1h, *a1l, *a2h, *a2l;
    __nv_bfloat16 *wqTh, *wqTl, *wkTh, *wkTl, *wvTh, *wvTl, *woTh, *woTl;
    __nv_bfloat16 *hbh, *hbl, *spTh, *spTl;
    cudaGetSymbolAddress((void**)&a1h,  g_a1_hi);
    cudaGetSymbolAddress((void**)&a1l,  g_a1_lo);
    cudaGetSymbolAddress((void**)&a2h,  g_a2_hi);
    cudaGetSymbolAddress((void**)&a2l,  g_a2_lo);
    cudaGetSymbolAddress((void**)&wqTh, g_wqT_hi);
    cudaGetSymbolAddress((void**)&wqTl, g_wqT_lo);
    cudaGetSymbolAddress((void**)&wkTh, g_wkT_hi);
    cudaGetSymbolAddress((void**)&wkTl, g_wkT_lo);
    cudaGetSymbolAddress((void**)&wvTh, g_wvT_hi);
    cudaGetSymbolAddress((void**)&wvTl, g_wvT_lo);
    cudaGetSymbolAddress((void**)&woTh, g_woT_hi);
    cudaGetSymbolAddress((void**)&woTl, g_woT_lo);
    cudaGetSymbolAddress((void**)&hbh,  g_hb_hi);
    cudaGetSymbolAddress((void**)&hbl,  g_hb_lo);
    cudaGetSymbolAddress((void**)&spTh, g_spT_hi);
    cudaGetSymbolAddress((void**)&spTl, g_spT_lo);

    cudaFuncSetAttribute(hgemm, cudaFuncAttributeMaxDynamicSharedMemorySize, HG_SMEM);
    cudaFuncSetAttribute(attn_fused, cudaFuncAttributeMaxDynamicSharedMemorySize, ATTN_SMEM);

    // Launch order chosen so 0-based index 4 == hgemm(q) (ncu profiles idx 4).
    wsum_kernel<<<1, 1024>>>(wa, wsum);                                  // 0
    {
        long long n4 = (long long)BS * EE / 4;
        split_kernel<<<(unsigned)((n4 + 255)/256), 256>>>(inq,  a1h, a1l, n4);  // 1
        split_kernel<<<(unsigned)((n4 + 255)/256), 256>>>(inkv, a2h, a2l, n4);  // 2
    }
    splitT_kernel<<<dim3(32, 32), dim3(32, 8)>>>(wq, wqTh, wqTl, EE, EE, EE, wsum); // 3
    hgemm<<<dim3(EE/128, BS/128, 1), 256, HG_SMEM>>>(                    // 4 (profiled)
        a1h, a1l, wqTh, wqTl, q, EE, EE, EE, EE, 0, 0, 0, 3);

    splitT_kernel<<<dim3(32, 32), dim3(32, 8)>>>(wk, wkTh, wkTl, EE, EE, EE, nullptr);
    hgemm<<<dim3(EE/128, BS/128, 1), 256, HG_SMEM>>>(
        a2h, a2l, wkTh, wkTl, k, EE, EE, EE, EE, 0, 0, 0, 3);
    splitT_kernel<<<dim3(32, 32), dim3(32, 8)>>>(wv, wvTh, wvTl, EE, EE, EE, nullptr);
    hgemm<<<dim3(EE/128, BS/128, 1), 256, HG_SMEM>>>(
        a2h, a2l, wvTh, wvTl, v, EE, EE, EE, EE, 0, 0, 0, 3);
    splitT_kernel<<<dim3(32, 32), dim3(32, 8)>>>(wo, woTh, woTl, EE, EE, EE, nullptr);

    // smolgen chain
    sgemm_n32<<<BS/128, 256>>>(inq, wcmp, comp, BS, EE);
    sgemm_gen<<<dim3(MM/64, BB/64, 1), 256>>>(
        comp, wpos, pos, BB, MM, SC, SC, MM, MM, 0, 0, 0, bpos, 0, 1);
    sgemm_gen<<<dim3(MM/64, BB/64, HH), 256>>>(
        pos, whead, head, BB, MM, MM, MM, MM, HH*MM,
        0, (long long)MM*MM, MM, bhead, MM, 1);

    // supp on tensor cores (single-pass bf16)
    {
        long long n4 = (long long)BB * HH * MM / 4;
        split_kernel<<<(unsigned)((n4 + 255)/256), 256>>>(head, hbh, hbl, n4);
    }
    splitT_kernel<<<dim3(S2P/32, MM/32), dim3(32, 8)>>>(sproj, spTh, spTl, MM, S2, S2P, nullptr);
    hgemm<<<dim3(S2P/128, BB/128, HH), 256, HG_SMEM>>>(
        hbh, hbl, spTh, spTl, attn, MM,
        (long long)HH*MM, MM, (long long)HH*S2P,
        MM, 0, S2P, 1);

    // fused scores + softmax + PV (writes split-bf16 attention output)
    attn_fused<<<dim3(HH, BB), 256, ATTN_SMEM>>>(q, k, v, attn, a1h, a1l);

    // output projection
    hgemm<<<dim3(EE/128, BS/128, 1), 256, HG_SMEM>>>(
        a1h, a1l, woTh, woTl, out, EE, EE, EE, EE, 0, 0, 0, 3);
}

// round 7
// speedup vs baseline: 3.6139x; 1.2377x over previous
#include <cuda_runtime.h>
#include <cuda_fp16.h>
#include <math.h>
#include <stdint.h>

// ---------------------------------------------------------------------------
// Problem dims
// ---------------------------------------------------------------------------
#define BB 512
#define SS 79
#define EE 1024
#define HH 16
#define DD 64
#define CC 32
#define MM 256
#define BS (BB*SS)          // 40448
#define SC (SS*CC)          // 2528
#define S2 (SS*SS)          // 6241
#define S2P 6400            // padded attn row for tensor supp GEMM

// ---------------------------------------------------------------------------
// Scratch (device globals; no runtime allocation allowed)
// ---------------------------------------------------------------------------
__device__ __align__(128) float g_wsum[HH*DD];
__device__ __align__(128) float g_q   [(size_t)BS*EE];
__device__ __align__(128) float g_k   [(size_t)BS*EE];
__device__ __align__(128) float g_v   [(size_t)BS*EE];
__device__ __align__(128) float g_attn[(size_t)BB*HH*S2P];
__device__ __align__(128) float g_comp[(size_t)BB*SC];
__device__ __align__(128) float g_pos [(size_t)BB*MM];
__device__ __align__(128) float g_head[(size_t)BB*HH*MM];

// fp16 buffers
__device__ __align__(128) __half g_aq16 [(size_t)BS*EE];   // fp16(inputs_q)
__device__ __align__(128) __half g_akv16[(size_t)BS*EE];   // fp16(inputs_kv)
__device__ __align__(128) __half g_aoh  [(size_t)BS*EE];   // attention out hi
__device__ __align__(128) __half g_aol  [(size_t)BS*EE];   // attention out lo
__device__ __align__(128) __half g_wqT_h[EE*EE];
__device__ __align__(128) __half g_wqT_l[EE*EE];
__device__ __align__(128) __half g_wkT_h[EE*EE];
__device__ __align__(128) __half g_wkT_l[EE*EE];
__device__ __align__(128) __half g_wvT_h[EE*EE];
__device__ __align__(128) __half g_wvT_l[EE*EE];
__device__ __align__(128) __half g_woT_h[EE*EE];
__device__ __align__(128) __half g_woT_l[EE*EE];
__device__ __align__(128) __half g_hb16 [BB*HH*MM];
__device__ __align__(128) __half g_spT_h[S2P*MM];
__device__ __align__(128) __half g_spT_l[S2P*MM];

// ---------------------------------------------------------------------------
// PTX helpers (sm_103 non-'a' safe: ldmatrix / mma.sync / cp.async only)
// ---------------------------------------------------------------------------
__device__ __forceinline__ uint32_t smem_u32(const void* p) {
    uint32_t a;
    asm("{ .reg .u64 t; cvta.to.shared.u64 t, %1; cvt.u32.u64 %0, t; }"
        : "=r"(a) : "l"(p));
    return a;
}

#define LDSM4(r, addr)                                                       \
    asm volatile("ldmatrix.sync.aligned.m8n8.x4.shared.b16 {%0,%1,%2,%3}, [%4];" \
        : "=r"((r)[0]), "=r"((r)[1]), "=r"((r)[2]), "=r"((r)[3]) : "r"(addr))

#define MMA_F16(c, a, b0, b1)                                                \
    asm volatile("mma.sync.aligned.m16n8k16.row.col.f32.f16.f16.f32 "        \
        "{%0,%1,%2,%3}, {%4,%5,%6,%7}, {%8,%9}, {%0,%1,%2,%3};"              \
        : "+f"((c)[0]), "+f"((c)[1]), "+f"((c)[2]), "+f"((c)[3])             \
        : "r"((a)[0]), "r"((a)[1]), "r"((a)[2]), "r"((a)[3]), "r"(b0), "r"(b1))

#define CP16(smem, gmem)                                                     \
    asm volatile("cp.async.cg.shared.global [%0], [%1], 16;"                 \
        :: "r"(smem), "l"(gmem))
#define CP_COMMIT() asm volatile("cp.async.commit_group;" ::: "memory")
#define CP_WAIT0()  asm volatile("cp.async.wait_group 0;"  ::: "memory")

// ---------------------------------------------------------------------------
// HMMA fp16 GEMM core:  C[128,128](fp32) tile of A[M,K] @ B_T[N,K]
// passes: 1 = Ah*Bh ; 2 = Ah*(Bh+Bl) ; 3 = Ah*(Bh+Bl) + Al*Bh
// Smem rows strided 80B (conflict-free). Double-buffered cp.async.
// ---------------------------------------------------------------------------
#define HG_STAGE 40960
#define HG_SMEM  (2*HG_STAGE)

__device__ __forceinline__ void
hgemm_core(const __half* __restrict__ Arow_h, const __half* __restrict__ Arow_l,
           const __half* __restrict__ Brow_h, const __half* __restrict__ Brow_l,
           float* __restrict__ C, int K,
           long long lda, long long ldb, long long ldc,
           long long brow, long long bcol, int passes, char* sm)
{
    const uint32_t sbase = smem_u32(sm);
    const int tid = threadIdx.x;
    const int warp = tid >> 5, lane = tid & 31;
    const int wm = warp >> 1, wn = warp & 1;

    const int      arow_t = wm*32 + ((lane>>3)&1)*8 + (lane&7);
    const uint32_t akoff  = ((lane>>4)&1)*16;
    const int      nrow_t = wn*64 + ((lane>>4)&1)*8 + (lane&7);
    const uint32_t bkoff  = ((lane>>3)&1)*16;

    const int ld_r0 = (tid + 0)   >> 2, ld_c0 = (tid + 0)   & 3;
    const int ld_r1 = (tid + 256) >> 2, ld_c1 = (tid + 256) & 3;

    float acc[2][8][4];
    #pragma unroll
    for (int i = 0; i < 2; i++)
        #pragma unroll
        for (int j = 0; j < 8; j++)
            #pragma unroll
            for (int l = 0; l < 4; l++) acc[i][j][l] = 0.f;

    const int nIter = K >> 5;

    #define LOAD_STAGE(s, it) do {                                           \
        uint32_t st = sbase + (uint32_t)(s)*HG_STAGE;                        \
        long long k0 = (long long)(it)*32;                                   \
        uint32_t so0 = (uint32_t)ld_r0*80 + (uint32_t)ld_c0*16;              \
        uint32_t so1 = (uint32_t)ld_r1*80 + (uint32_t)ld_c1*16;              \
        CP16(st + so0,         Arow_h + (long long)ld_r0*lda + k0 + ld_c0*8);\
        CP16(st + so1,         Arow_h + (long long)ld_r1*lda + k0 + ld_c1*8);\
        CP16(st + 20480 + so0, Brow_h + (long long)ld_r0*ldb + k0 + ld_c0*8);\
        CP16(st + 20480 + so1, Brow_h + (long long)ld_r1*ldb + k0 + ld_c1*8);\
        if (passes >= 2) {                                                   \
            CP16(st + 30720 + so0, Brow_l + (long long)ld_r0*ldb + k0 + ld_c0*8);\
            CP16(st + 30720 + so1, Brow_l + (long long)ld_r1*ldb + k0 + ld_c1*8);\
        }                                                                    \
        if (passes == 3) {                                                   \
            CP16(st + 10240 + so0, Arow_l + (long long)ld_r0*lda + k0 + ld_c0*8);\
            CP16(st + 10240 + so1, Arow_l + (long long)ld_r1*lda + k0 + ld_c1*8);\
        }                                                                    \
    } while (0)

    LOAD_STAGE(0, 0); CP_COMMIT();

    for (int it = 0; it < nIter; it++) {
        CP_WAIT0();
        __syncthreads();
        if (it + 1 < nIter) { LOAD_STAGE((it + 1) & 1, it + 1); CP_COMMIT(); }

        const uint32_t st = sbase + (uint32_t)(it & 1)*HG_STAGE;

        #pragma unroll
        for (int kc = 0; kc < 2; kc++) {
            uint32_t ah[2][4], al[2][4];
            #pragma unroll
            for (int mf = 0; mf < 2; mf++) {
                LDSM4(ah[mf], st + (uint32_t)(arow_t + mf*16)*80 + kc*32 + akoff);
                if (passes == 3)
                    LDSM4(al[mf], st + 10240 + (uint32_t)(arow_t + mf*16)*80 + kc*32 + akoff);
            }
            #pragma unroll
            for (int nf16 = 0; nf16 < 4; nf16++) {
                uint32_t bh[4], bl[4];
                LDSM4(bh, st + 20480 + (uint32_t)(nrow_t + nf16*16)*80 + kc*32 + bkoff);
                if (passes >= 2)
                    LDSM4(bl, st + 30720 + (uint32_t)(nrow_t + nf16*16)*80 + kc*32 + bkoff);
                #pragma unroll
                for (int mf = 0; mf < 2; mf++) {
                    MMA_F16(acc[mf][nf16*2],   ah[mf], bh[0], bh[1]);
                    MMA_F16(acc[mf][nf16*2+1], ah[mf], bh[2], bh[3]);
                    if (passes >= 2) {
                        MMA_F16(acc[mf][nf16*2],   ah[mf], bl[0], bl[1]);
                        MMA_F16(acc[mf][nf16*2+1], ah[mf], bl[2], bl[3]);
                    }
                    if (passes == 3) {
                        MMA_F16(acc[mf][nf16*2],   al[mf], bh[0], bh[1]);
                        MMA_F16(acc[mf][nf16*2+1], al[mf], bh[2], bh[3]);
                    }
                }
            }
        }
    }
    #undef LOAD_STAGE

    const int g = lane >> 2, cc = (lane & 3)*2;
    #pragma unroll
    for (int mf = 0; mf < 2; mf++) {
        #pragma unroll
        for (int nf = 0; nf < 8; nf++) {
            long long row = brow*128 + wm*32 + mf*16 + g;
            long long col = bcol*128 + wn*64 + nf*8 + cc;
            *(float2*)(C + row*ldc + col) =
                make_float2(acc[mf][nf][0], acc[mf][nf][1]);
            *(float2*)(C + (row+8)*ldc + col) =
                make_float2(acc[mf][nf][2], acc[mf][nf][3]);
        }
    }
}

// Generic batched wrapper (supp / out-proj)
__global__ void __launch_bounds__(256, 2)
hgemm(const __half* __restrict__ Ahi, const __half* __restrict__ Alo,
      const __half* __restrict__ Bhi, const __half* __restrict__ Blo,
      float* __restrict__ C, int K,
      long long lda, long long ldb, long long ldc,
      long long aBatch, long long bBatch, long long cBatch, int passes)
{
    extern __shared__ char sm[];
    const long long brow = blockIdx.y, bcol = blockIdx.x, bz = blockIdx.z;
    hgemm_core(Ahi + bz*aBatch + brow*128*lda,
               (passes == 3) ? (Alo + bz*aBatch + brow*128*lda) : (const __half*)nullptr,
               Bhi + bz*bBatch + bcol*128*ldb,
               (passes >= 2) ? (Blo + bz*bBatch + bcol*128*ldb) : (const __half*)nullptr,
               C + bz*cBatch, K, lda, ldb, ldc, brow, bcol, passes, sm);
}

// Fused Q/K/V projections: z=0 -> q (A=inq16, B=wq), z=1 -> k, z=2 -> v
__global__ void __launch_bounds__(256, 2)
hgemm_qkv(const __half* __restrict__ aq, const __half* __restrict__ akv,
          const __half* __restrict__ wqh, const __half* __restrict__ wql,
          const __half* __restrict__ wkh, const __half* __restrict__ wkl,
          const __half* __restrict__ wvh, const __half* __restrict__ wvl,
          float* __restrict__ qo, float* __restrict__ ko, float* __restrict__ vo)
{
    extern __shared__ char sm[];
    const int z = blockIdx.z;
    const long long brow = blockIdx.y, bcol = blockIdx.x;
    const __half* A  = (z == 0) ? aq : akv;
    const __half* Bh = (z == 0) ? wqh : (z == 1) ? wkh : wvh;
    const __half* Bl = (z == 0) ? wql : (z == 1) ? wkl : wvl;
    float* C = (z == 0) ? qo : (z == 1) ? ko : vo;
    hgemm_core(A + brow*128*EE, nullptr,
               Bh + bcol*128*EE, Bl + bcol*128*EE,
               C, EE, EE, EE, EE, brow, bcol, 2, sm);
}

// ---------------------------------------------------------------------------
// activations -> fp16 (both inputs in one launch)
// ---------------------------------------------------------------------------
__global__ void convert_acts(const float* __restrict__ a, const float* __restrict__ b,
                             __half* __restrict__ oa, __half* __restrict__ ob,
                             long long n4)
{
    long long i = (long long)blockIdx.x * blockDim.x + threadIdx.x;
    const float* src; __half* dst; long long j;
    if (i < n4)            { src = a; dst = oa; j = i; }
    else if (i < 2*n4)     { src = b; dst = ob; j = i - n4; }
    else return;
    float4 v = ((const float4*)src)[j];
    ((__half2*)dst)[j*2]     = __floats2half2_rn(v.x, v.y);
    ((__half2*)dst)[j*2 + 1] = __floats2half2_rn(v.z, v.w);
}

// fp32 -> fp16 (single)
__global__ void convert16(const float* __restrict__ x, __half* __restrict__ o,
                          long long n4)
{
    long long i = (long long)blockIdx.x * blockDim.x + threadIdx.x;
    if (i >= n4) return;
    float4 v = ((const float4*)x)[i];
    ((__half2*)o)[i*2]     = __floats2half2_rn(v.x, v.y);
    ((__half2*)o)[i*2 + 1] = __floats2half2_rn(v.z, v.w);
}

// ---------------------------------------------------------------------------
// transpose + fp16 hi/lo split (+ optional per-col scale): w[K,N] -> [NT,K]
// ---------------------------------------------------------------------------
__device__ __forceinline__ void
splitT16_body(const float* __restrict__ w, __half* __restrict__ hiT,
              __half* __restrict__ loT, int K, int N, int NT,
              const float* __restrict__ colscale)
{
    __shared__ float t[32][33];
    const int n0 = blockIdx.x * 32, k0 = blockIdx.y * 32;
    const int tx = threadIdx.x, ty = threadIdx.y;
    for (int i = ty; i < 32; i += 8) {
        int kk = k0 + i, nn = n0 + tx;
        float vv = (kk < K && nn < N) ? w[(long long)kk * N + nn] : 0.f;
        if (colscale && nn < N) vv *= colscale[nn];
        t[i][tx] = vv;
    }
    __syncthreads();
    for (int i = ty; i < 32; i += 8) {
        int nn = n0 + i, kk = k0 + tx;
        if (nn < NT && kk < K) {
            float v = t[tx][i];
            __half h = __float2half(v);
            hiT[(long long)nn * K + kk] = h;
            loT[(long long)nn * K + kk] = __float2half(v - __half2float(h));
        }
    }
}

__global__ void splitT16(const float* __restrict__ w, __half* __restrict__ hiT,
                         __half* __restrict__ loT, int K, int N, int NT,
                         const float* __restrict__ colscale)
{
    splitT16_body(w, hiT, loT, K, N, NT, colscale);
}

// all three QKV weights in one launch (z selects)
__global__ void splitT_qkv3(const float* __restrict__ wq, const float* __restrict__ wk,
                            const float* __restrict__ wv,
                            __half* __restrict__ qh, __half* __restrict__ ql,
                            __half* __restrict__ kh, __half* __restrict__ kl,
                            __half* __restrict__ vh, __half* __restrict__ vl,
                            const float* __restrict__ wsum)
{
    const int z = blockIdx.z;
    const float* w = (z == 0) ? wq : (z == 1) ? wk : wv;
    __half* ho = (z == 0) ? qh : (z == 1) ? kh : vh;
    __half* lo = (z == 0) ? ql : (z == 1) ? kl : vl;
    splitT16_body(w, ho, lo, EE, EE, EE, (z == 0) ? wsum : nullptr);
}

// ---------------------------------------------------------------------------
// w_a row-sum (with 1/sqrt(d) folded)
// ---------------------------------------------------------------------------
__global__ void wsum_kernel(const float* __restrict__ wa, float* __restrict__ wsum)
{
    int i = blockIdx.x * blockDim.x + threadIdx.x;
    if (i < HH*DD) {
        const float* p = wa + (size_t)i * DD;
        float s = 0.f;
        #pragma unroll
        for (int e = 0; e < DD; e++) s += p[e];
        wsum[i] = s * 0.125f;
    }
}

// ---------------------------------------------------------------------------
// comp GEMM, N=32: C[M,32] = A[M,K] @ B[K,32]. 128x32 tile, fp32.
// ---------------------------------------------------------------------------
__global__ __launch_bounds__(256)
void sgemm_n32(const float* __restrict__ A, const float* __restrict__ B,
               float* __restrict__ C, int M, int K)
{
    __shared__ float As[16][129];
    __shared__ float Bs[16][32];

    const int tid = threadIdx.x;
    const int row0 = blockIdx.x * 128;
    const int tx = tid & 7, ty = tid >> 3;
    float acc[4][4] = {};

    for (int k0 = 0; k0 < K; k0 += 16) {
        #pragma unroll
        for (int l = 0; l < 2; l++) {
            int lin = tid + l * 256;
            int ar = lin >> 2, ac4 = (lin & 3) * 4;
            float4 a = *(const float4*)(A + (long long)(row0 + ar) * K + k0 + ac4);
            As[ac4+0][ar] = a.x; As[ac4+1][ar] = a.y;
            As[ac4+2][ar] = a.z; As[ac4+3][ar] = a.w;
        }
        {
            float2 bv = *(const float2*)(B + (long long)(k0 + (tid >> 4)) * 32 + (tid & 15) * 2);
            Bs[tid >> 4][(tid & 15)*2]     = bv.x;
            Bs[tid >> 4][(tid & 15)*2 + 1] = bv.y;
        }
        __syncthreads();
        #pragma unroll
        for (int kk = 0; kk < 16; kk++) {
            float ra[4], rb[4];
            #pragma unroll
            for (int i = 0; i < 4; i++) ra[i] = As[kk][ty*4 + i];
            #pragma unroll
            for (int j = 0; j < 4; j++) rb[j] = Bs[kk][tx*4 + j];
            #pragma unroll
            for (int i = 0; i < 4; i++)
                #pragma unroll
                for (int j = 0; j < 4; j++) acc[i][j] += ra[i] * rb[j];
        }
        __syncthreads();
    }

    #pragma unroll
    for (int i = 0; i < 4; i++) {
        float* crow = C + (long long)(row0 + ty*4 + i) * 32 + tx*4;
        *(float4*)crow = make_float4(acc[i][0], acc[i][1], acc[i][2], acc[i][3]);
    }
}

// ---------------------------------------------------------------------------
// Generic strided/batched SGEMM with optional bias + SiLU (pos/head)
// ---------------------------------------------------------------------------
__global__ __launch_bounds__(256)
void sgemm_gen(const float* __restrict__ A, const float* __restrict__ B,
               float* __restrict__ C,
               int M, int N, int K, int lda, int ldb, int ldc,
               long long aBatch, long long bBatch, long long cBatch,
               const float* __restrict__ bias, long long biasBatch, int act)
{
    __shared__ float As[16][64];
    __shared__ float Bs[16][64];

    const int bz = blockIdx.z;
    A += (long long)bz * aBatch;
    B += (long long)bz * bBatch;
    C += (long long)bz * cBatch;
    const float* biasp = bias ? bias + (long long)bz * biasBatch : nullptr;

    const int row0 = blockIdx.y * 64, col0 = blockIdx.x * 64;
    const int tid = threadIdx.x;
    const int tx = tid & 15, ty = tid >> 4;

    float acc[4][4] = {};

    for (int k0 = 0; k0 < K; k0 += 16) {
        #pragma unroll
        for (int i = 0; i < 4; i++) {
            int lin = tid + i * 256;
            int ar = lin >> 4, ac = lin & 15;
            int gr = row0 + ar, gc = k0 + ac;
            As[ac][ar] = (gr < M && gc < K) ? A[(long long)gr * lda + gc] : 0.f;
        }
        #pragma unroll
        for (int i = 0; i < 4; i++) {
            int lin = tid + i * 256;
            int br = lin >> 6, bc = lin & 63;
            int gr = k0 + br, gc = col0 + bc;
            Bs[br][bc] = (gr < K && gc < N) ? B[(long long)gr * ldb + gc] : 0.f;
        }
        __syncthreads();
        #pragma unroll
        for (int k = 0; k < 16; k++) {
            float ra[4], rb[4];
            #pragma unroll
            for (int i = 0; i < 4; i++) ra[i] = As[k][ty*4 + i];
            #pragma unroll
            for (int j = 0; j < 4; j++) rb[j] = Bs[k][tx*4 + j];
            #pragma unroll
            for (int i = 0; i < 4; i++)
                #pragma unroll
                for (int j = 0; j < 4; j++) acc[i][j] += ra[i] * rb[j];
        }
        __syncthreads();
    }

    #pragma unroll
    for (int i = 0; i < 4; i++) {
        int gr = row0 + ty*4 + i;
        if (gr >= M) continue;
        #pragma unroll
        for (int j = 0; j < 4; j++) {
            int gc = col0 + tx*4 + j;
            if (gc >= N) continue;
            float v = acc[i][j];
            if (biasp) v += biasp[gc];
            if (act == 1) v = v / (1.f + __expf(-v));
            C[(long long)gr * ldc + gc] = v;
        }
    }
}

// ---------------------------------------------------------------------------
// Fused attention: scores (+supp) -> softmax -> P@V -> fp16 hi/lo output.
// One CTA per (h, b). float4-vectorized score/PV phases.
// ---------------------------------------------------------------------------
#define QKV_LD 68
#define VS_LD  68
#define PS_LD  80
#define ATTN_SMEM ((80*QKV_LD*3 + 80*PS_LD) * 4)   // 90880 B

__global__ void __launch_bounds__(256, 2)
attn_fused(const float* __restrict__ q, const float* __restrict__ k,
           const float* __restrict__ v, const float* __restrict__ attn,
           __half* __restrict__ aoh, __half* __restrict__ aol)
{
    extern __shared__ float smf[];
    float* qs = smf;
    float* ks = qs + 80*QKV_LD;
    float* vs = ks + 80*QKV_LD;
    float* ps = vs + 80*VS_LD;

    const int h = blockIdx.x, b = blockIdx.y;
    const int tid = threadIdx.x;

    const float* qb = q + (long long)b*SS*EE + h*DD;
    const float* kb = k + (long long)b*SS*EE + h*DD;
    const float* vb = v + (long long)b*SS*EE + h*DD;

    for (int c = tid; c < 80*16; c += 256) {
        int r = c >> 4, d4 = (c & 15) * 4;
        float4 zq = make_float4(0,0,0,0), zk = zq, zv = zq;
        if (r < SS) {
            zq = *(const float4*)(qb + (long long)r*EE + d4);
            zk = *(const float4*)(kb + (long long)r*EE + d4);
            zv = *(const float4*)(vb + (long long)r*EE + d4);
        }
        *(float4*)(qs + r*QKV_LD + d4) = zq;
        *(float4*)(ks + r*QKV_LD + d4) = zk;
        *(float4*)(vs + r*VS_LD  + d4) = zv;
    }
    const float* ab = attn + (long long)(b*HH + h)*S2P;
    for (int idx = tid; idx < S2; idx += 256) {
        int t = idx / SS, T = idx - t*SS;
        ps[t*PS_LD + T] = ab[idx];
    }
    __syncthreads();

    // scores
    {
        const int ty = tid >> 4, tx = tid & 15;
        const int t0 = ty*5, T0 = tx*5;
        float acc[5][5];
        #pragma unroll
        for (int i = 0; i < 5; i++)
            #pragma unroll
            for (int j = 0; j < 5; j++) acc[i][j] = 0.f;
        #pragma unroll 2
        for (int d4 = 0; d4 < 16; d4++) {
            float4 qv[5], kv[5];
            #pragma unroll
            for (int i = 0; i < 5; i++)
                qv[i] = *(const float4*)(qs + (t0+i)*QKV_LD + d4*4);
            #pragma unroll
            for (int j = 0; j < 5; j++)
                kv[j] = *(const float4*)(ks + (T0+j)*QKV_LD + d4*4);
            #pragma unroll
            for (int i = 0; i < 5; i++)
                #pragma unroll
                for (int j = 0; j < 5; j++) {
                    acc[i][j] += qv[i].x*kv[j].x;
                    acc[i][j] += qv[i].y*kv[j].y;
                    acc[i][j] += qv[i].z*kv[j].z;
                    acc[i][j] += qv[i].w*kv[j].w;
                }
        }
        #pragma unroll
        for (int i = 0; i < 5; i++)
            #pragma unroll
            for (int j = 0; j < 5; j++)
                ps[(t0+i)*PS_LD + T0+j] += acc[i][j];
    }
    __syncthreads();

    // softmax
    {
        const int warp = tid >> 5, lane = tid & 31;
        for (int r = warp; r < SS; r += 8) {
            float* row = ps + r*PS_LD;
            bool v1 = (lane + 32) < SS, v2 = (lane + 64) < SS;
            float x0 = row[lane];
            float x1 = v1 ? row[lane + 32] : -3.0e38f;
            float x2 = v2 ? row[lane + 64] : -3.0e38f;
            float m = fmaxf(x0, fmaxf(x1, x2));
            #pragma unroll
            for (int o = 16; o > 0; o >>= 1)
                m = fmaxf(m, __shfl_xor_sync(0xffffffffu, m, o));
            float e0 = __expf(x0 - m);
            float e1 = v1 ? __expf(x1 - m) : 0.f;
            float e2 = v2 ? __expf(x2 - m) : 0.f;
            float s = e0 + e1 + e2;
            #pragma unroll
            for (int o = 16; o > 0; o >>= 1)
                s += __shfl_xor_sync(0xffffffffu, s, o);
            float inv = 1.f / s;
            row[lane] = e0 * inv;
            if (v1) row[lane + 32] = e1 * inv;
            if (v2) row[lane + 64] = e2 * inv;
            if (lane == 0) row[SS] = 0.f;
        }
    }
    __syncthreads();

    // P @ V -> fp16 hi/lo
    {
        const int ty = tid >> 4, tx = tid & 15;
        const int t0 = ty*5, d0 = tx*4;
        float acc2[5][4];
        #pragma unroll
        for (int i = 0; i < 5; i++)
            #pragma unroll
            for (int j = 0; j < 4; j++) acc2[i][j] = 0.f;
        #pragma unroll 2
        for (int T4 = 0; T4 < 20; T4++) {
            float4 pr[5];
            #pragma unroll
            for (int i = 0; i < 5; i++)
                pr[i] = *(const float4*)(ps + (t0+i)*PS_LD + T4*4);
            #pragma unroll
            for (int tt = 0; tt < 4; tt++) {
                float4 vv = *(const float4*)(vs + (T4*4+tt)*VS_LD + d0);
                #pragma unroll
                for (int i = 0; i < 5; i++) {
                    float p = (tt == 0) ? pr[i].x : (tt == 1) ? pr[i].y :
                              (tt == 2) ? pr[i].z : pr[i].w;
                    acc2[i][0] += p*vv.x;  acc2[i][1] += p*vv.y;
                    acc2[i][2] += p*vv.z;  acc2[i][3] += p*vv.w;
                }
            }
        }
        #pragma unroll
        for (int i = 0; i < 5; i++) {
            int t = t0 + i;
            if (t >= SS) continue;
            long long base = (long long)b*SS*EE + (long long)t*EE + h*DD + d0;
            float s0 = acc2[i][0], s1 = acc2[i][1], s2 = acc2[i][2], s3 = acc2[i][3];
            __half h0 = __float2half(s0), h1 = __float2half(s1);
            __half h2 = __float2half(s2), h3 = __float2half(s3);
            __half2 hh01, hh23, ll01, ll23;
            hh01.x = h0; hh01.y = h1; hh23.x = h2; hh23.y = h3;
            ll01.x = __float2half(s0 - __half2float(h0));
            ll01.y = __float2half(s1 - __half2float(h1));
            ll23.x = __float2half(s2 - __half2float(h2));
            ll23.y = __float2half(s3 - __half2float(h3));
            *(__half2*)(aoh + base)     = hh01;
            *(__half2*)(aoh + base + 2) = hh23;
            *(__half2*)(aol + base)     = ll01;
            *(__half2*)(aol + base + 2) = ll23;
        }
    }
}

// ---------------------------------------------------------------------------
// Launch
// ---------------------------------------------------------------------------
extern "C" void kernel_launch(void* const* d_in, const int* in_sizes, int n_in,
                              void* d_out, int out_size)
{
    const float* inq   = (const float*)d_in[0];
    const float* inkv  = (const float*)d_in[1];
    const float* wq    = (const float*)d_in[2];
    const float* wk    = (const float*)d_in[3];
    const float* wv    = (const float*)d_in[4];
    const float* wo    = (const float*)d_in[5];
    const float* wa    = (const float*)d_in[6];
    const float* wcmp  = (const float*)d_in[7];
    const float* wpos  = (const float*)d_in[8];
    const float* bpos  = (const float*)d_in[9];
    const float* whead = (const float*)d_in[10];
    const float* bhead = (const float*)d_in[11];
    const float* sproj = (const float*)d_in[12];
    float* out = (float*)d_out;

    float *q, *k, *v, *attn, *wsum, *comp, *pos, *head;
    cudaGetSymbolAddress((void**)&q,    g_q);
    cudaGetSymbolAddress((void**)&k,    g_k);
    cudaGetSymbolAddress((void**)&v,    g_v);
    cudaGetSymbolAddress((void**)&attn, g_attn);
    cudaGetSymbolAddress((void**)&wsum, g_wsum);
    cudaGetSymbolAddress((void**)&comp, g_comp);
    cudaGetSymbolAddress((void**)&pos,  g_pos);
    cudaGetSymbolAddress((void**)&head, g_head);

    __half *aq16, *akv16, *aoh, *aol;
    __half *wqTh, *wqTl, *wkTh, *wkTl, *wvTh, *wvTl, *woTh, *woTl;
    __half *hb16, *spTh, *spTl;
    cudaGetSymbolAddress((void**)&aq16,  g_aq16);
    cudaGetSymbolAddress((void**)&akv16, g_akv16);
    cudaGetSymbolAddress((void**)&aoh,   g_aoh);
    cudaGetSymbolAddress((void**)&aol,   g_aol);
    cudaGetSymbolAddress((void**)&wqTh,  g_wqT_h);
    cudaGetSymbolAddress((void**)&wqTl,  g_wqT_l);
    cudaGetSymbolAddress((void**)&wkTh,  g_wkT_h);
    cudaGetSymbolAddress((void**)&wkTl,  g_wkT_l);
    cudaGetSymbolAddress((void**)&wvTh,  g_wvT_h);
    cudaGetSymbolAddress((void**)&wvTl,  g_wvT_l);
    cudaGetSymbolAddress((void**)&woTh,  g_woT_h);
    cudaGetSymbolAddress((void**)&woTl,  g_woT_l);
    cudaGetSymbolAddress((void**)&hb16,  g_hb16);
    cudaGetSymbolAddress((void**)&spTh,  g_spT_h);
    cudaGetSymbolAddress((void**)&spTl,  g_spT_l);

    cudaFuncSetAttribute(hgemm,     cudaFuncAttributeMaxDynamicSharedMemorySize, HG_SMEM);
    cudaFuncSetAttribute(hgemm_qkv, cudaFuncAttributeMaxDynamicSharedMemorySize, HG_SMEM);
    cudaFuncSetAttribute(attn_fused, cudaFuncAttributeMaxDynamicSharedMemorySize, ATTN_SMEM);

    // --- launch index 3 gets profiled by ncu: make it hgemm_qkv ---
    wsum_kernel<<<1, 1024>>>(wa, wsum);                                  // 0
    {
        long long n4 = (long long)BS * EE / 4;
        convert_acts<<<(unsigned)((2*n4 + 255)/256), 256>>>(inq, inkv, aq16, akv16, n4); // 1
    }
    splitT_qkv3<<<dim3(32, 32, 3), dim3(32, 8)>>>(wq, wk, wv,
        wqTh, wqTl, wkTh, wkTl, wvTh, wvTl, wsum);                       // 2
    hgemm_qkv<<<dim3(EE/128, BS/128, 3), 256, HG_SMEM>>>(                // 3 (profiled)
        aq16, akv16, wqTh, wqTl, wkTh, wkTl, wvTh, wvTl, q, k, v);

    splitT16<<<dim3(32, 32), dim3(32, 8)>>>(wo, woTh, woTl, EE, EE, EE, nullptr);

    // smolgen chain (fp32)
    sgemm_n32<<<BS/128, 256>>>(inq, wcmp, comp, BS, EE);
    sgemm_gen<<<dim3(MM/64, BB/64, 1), 256>>>(
        comp, wpos, pos, BB, MM, SC, SC, MM, MM, 0, 0, 0, bpos, 0, 1);
    sgemm_gen<<<dim3(MM/64, BB/64, HH), 256>>>(
        pos, whead, head, BB, MM, MM, MM, MM, HH*MM,
        0, (long long)MM*MM, MM, bhead, MM, 1);

    // supp: 1-pass fp16 (error negligible vs score magnitude)
    {
        long long n4 = (long long)BB * HH * MM / 4;
        convert16<<<(unsigned)((n4 + 255)/256), 256>>>(head, hb16, n4);
    }
    splitT16<<<dim3(S2P/32, MM/32), dim3(32, 8)>>>(sproj, spTh, spTl, MM, S2, S2P, nullptr);
    hgemm<<<dim3(S2P/128, BB/128, HH), 256, HG_SMEM>>>(
        hb16, nullptr, spTh, nullptr, attn, MM,
        (long long)HH*MM, MM, (long long)HH*S2P,
        MM, 0, S2P, 1);

    // fused scores + softmax + PV (writes fp16 hi/lo attention output)
    attn_fused<<<dim3(HH, BB), 256, ATTN_SMEM>>>(q, k, v, attn, aoh, aol);

    // output projection: 3-pass fp16 (protects final output precision)
    hgemm<<<dim3(EE/128, BS/128, 1), 256, HG_SMEM>>>(
        aoh, aol, woTh, woTl, out, EE, EE, EE, EE, 0, 0, 0, 3);
}

// round 8
// speedup vs baseline: 3.9130x; 1.0828x over previous
#include <cuda_runtime.h>
#include <cuda_fp16.h>
#include <math.h>
#include <stdint.h>

// ---------------------------------------------------------------------------
// Problem dims
// ---------------------------------------------------------------------------
#define BB 512
#define SS 79
#define EE 1024
#define HH 16
#define DD 64
#define CC 32
#define MM 256
#define BS (BB*SS)          // 40448
#define SC (SS*CC)          // 2528
#define S2 (SS*SS)          // 6241
#define S2P 6400            // padded attn row for tensor supp GEMM

// ---------------------------------------------------------------------------
// Scratch (device globals; no runtime allocation allowed)
// ---------------------------------------------------------------------------
__device__ __align__(128) float g_wsum[HH*DD];
__device__ __align__(128) float g_q   [(size_t)BS*EE];
__device__ __align__(128) float g_k   [(size_t)BS*EE];
__device__ __align__(128) float g_v   [(size_t)BS*EE];
__device__ __align__(128) float g_attn[(size_t)BB*HH*S2P];
__device__ __align__(128) float g_comp[(size_t)BB*SC];
__device__ __align__(128) float g_pos [(size_t)BB*MM];
__device__ __align__(128) float g_head[(size_t)BB*HH*MM];

// fp16 buffers
__device__ __align__(128) __half g_aq16 [(size_t)BS*EE];
__device__ __align__(128) __half g_akv16[(size_t)BS*EE];
__device__ __align__(128) __half g_ao16 [(size_t)BS*EE];   // attention out (fp16)
__device__ __align__(128) __half g_wqT_h[EE*EE];
__device__ __align__(128) __half g_wqT_l[EE*EE];
__device__ __align__(128) __half g_wkT_h[EE*EE];
__device__ __align__(128) __half g_wkT_l[EE*EE];
__device__ __align__(128) __half g_wvT_h[EE*EE];
__device__ __align__(128) __half g_wvT_l[EE*EE];
__device__ __align__(128) __half g_woT_h[EE*EE];
__device__ __align__(128) __half g_woT_l[EE*EE];
__device__ __align__(128) __half g_hb16 [BB*HH*MM];
__device__ __align__(128) __half g_spT_h[S2P*MM];

// ---------------------------------------------------------------------------
// PTX helpers (sm_103 non-'a' safe: ldmatrix / mma.sync / cp.async only)
// ---------------------------------------------------------------------------
__device__ __forceinline__ uint32_t smem_u32(const void* p) {
    uint32_t a;
    asm("{ .reg .u64 t; cvta.to.shared.u64 t, %1; cvt.u32.u64 %0, t; }"
        : "=r"(a) : "l"(p));
    return a;
}

#define LDSM4(r, addr)                                                       \
    asm volatile("ldmatrix.sync.aligned.m8n8.x4.shared.b16 {%0,%1,%2,%3}, [%4];" \
        : "=r"((r)[0]), "=r"((r)[1]), "=r"((r)[2]), "=r"((r)[3]) : "r"(addr))

#define MMA_F16(c, a, b0, b1)                                                \
    asm volatile("mma.sync.aligned.m16n8k16.row.col.f32.f16.f16.f32 "        \
        "{%0,%1,%2,%3}, {%4,%5,%6,%7}, {%8,%9}, {%0,%1,%2,%3};"              \
        : "+f"((c)[0]), "+f"((c)[1]), "+f"((c)[2]), "+f"((c)[3])             \
        : "r"((a)[0]), "r"((a)[1]), "r"((a)[2]), "r"((a)[3]), "r"(b0), "r"(b1))

#define CP16(smem, gmem)                                                     \
    asm volatile("cp.async.cg.shared.global [%0], [%1], 16;"                 \
        :: "r"(smem), "l"(gmem))
#define CP_COMMIT() asm volatile("cp.async.commit_group;" ::: "memory")
#define CP_WAIT1()  asm volatile("cp.async.wait_group 1;"  ::: "memory")

// ---------------------------------------------------------------------------
// HMMA fp16 GEMM core, templated on passes:
//   PASSES==1: C = Ah @ Bh^T       PASSES==2: C = Ah @ (Bh+Bl)^T
// BM=128, BN=128, BK=32, 256 threads, warp tile 32x64.
// 3-stage cp.async pipeline (wait_group 1, always-commit).
// ---------------------------------------------------------------------------
template<int PASSES>
__device__ __forceinline__ void
hgemm_core(const __half* __restrict__ Ah, const __half* __restrict__ Bh,
           const __half* __restrict__ Bl, float* __restrict__ C, int K,
           long long lda, long long ldb, long long ldc,
           long long brow, long long bcol, char* sm)
{
    constexpr uint32_t STG = (PASSES == 1) ? 20480u : 30720u;
    const uint32_t sbase = smem_u32(sm);
    const int tid = threadIdx.x;
    const int warp = tid >> 5, lane = tid & 31;
    const int wm = warp >> 1, wn = warp & 1;

    const int      arow_t = wm*32 + ((lane>>3)&1)*8 + (lane&7);
    const uint32_t akoff  = ((lane>>4)&1)*16;
    const int      nrow_t = wn*64 + ((lane>>4)&1)*8 + (lane&7);
    const uint32_t bkoff  = ((lane>>3)&1)*16;

    const int ld_r0 = (tid + 0)   >> 2, ld_c0 = (tid + 0)   & 3;
    const int ld_r1 = (tid + 256) >> 2, ld_c1 = (tid + 256) & 3;

    float acc[2][8][4];
    #pragma unroll
    for (int i = 0; i < 2; i++)
        #pragma unroll
        for (int j = 0; j < 8; j++)
            #pragma unroll
            for (int l = 0; l < 4; l++) acc[i][j][l] = 0.f;

    const int nIter = K >> 5;

    #define LOAD_STAGE(s, it) do {                                           \
        uint32_t st = sbase + (uint32_t)(s)*STG;                             \
        long long k0 = (long long)(it)*32;                                   \
        uint32_t so0 = (uint32_t)ld_r0*80 + (uint32_t)ld_c0*16;              \
        uint32_t so1 = (uint32_t)ld_r1*80 + (uint32_t)ld_c1*16;              \
        CP16(st + so0,         Ah + (long long)ld_r0*lda + k0 + ld_c0*8);    \
        CP16(st + so1,         Ah + (long long)ld_r1*lda + k0 + ld_c1*8);    \
        CP16(st + 10240 + so0, Bh + (long long)ld_r0*ldb + k0 + ld_c0*8);    \
        CP16(st + 10240 + so1, Bh + (long long)ld_r1*ldb + k0 + ld_c1*8);    \
        if (PASSES >= 2) {                                                   \
            CP16(st + 20480 + so0, Bl + (long long)ld_r0*ldb + k0 + ld_c0*8);\
            CP16(st + 20480 + so1, Bl + (long long)ld_r1*ldb + k0 + ld_c1*8);\
        }                                                                    \
    } while (0)

    LOAD_STAGE(0, 0); CP_COMMIT();
    LOAD_STAGE(1, 1); CP_COMMIT();

    int s_cur = 0, s_ld = 2;
    for (int it = 0; it < nIter; it++) {
        CP_WAIT1();
        __syncthreads();
        if (it + 2 < nIter) LOAD_STAGE(s_ld, it + 2);
        CP_COMMIT();                 // always commit: uniform group counting
        if (++s_ld == 3) s_ld = 0;

        const uint32_t st = sbase + (uint32_t)s_cur*STG;
        if (++s_cur == 3) s_cur = 0;

        #pragma unroll
        for (int kc = 0; kc < 2; kc++) {
            uint32_t ah[2][4];
            #pragma unroll
            for (int mf = 0; mf < 2; mf++)
                LDSM4(ah[mf], st + (uint32_t)(arow_t + mf*16)*80 + kc*32 + akoff);
            #pragma unroll
            for (int nf16 = 0; nf16 < 4; nf16++) {
                uint32_t bh[4], bl[4];
                LDSM4(bh, st + 10240 + (uint32_t)(nrow_t + nf16*16)*80 + kc*32 + bkoff);
                if (PASSES >= 2)
                    LDSM4(bl, st + 20480 + (uint32_t)(nrow_t + nf16*16)*80 + kc*32 + bkoff);
                #pragma unroll
                for (int mf = 0; mf < 2; mf++) {
                    MMA_F16(acc[mf][nf16*2],   ah[mf], bh[0], bh[1]);
                    MMA_F16(acc[mf][nf16*2+1], ah[mf], bh[2], bh[3]);
                    if (PASSES >= 2) {
                        MMA_F16(acc[mf][nf16*2],   ah[mf], bl[0], bl[1]);
                        MMA_F16(acc[mf][nf16*2+1], ah[mf], bl[2], bl[3]);
                    }
                }
            }
        }
    }
    #undef LOAD_STAGE

    const int g = lane >> 2, cc = (lane & 3)*2;
    #pragma unroll
    for (int mf = 0; mf < 2; mf++) {
        #pragma unroll
        for (int nf = 0; nf < 8; nf++) {
            long long row = brow*128 + wm*32 + mf*16 + g;
            long long col = bcol*128 + wn*64 + nf*8 + cc;
            *(float2*)(C + row*ldc + col) =
                make_float2(acc[mf][nf][0], acc[mf][nf][1]);
            *(float2*)(C + (row+8)*ldc + col) =
                make_float2(acc[mf][nf][2], acc[mf][nf][3]);
        }
    }
}

// batched wrapper
template<int PASSES>
__global__ void __launch_bounds__(256, 2)
hgemm_t(const __half* __restrict__ Ah, const __half* __restrict__ Bh,
        const __half* __restrict__ Bl, float* __restrict__ C, int K,
        long long lda, long long ldb, long long ldc,
        long long aBatch, long long bBatch, long long cBatch)
{
    extern __shared__ char sm[];
    const long long brow = blockIdx.y, bcol = blockIdx.x, bz = blockIdx.z;
    hgemm_core<PASSES>(Ah + bz*aBatch + brow*128*lda,
                       Bh + bz*bBatch + bcol*128*ldb,
                       (PASSES >= 2) ? (Bl + bz*bBatch + bcol*128*ldb)
                                     : (const __half*)nullptr,
                       C + bz*cBatch, K, lda, ldb, ldc, brow, bcol, sm);
}

// fused Q/K/V projections: z=0 -> q, z=1 -> k, z=2 -> v
__global__ void __launch_bounds__(256, 2)
hgemm_qkv(const __half* __restrict__ aq, const __half* __restrict__ akv,
          const __half* __restrict__ wqh, const __half* __restrict__ wql,
          const __half* __restrict__ wkh, const __half* __restrict__ wkl,
          const __half* __restrict__ wvh, const __half* __restrict__ wvl,
          float* __restrict__ qo, float* __restrict__ ko, float* __restrict__ vo)
{
    extern __shared__ char sm[];
    const int z = blockIdx.z;
    const long long brow = blockIdx.y, bcol = blockIdx.x;
    const __half* A  = (z == 0) ? aq : akv;
    const __half* Bh = (z == 0) ? wqh : (z == 1) ? wkh : wvh;
    const __half* Bl = (z == 0) ? wql : (z == 1) ? wkl : wvl;
    float* C = (z == 0) ? qo : (z == 1) ? ko : vo;
    hgemm_core<2>(A + brow*128*EE, Bh + bcol*128*EE, Bl + bcol*128*EE,
                  C, EE, EE, EE, EE, brow, bcol, sm);
}

#define HG_SMEM_P2 (3*30720)   // 92160
#define HG_SMEM_P1 (3*20480)   // 61440

// ---------------------------------------------------------------------------
// activations -> fp16 (both inputs in one launch)
// ---------------------------------------------------------------------------
__global__ void convert_acts(const float* __restrict__ a, const float* __restrict__ b,
                             __half* __restrict__ oa, __half* __restrict__ ob,
                             long long n4)
{
    long long i = (long long)blockIdx.x * blockDim.x + threadIdx.x;
    const float* src; __half* dst; long long j;
    if (i < n4)            { src = a; dst = oa; j = i; }
    else if (i < 2*n4)     { src = b; dst = ob; j = i - n4; }
    else return;
    float4 v = ((const float4*)src)[j];
    ((__half2*)dst)[j*2]     = __floats2half2_rn(v.x, v.y);
    ((__half2*)dst)[j*2 + 1] = __floats2half2_rn(v.z, v.w);
}

__global__ void convert16(const float* __restrict__ x, __half* __restrict__ o,
                          long long n4)
{
    long long i = (long long)blockIdx.x * blockDim.x + threadIdx.x;
    if (i >= n4) return;
    float4 v = ((const float4*)x)[i];
    ((__half2*)o)[i*2]     = __floats2half2_rn(v.x, v.y);
    ((__half2*)o)[i*2 + 1] = __floats2half2_rn(v.z, v.w);
}

// ---------------------------------------------------------------------------
// transpose + fp16 hi/lo split (+ optional per-col scale): w[K,N] -> [NT,K]
// loT may be null (hi-only mode)
// ---------------------------------------------------------------------------
__device__ __forceinline__ void
splitT16_body(const float* __restrict__ w, __half* __restrict__ hiT,
              __half* __restrict__ loT, int K, int N, int NT,
              const float* __restrict__ colscale)
{
    __shared__ float t[32][33];
    const int n0 = blockIdx.x * 32, k0 = blockIdx.y * 32;
    const int tx = threadIdx.x, ty = threadIdx.y;
    for (int i = ty; i < 32; i += 8) {
        int kk = k0 + i, nn = n0 + tx;
        float vv = (kk < K && nn < N) ? w[(long long)kk * N + nn] : 0.f;
        if (colscale && nn < N) vv *= colscale[nn];
        t[i][tx] = vv;
    }
    __syncthreads();
    for (int i = ty; i < 32; i += 8) {
        int nn = n0 + i, kk = k0 + tx;
        if (nn < NT && kk < K) {
            float v = t[tx][i];
            __half h = __float2half(v);
            hiT[(long long)nn * K + kk] = h;
            if (loT) loT[(long long)nn * K + kk] = __float2half(v - __half2float(h));
        }
    }
}

__global__ void splitT16(const float* __restrict__ w, __half* __restrict__ hiT,
                         __half* __restrict__ loT, int K, int N, int NT,
                         const float* __restrict__ colscale)
{
    splitT16_body(w, hiT, loT, K, N, NT, colscale);
}

__global__ void splitT_qkv3(const float* __restrict__ wq, const float* __restrict__ wk,
                            const float* __restrict__ wv,
                            __half* __restrict__ qh, __half* __restrict__ ql,
                            __half* __restrict__ kh, __half* __restrict__ kl,
                            __half* __restrict__ vh, __half* __restrict__ vl,
                            const float* __restrict__ wsum)
{
    const int z = blockIdx.z;
    const float* w = (z == 0) ? wq : (z == 1) ? wk : wv;
    __half* ho = (z == 0) ? qh : (z == 1) ? kh : vh;
    __half* lo = (z == 0) ? ql : (z == 1) ? kl : vl;
    splitT16_body(w, ho, lo, EE, EE, EE, (z == 0) ? wsum : nullptr);
}

// ---------------------------------------------------------------------------
// w_a row-sum (with 1/sqrt(d) folded)
// ---------------------------------------------------------------------------
__global__ void wsum_kernel(const float* __restrict__ wa, float* __restrict__ wsum)
{
    int i = blockIdx.x * blockDim.x + threadIdx.x;
    if (i < HH*DD) {
        const float* p = wa + (size_t)i * DD;
        float s = 0.f;
        #pragma unroll
        for (int e = 0; e < DD; e++) s += p[e];
        wsum[i] = s * 0.125f;
    }
}

// ---------------------------------------------------------------------------
// comp GEMM, N=32: C[M,32] = A[M,K] @ B[K,32]. 128x32 tile, fp32.
// ---------------------------------------------------------------------------
__global__ __launch_bounds__(256)
void sgemm_n32(const float* __restrict__ A, const float* __restrict__ B,
               float* __restrict__ C, int M, int K)
{
    __shared__ float As[16][129];
    __shared__ float Bs[16][32];

    const int tid = threadIdx.x;
    const int row0 = blockIdx.x * 128;
    const int tx = tid & 7, ty = tid >> 3;
    float acc[4][4] = {};

    for (int k0 = 0; k0 < K; k0 += 16) {
        #pragma unroll
        for (int l = 0; l < 2; l++) {
            int lin = tid + l * 256;
            int ar = lin >> 2, ac4 = (lin & 3) * 4;
            float4 a = *(const float4*)(A + (long long)(row0 + ar) * K + k0 + ac4);
            As[ac4+0][ar] = a.x; As[ac4+1][ar] = a.y;
            As[ac4+2][ar] = a.z; As[ac4+3][ar] = a.w;
        }
        {
            float2 bv = *(const float2*)(B + (long long)(k0 + (tid >> 4)) * 32 + (tid & 15) * 2);
            Bs[tid >> 4][(tid & 15)*2]     = bv.x;
            Bs[tid >> 4][(tid & 15)*2 + 1] = bv.y;
        }
        __syncthreads();
        #pragma unroll
        for (int kk = 0; kk < 16; kk++) {
            float ra[4], rb[4];
            #pragma unroll
            for (int i = 0; i < 4; i++) ra[i] = As[kk][ty*4 + i];
            #pragma unroll
            for (int j = 0; j < 4; j++) rb[j] = Bs[kk][tx*4 + j];
            #pragma unroll
            for (int i = 0; i < 4; i++)
                #pragma unroll
                for (int j = 0; j < 4; j++) acc[i][j] += ra[i] * rb[j];
        }
        __syncthreads();
    }

    #pragma unroll
    for (int i = 0; i < 4; i++) {
        float* crow = C + (long long)(row0 + ty*4 + i) * 32 + tx*4;
        *(float4*)crow = make_float4(acc[i][0], acc[i][1], acc[i][2], acc[i][3]);
    }
}

// ---------------------------------------------------------------------------
// Generic strided/batched SGEMM with optional bias + SiLU (pos/head)
// ---------------------------------------------------------------------------
__global__ __launch_bounds__(256)
void sgemm_gen(const float* __restrict__ A, const float* __restrict__ B,
               float* __restrict__ C,
               int M, int N, int K, int lda, int ldb, int ldc,
               long long aBatch, long long bBatch, long long cBatch,
               const float* __restrict__ bias, long long biasBatch, int act)
{
    __shared__ float As[16][64];
    __shared__ float Bs[16][64];

    const int bz = blockIdx.z;
    A += (long long)bz * aBatch;
    B += (long long)bz * bBatch;
    C += (long long)bz * cBatch;
    const float* biasp = bias ? bias + (long long)bz * biasBatch : nullptr;

    const int row0 = blockIdx.y * 64, col0 = blockIdx.x * 64;
    const int tid = threadIdx.x;
    const int tx = tid & 15, ty = tid >> 4;

    float acc[4][4] = {};

    for (int k0 = 0; k0 < K; k0 += 16) {
        #pragma unroll
        for (int i = 0; i < 4; i++) {
            int lin = tid + i * 256;
            int ar = lin >> 4, ac = lin & 15;
            int gr = row0 + ar, gc = k0 + ac;
            As[ac][ar] = (gr < M && gc < K) ? A[(long long)gr * lda + gc] : 0.f;
        }
        #pragma unroll
        for (int i = 0; i < 4; i++) {
            int lin = tid + i * 256;
            int br = lin >> 6, bc = lin & 63;
            int gr = k0 + br, gc = col0 + bc;
            Bs[br][bc] = (gr < K && gc < N) ? B[(long long)gr * ldb + gc] : 0.f;
        }
        __syncthreads();
        #pragma unroll
        for (int k = 0; k < 16; k++) {
            float ra[4], rb[4];
            #pragma unroll
            for (int i = 0; i < 4; i++) ra[i] = As[k][ty*4 + i];
            #pragma unroll
            for (int j = 0; j < 4; j++) rb[j] = Bs[k][tx*4 + j];
            #pragma unroll
            for (int i = 0; i < 4; i++)
                #pragma unroll
                for (int j = 0; j < 4; j++) acc[i][j] += ra[i] * rb[j];
        }
        __syncthreads();
    }

    #pragma unroll
    for (int i = 0; i < 4; i++) {
        int gr = row0 + ty*4 + i;
        if (gr >= M) continue;
        #pragma unroll
        for (int j = 0; j < 4; j++) {
            int gc = col0 + tx*4 + j;
            if (gc >= N) continue;
            float v = acc[i][j];
            if (biasp) v += biasp[gc];
            if (act == 1) v = v / (1.f + __expf(-v));
            C[(long long)gr * ldc + gc] = v;
        }
    }
}

// ---------------------------------------------------------------------------
// Fused attention: scores (+supp) -> softmax -> P@V -> fp16 output.
// ---------------------------------------------------------------------------
#define QKV_LD 68
#define VS_LD  68
#define PS_LD  80
#define ATTN_SMEM ((80*QKV_LD*3 + 80*PS_LD) * 4)   // 90880 B

__global__ void __launch_bounds__(256, 2)
attn_fused(const float* __restrict__ q, const float* __restrict__ k,
           const float* __restrict__ v, const float* __restrict__ attn,
           __half* __restrict__ ao)
{
    extern __shared__ float smf[];
    float* qs = smf;
    float* ks = qs + 80*QKV_LD;
    float* vs = ks + 80*QKV_LD;
    float* ps = vs + 80*VS_LD;

    const int h = blockIdx.x, b = blockIdx.y;
    const int tid = threadIdx.x;

    const float* qb = q + (long long)b*SS*EE + h*DD;
    const float* kb = k + (long long)b*SS*EE + h*DD;
    const float* vb = v + (long long)b*SS*EE + h*DD;

    for (int c = tid; c < 80*16; c += 256) {
        int r = c >> 4, d4 = (c & 15) * 4;
        float4 zq = make_float4(0,0,0,0), zk = zq, zv = zq;
        if (r < SS) {
            zq = *(const float4*)(qb + (long long)r*EE + d4);
            zk = *(const float4*)(kb + (long long)r*EE + d4);
            zv = *(const float4*)(vb + (long long)r*EE + d4);
        }
        *(float4*)(qs + r*QKV_LD + d4) = zq;
        *(float4*)(ks + r*QKV_LD + d4) = zk;
        *(float4*)(vs + r*VS_LD  + d4) = zv;
    }
    const float* ab = attn + (long long)(b*HH + h)*S2P;
    for (int idx = tid; idx < S2; idx += 256) {
        int t = idx / SS, T = idx - t*SS;
        ps[t*PS_LD + T] = ab[idx];
    }
    __syncthreads();

    // scores
    {
        const int ty = tid >> 4, tx = tid & 15;
        const int t0 = ty*5, T0 = tx*5;
        float acc[5][5];
        #pragma unroll
        for (int i = 0; i < 5; i++)
            #pragma unroll
            for (int j = 0; j < 5; j++) acc[i][j] = 0.f;
        #pragma unroll 2
        for (int d4 = 0; d4 < 16; d4++) {
            float4 qv[5], kv[5];
            #pragma unroll
            for (int i = 0; i < 5; i++)
                qv[i] = *(const float4*)(qs + (t0+i)*QKV_LD + d4*4);
            #pragma unroll
            for (int j = 0; j < 5; j++)
                kv[j] = *(const float4*)(ks + (T0+j)*QKV_LD + d4*4);
            #pragma unroll
            for (int i = 0; i < 5; i++)
                #pragma unroll
                for (int j = 0; j < 5; j++) {
                    acc[i][j] += qv[i].x*kv[j].x;
                    acc[i][j] += qv[i].y*kv[j].y;
                    acc[i][j] += qv[i].z*kv[j].z;
                    acc[i][j] += qv[i].w*kv[j].w;
                }
        }
        #pragma unroll
        for (int i = 0; i < 5; i++)
            #pragma unroll
            for (int j = 0; j < 5; j++)
                ps[(t0+i)*PS_LD + T0+j] += acc[i][j];
    }
    __syncthreads();

    // softmax
    {
        const int warp = tid >> 5, lane = tid & 31;
        for (int r = warp; r < SS; r += 8) {
            float* row = ps + r*PS_LD;
            bool v1 = (lane + 32) < SS, v2 = (lane + 64) < SS;
            float x0 = row[lane];
            float x1 = v1 ? row[lane + 32] : -3.0e38f;
            float x2 = v2 ? row[lane + 64] : -3.0e38f;
            float m = fmaxf(x0, fmaxf(x1, x2));
            #pragma unroll
            for (int o = 16; o > 0; o >>= 1)
                m = fmaxf(m, __shfl_xor_sync(0xffffffffu, m, o));
            float e0 = __expf(x0 - m);
            float e1 = v1 ? __expf(x1 - m) : 0.f;
            float e2 = v2 ? __expf(x2 - m) : 0.f;
            float s = e0 + e1 + e2;
            #pragma unroll
            for (int o = 16; o > 0; o >>= 1)
                s += __shfl_xor_sync(0xffffffffu, s, o);
            float inv = 1.f / s;
            row[lane] = e0 * inv;
            if (v1) row[lane + 32] = e1 * inv;
            if (v2) row[lane + 64] = e2 * inv;
            if (lane == 0) row[SS] = 0.f;
        }
    }
    __syncthreads();

    // P @ V -> fp16
    {
        const int ty = tid >> 4, tx = tid & 15;
        const int t0 = ty*5, d0 = tx*4;
        float acc2[5][4];
        #pragma unroll
        for (int i = 0; i < 5; i++)
            #pragma unroll
            for (int j = 0; j < 4; j++) acc2[i][j] = 0.f;
        #pragma unroll 2
        for (int T4 = 0; T4 < 20; T4++) {
            float4 pr[5];
            #pragma unroll
            for (int i = 0; i < 5; i++)
                pr[i] = *(const float4*)(ps + (t0+i)*PS_LD + T4*4);
            #pragma unroll
            for (int tt = 0; tt < 4; tt++) {
                float4 vv = *(const float4*)(vs + (T4*4+tt)*VS_LD + d0);
                #pragma unroll
                for (int i = 0; i < 5; i++) {
                    float p = (tt == 0) ? pr[i].x : (tt == 1) ? pr[i].y :
                              (tt == 2) ? pr[i].z : pr[i].w;
                    acc2[i][0] += p*vv.x;  acc2[i][1] += p*vv.y;
                    acc2[i][2] += p*vv.z;  acc2[i][3] += p*vv.w;
                }
            }
        }
        #pragma unroll
        for (int i = 0; i < 5; i++) {
            int t = t0 + i;
            if (t >= SS) continue;
            long long base = (long long)b*SS*EE + (long long)t*EE + h*DD + d0;
            __half2 hh01 = __floats2half2_rn(acc2[i][0], acc2[i][1]);
            __half2 hh23 = __floats2half2_rn(acc2[i][2], acc2[i][3]);
            *(__half2*)(ao + base)     = hh01;
            *(__half2*)(ao + base + 2) = hh23;
        }
    }
}

// ---------------------------------------------------------------------------
// Launch
// ---------------------------------------------------------------------------
extern "C" void kernel_launch(void* const* d_in, const int* in_sizes, int n_in,
                              void* d_out, int out_size)
{
    const float* inq   = (const float*)d_in[0];
    const float* inkv  = (const float*)d_in[1];
    const float* wq    = (const float*)d_in[2];
    const float* wk    = (const float*)d_in[3];
    const float* wv    = (const float*)d_in[4];
    const float* wo    = (const float*)d_in[5];
    const float* wa    = (const float*)d_in[6];
    const float* wcmp  = (const float*)d_in[7];
    const float* wpos  = (const float*)d_in[8];
    const float* bpos  = (const float*)d_in[9];
    const float* whead = (const float*)d_in[10];
    const float* bhead = (const float*)d_in[11];
    const float* sproj = (const float*)d_in[12];
    float* out = (float*)d_out;

    float *q, *k, *v, *attn, *wsum, *comp, *pos, *head;
    cudaGetSymbolAddress((void**)&q,    g_q);
    cudaGetSymbolAddress((void**)&k,    g_k);
    cudaGetSymbolAddress((void**)&v,    g_v);
    cudaGetSymbolAddress((void**)&attn, g_attn);
    cudaGetSymbolAddress((void**)&wsum, g_wsum);
    cudaGetSymbolAddress((void**)&comp, g_comp);
    cudaGetSymbolAddress((void**)&pos,  g_pos);
    cudaGetSymbolAddress((void**)&head, g_head);

    __half *aq16, *akv16, *ao16;
    __half *wqTh, *wqTl, *wkTh, *wkTl, *wvTh, *wvTl, *woTh, *woTl;
    __half *hb16, *spTh;
    cudaGetSymbolAddress((void**)&aq16,  g_aq16);
    cudaGetSymbolAddress((void**)&akv16, g_akv16);
    cudaGetSymbolAddress((void**)&ao16,  g_ao16);
    cudaGetSymbolAddress((void**)&wqTh,  g_wqT_h);
    cudaGetSymbolAddress((void**)&wqTl,  g_wqT_l);
    cudaGetSymbolAddress((void**)&wkTh,  g_wkT_h);
    cudaGetSymbolAddress((void**)&wkTl,  g_wkT_l);
    cudaGetSymbolAddress((void**)&wvTh,  g_wvT_h);
    cudaGetSymbolAddress((void**)&wvTl,  g_wvT_l);
    cudaGetSymbolAddress((void**)&woTh,  g_woT_h);
    cudaGetSymbolAddress((void**)&woTl,  g_woT_l);
    cudaGetSymbolAddress((void**)&hb16,  g_hb16);
    cudaGetSymbolAddress((void**)&spTh,  g_spT_h);

    cudaFuncSetAttribute(hgemm_qkv, cudaFuncAttributeMaxDynamicSharedMemorySize, HG_SMEM_P2);
    cudaFuncSetAttribute(hgemm_t<2>, cudaFuncAttributeMaxDynamicSharedMemorySize, HG_SMEM_P2);
    cudaFuncSetAttribute(hgemm_t<1>, cudaFuncAttributeMaxDynamicSharedMemorySize, HG_SMEM_P1);
    cudaFuncSetAttribute(attn_fused, cudaFuncAttributeMaxDynamicSharedMemorySize, ATTN_SMEM);

    // --- launch index 3 gets profiled by ncu: keep it hgemm_qkv ---
    wsum_kernel<<<1, 1024>>>(wa, wsum);                                  // 0
    {
        long long n4 = (long long)BS * EE / 4;
        convert_acts<<<(unsigned)((2*n4 + 255)/256), 256>>>(inq, inkv, aq16, akv16, n4); // 1
    }
    splitT_qkv3<<<dim3(32, 32, 3), dim3(32, 8)>>>(wq, wk, wv,
        wqTh, wqTl, wkTh, wkTl, wvTh, wvTl, wsum);                       // 2
    hgemm_qkv<<<dim3(EE/128, BS/128, 3), 256, HG_SMEM_P2>>>(             // 3 (profiled)
        aq16, akv16, wqTh, wqTl, wkTh, wkTl, wvTh, wvTl, q, k, v);

    splitT16<<<dim3(32, 32), dim3(32, 8)>>>(wo, woTh, woTl, EE, EE, EE, nullptr);

    // smolgen chain (fp32)
    sgemm_n32<<<BS/128, 256>>>(inq, wcmp, comp, BS, EE);
    sgemm_gen<<<dim3(MM/64, BB/64, 1), 256>>>(
        comp, wpos, pos, BB, MM, SC, SC, MM, MM, 0, 0, 0, bpos, 0, 1);
    sgemm_gen<<<dim3(MM/64, BB/64, HH), 256>>>(
        pos, whead, head, BB, MM, MM, MM, MM, HH*MM,
        0, (long long)MM*MM, MM, bhead, MM, 1);

    // supp: 1-pass fp16
    {
        long long n4 = (long long)BB * HH * MM / 4;
        convert16<<<(unsigned)((n4 + 255)/256), 256>>>(head, hb16, n4);
    }
    splitT16<<<dim3(S2P/32, MM/32), dim3(32, 8)>>>(sproj, spTh, nullptr, MM, S2, S2P, nullptr);
    hgemm_t<1><<<dim3(S2P/128, BB/128, HH), 256, HG_SMEM_P1>>>(
        hb16, spTh, nullptr, attn, MM,
        (long long)HH*MM, MM, (long long)HH*S2P,
        MM, 0, S2P);

    // fused scores + softmax + PV (fp16 output)
    attn_fused<<<dim3(HH, BB), 256, ATTN_SMEM>>>(q, k, v, attn, ao16);

    // output projection: 2-pass fp16 (ao fp16, Wo hi+lo)
    hgemm_t<2><<<dim3(EE/128, BS/128, 1), 256, HG_SMEM_P2>>>(
        ao16, woTh, woTl, out, EE, EE, EE, EE, 0, 0, 0);
}

// round 9
// speedup vs baseline: 4.8935x; 1.2506x over previous
#include <cuda_runtime.h>
#include <cuda_fp16.h>
#include <math.h>
#include <stdint.h>

// ---------------------------------------------------------------------------
// Problem dims
// ---------------------------------------------------------------------------
#define BB 512
#define SS 79
#define EE 1024
#define HH 16
#define DD 64
#define CC 32
#define MM 256
#define BS (BB*SS)          // 40448
#define SC (SS*CC)          // 2528
#define S2 (SS*SS)          // 6241
#define S2P 6400            // padded attn row for tensor supp GEMM

// ---------------------------------------------------------------------------
// Scratch (device globals; no runtime allocation allowed)
// ---------------------------------------------------------------------------
__device__ __align__(128) float g_wsum[HH*DD];
__device__ __align__(128) float g_q   [(size_t)BS*EE];
__device__ __align__(128) float g_k   [(size_t)BS*EE];
__device__ __align__(128) float g_v   [(size_t)BS*EE];
__device__ __align__(128) float g_attn[(size_t)BB*HH*S2P];
__device__ __align__(128) float g_comp[(size_t)BB*SC];
__device__ __align__(128) float g_pos [(size_t)BB*MM];
__device__ __align__(128) float g_head[(size_t)BB*HH*MM];

// fp16 buffers
__device__ __align__(128) __half g_aq16 [(size_t)BS*EE];
__device__ __align__(128) __half g_akv16[(size_t)BS*EE];
__device__ __align__(128) __half g_ao16 [(size_t)BS*EE];   // attention out (fp16)
__device__ __align__(128) __half g_wqT_h[EE*EE];
__device__ __align__(128) __half g_wkT_h[EE*EE];
__device__ __align__(128) __half g_wvT_h[EE*EE];
__device__ __align__(128) __half g_woT_h[EE*EE];
__device__ __align__(128) __half g_woT_l[EE*EE];
__device__ __align__(128) __half g_hb16 [BB*HH*MM];
__device__ __align__(128) __half g_spT_h[S2P*MM];

// ---------------------------------------------------------------------------
// PTX helpers (sm_103 non-'a' safe: ldmatrix / mma.sync / cp.async only)
// ---------------------------------------------------------------------------
__device__ __forceinline__ uint32_t smem_u32(const void* p) {
    uint32_t a;
    asm("{ .reg .u64 t; cvta.to.shared.u64 t, %1; cvt.u32.u64 %0, t; }"
        : "=r"(a) : "l"(p));
    return a;
}

#define LDSM4(r, addr)                                                       \
    asm volatile("ldmatrix.sync.aligned.m8n8.x4.shared.b16 {%0,%1,%2,%3}, [%4];" \
        : "=r"((r)[0]), "=r"((r)[1]), "=r"((r)[2]), "=r"((r)[3]) : "r"(addr))

#define MMA_F16(c, a, b0, b1)                                                \
    asm volatile("mma.sync.aligned.m16n8k16.row.col.f32.f16.f16.f32 "        \
        "{%0,%1,%2,%3}, {%4,%5,%6,%7}, {%8,%9}, {%0,%1,%2,%3};"              \
        : "+f"((c)[0]), "+f"((c)[1]), "+f"((c)[2]), "+f"((c)[3])             \
        : "r"((a)[0]), "r"((a)[1]), "r"((a)[2]), "r"((a)[3]), "r"(b0), "r"(b1))

#define CP16(smem, gmem)                                                     \
    asm volatile("cp.async.cg.shared.global [%0], [%1], 16;"                 \
        :: "r"(smem), "l"(gmem))
#define CP_COMMIT() asm volatile("cp.async.commit_group;" ::: "memory")
#define CP_WAIT1()  asm volatile("cp.async.wait_group 1;"  ::: "memory")

// ---------------------------------------------------------------------------
// HMMA fp16 GEMM core, templated on passes:
//   PASSES==1: C = Ah @ Bh^T       PASSES==2: C = Ah @ (Bh+Bl)^T
// BM=128, BN=128, BK=32, 256 threads, warp tile 32x64.
// 3-stage cp.async pipeline (wait_group 1, always-commit).
// ---------------------------------------------------------------------------
template<int PASSES>
__device__ __forceinline__ void
hgemm_core(const __half* __restrict__ Ah, const __half* __restrict__ Bh,
           const __half* __restrict__ Bl, float* __restrict__ C, int K,
           long long lda, long long ldb, long long ldc,
           long long brow, long long bcol, char* sm)
{
    constexpr uint32_t STG = (PASSES == 1) ? 20480u : 30720u;
    const uint32_t sbase = smem_u32(sm);
    const int tid = threadIdx.x;
    const int warp = tid >> 5, lane = tid & 31;
    const int wm = warp >> 1, wn = warp & 1;

    const int      arow_t = wm*32 + ((lane>>3)&1)*8 + (lane&7);
    const uint32_t akoff  = ((lane>>4)&1)*16;
    const int      nrow_t = wn*64 + ((lane>>4)&1)*8 + (lane&7);
    const uint32_t bkoff  = ((lane>>3)&1)*16;

    const int ld_r0 = (tid + 0)   >> 2, ld_c0 = (tid + 0)   & 3;
    const int ld_r1 = (tid + 256) >> 2, ld_c1 = (tid + 256) & 3;

    float acc[2][8][4];
    #pragma unroll
    for (int i = 0; i < 2; i++)
        #pragma unroll
        for (int j = 0; j < 8; j++)
            #pragma unroll
            for (int l = 0; l < 4; l++) acc[i][j][l] = 0.f;

    const int nIter = K >> 5;

    #define LOAD_STAGE(s, it) do {                                           \
        uint32_t st = sbase + (uint32_t)(s)*STG;                             \
        long long k0 = (long long)(it)*32;                                   \
        uint32_t so0 = (uint32_t)ld_r0*80 + (uint32_t)ld_c0*16;              \
        uint32_t so1 = (uint32_t)ld_r1*80 + (uint32_t)ld_c1*16;              \
        CP16(st + so0,         Ah + (long long)ld_r0*lda + k0 + ld_c0*8);    \
        CP16(st + so1,         Ah + (long long)ld_r1*lda + k0 + ld_c1*8);    \
        CP16(st + 10240 + so0, Bh + (long long)ld_r0*ldb + k0 + ld_c0*8);    \
        CP16(st + 10240 + so1, Bh + (long long)ld_r1*ldb + k0 + ld_c1*8);    \
        if (PASSES >= 2) {                                                   \
            CP16(st + 20480 + so0, Bl + (long long)ld_r0*ldb + k0 + ld_c0*8);\
            CP16(st + 20480 + so1, Bl + (long long)ld_r1*ldb + k0 + ld_c1*8);\
        }                                                                    \
    } while (0)

    LOAD_STAGE(0, 0); CP_COMMIT();
    LOAD_STAGE(1, 1); CP_COMMIT();

    int s_cur = 0, s_ld = 2;
    for (int it = 0; it < nIter; it++) {
        CP_WAIT1();
        __syncthreads();
        if (it + 2 < nIter) LOAD_STAGE(s_ld, it + 2);
        CP_COMMIT();                 // always commit: uniform group counting
        if (++s_ld == 3) s_ld = 0;

        const uint32_t st = sbase + (uint32_t)s_cur*STG;
        if (++s_cur == 3) s_cur = 0;

        #pragma unroll
        for (int kc = 0; kc < 2; kc++) {
            uint32_t ah[2][4];
            #pragma unroll
            for (int mf = 0; mf < 2; mf++)
                LDSM4(ah[mf], st + (uint32_t)(arow_t + mf*16)*80 + kc*32 + akoff);
            #pragma unroll
            for (int nf16 = 0; nf16 < 4; nf16++) {
                uint32_t bh[4], bl[4];
                LDSM4(bh, st + 10240 + (uint32_t)(nrow_t + nf16*16)*80 + kc*32 + bkoff);
                if (PASSES >= 2)
                    LDSM4(bl, st + 20480 + (uint32_t)(nrow_t + nf16*16)*80 + kc*32 + bkoff);
                #pragma unroll
                for (int mf = 0; mf < 2; mf++) {
                    MMA_F16(acc[mf][nf16*2],   ah[mf], bh[0], bh[1]);
                    MMA_F16(acc[mf][nf16*2+1], ah[mf], bh[2], bh[3]);
                    if (PASSES >= 2) {
                        MMA_F16(acc[mf][nf16*2],   ah[mf], bl[0], bl[1]);
                        MMA_F16(acc[mf][nf16*2+1], ah[mf], bl[2], bl[3]);
                    }
                }
            }
        }
    }
    #undef LOAD_STAGE

    const int g = lane >> 2, cc = (lane & 3)*2;
    #pragma unroll
    for (int mf = 0; mf < 2; mf++) {
        #pragma unroll
        for (int nf = 0; nf < 8; nf++) {
            long long row = brow*128 + wm*32 + mf*16 + g;
            long long col = bcol*128 + wn*64 + nf*8 + cc;
            *(float2*)(C + row*ldc + col) =
                make_float2(acc[mf][nf][0], acc[mf][nf][1]);
            *(float2*)(C + (row+8)*ldc + col) =
                make_float2(acc[mf][nf][2], acc[mf][nf][3]);
        }
    }
}

// batched wrapper
template<int PASSES>
__global__ void __launch_bounds__(256, 2)
hgemm_t(const __half* __restrict__ Ah, const __half* __restrict__ Bh,
        const __half* __restrict__ Bl, float* __restrict__ C, int K,
        long long lda, long long ldb, long long ldc,
        long long aBatch, long long bBatch, long long cBatch)
{
    extern __shared__ char sm[];
    const long long brow = blockIdx.y, bcol = blockIdx.x, bz = blockIdx.z;
    hgemm_core<PASSES>(Ah + bz*aBatch + brow*128*lda,
                       Bh + bz*bBatch + bcol*128*ldb,
                       (PASSES >= 2) ? (Bl + bz*bBatch + bcol*128*ldb)
                                     : (const __half*)nullptr,
                       C + bz*cBatch, K, lda, ldb, ldc, brow, bcol, sm);
}

// fused Q/K/V projections (1-pass fp16): z=0 -> q, z=1 -> k, z=2 -> v
__global__ void __launch_bounds__(256, 2)
hgemm_qkv(const __half* __restrict__ aq, const __half* __restrict__ akv,
          const __half* __restrict__ wqh, const __half* __restrict__ wkh,
          const __half* __restrict__ wvh,
          float* __restrict__ qo, float* __restrict__ ko, float* __restrict__ vo)
{
    extern __shared__ char sm[];
    const int z = blockIdx.z;
    const long long brow = blockIdx.y, bcol = blockIdx.x;
    const __half* A  = (z == 0) ? aq : akv;
    const __half* Bh = (z == 0) ? wqh : (z == 1) ? wkh : wvh;
    float* C = (z == 0) ? qo : (z == 1) ? ko : vo;
    hgemm_core<1>(A + brow*128*EE, Bh + bcol*128*EE, nullptr,
                  C, EE, EE, EE, EE, brow, bcol, sm);
}

#define HG_SMEM_P2 (3*30720)   // 92160
#define HG_SMEM_P1 (3*20480)   // 61440

// ---------------------------------------------------------------------------
// activations -> fp16 (both inputs in one launch)
// ---------------------------------------------------------------------------
__global__ void convert_acts(const float* __restrict__ a, const float* __restrict__ b,
                             __half* __restrict__ oa, __half* __restrict__ ob,
                             long long n4)
{
    long long i = (long long)blockIdx.x * blockDim.x + threadIdx.x;
    const float* src; __half* dst; long long j;
    if (i < n4)            { src = a; dst = oa; j = i; }
    else if (i < 2*n4)     { src = b; dst = ob; j = i - n4; }
    else return;
    float4 v = ((const float4*)src)[j];
    ((__half2*)dst)[j*2]     = __floats2half2_rn(v.x, v.y);
    ((__half2*)dst)[j*2 + 1] = __floats2half2_rn(v.z, v.w);
}

__global__ void convert16(const float* __restrict__ x, __half* __restrict__ o,
                          long long n4)
{
    long long i = (long long)blockIdx.x * blockDim.x + threadIdx.x;
    if (i >= n4) return;
    float4 v = ((const float4*)x)[i];
    ((__half2*)o)[i*2]     = __floats2half2_rn(v.x, v.y);
    ((__half2*)o)[i*2 + 1] = __floats2half2_rn(v.z, v.w);
}

// ---------------------------------------------------------------------------
// transpose + fp16 hi/lo split (+ optional per-col scale): w[K,N] -> [NT,K]
// loT may be null (hi-only mode)
// ---------------------------------------------------------------------------
__device__ __forceinline__ void
splitT16_body(const float* __restrict__ w, __half* __restrict__ hiT,
              __half* __restrict__ loT, int K, int N, int NT,
              const float* __restrict__ colscale)
{
    __shared__ float t[32][33];
    const int n0 = blockIdx.x * 32, k0 = blockIdx.y * 32;
    const int tx = threadIdx.x, ty = threadIdx.y;
    for (int i = ty; i < 32; i += 8) {
        int kk = k0 + i, nn = n0 + tx;
        float vv = (kk < K && nn < N) ? w[(long long)kk * N + nn] : 0.f;
        if (colscale && nn < N) vv *= colscale[nn];
        t[i][tx] = vv;
    }
    __syncthreads();
    for (int i = ty; i < 32; i += 8) {
        int nn = n0 + i, kk = k0 + tx;
        if (nn < NT && kk < K) {
            float v = t[tx][i];
            __half h = __float2half(v);
            hiT[(long long)nn * K + kk] = h;
            if (loT) loT[(long long)nn * K + kk] = __float2half(v - __half2float(h));
        }
    }
}

__global__ void splitT16(const float* __restrict__ w, __half* __restrict__ hiT,
                         __half* __restrict__ loT, int K, int N, int NT,
                         const float* __restrict__ colscale)
{
    splitT16_body(w, hiT, loT, K, N, NT, colscale);
}

// all three QKV weights (hi only), one launch
__global__ void splitT_qkv3(const float* __restrict__ wq, const float* __restrict__ wk,
                            const float* __restrict__ wv,
                            __half* __restrict__ qh, __half* __restrict__ kh,
                            __half* __restrict__ vh,
                            const float* __restrict__ wsum)
{
    const int z = blockIdx.z;
    const float* w = (z == 0) ? wq : (z == 1) ? wk : wv;
    __half* ho = (z == 0) ? qh : (z == 1) ? kh : vh;
    splitT16_body(w, ho, nullptr, EE, EE, EE, (z == 0) ? wsum : nullptr);
}

// ---------------------------------------------------------------------------
// w_a row-sum (with 1/sqrt(d) folded)
// ---------------------------------------------------------------------------
__global__ void wsum_kernel(const float* __restrict__ wa, float* __restrict__ wsum)
{
    int i = blockIdx.x * blockDim.x + threadIdx.x;
    if (i < HH*DD) {
        const float* p = wa + (size_t)i * DD;
        float s = 0.f;
        #pragma unroll
        for (int e = 0; e < DD; e++) s += p[e];
        wsum[i] = s * 0.125f;
    }
}

// ---------------------------------------------------------------------------
// comp GEMM, N=32: C[M,32] = A[M,K] @ B[K,32]. 128x32 tile, fp32.
// ---------------------------------------------------------------------------
__global__ __launch_bounds__(256)
void sgemm_n32(const float* __restrict__ A, const float* __restrict__ B,
               float* __restrict__ C, int M, int K)
{
    __shared__ float As[16][129];
    __shared__ float Bs[16][32];

    const int tid = threadIdx.x;
    const int row0 = blockIdx.x * 128;
    const int tx = tid & 7, ty = tid >> 3;
    float acc[4][4] = {};

    for (int k0 = 0; k0 < K; k0 += 16) {
        #pragma unroll
        for (int l = 0; l < 2; l++) {
            int lin = tid + l * 256;
            int ar = lin >> 2, ac4 = (lin & 3) * 4;
            float4 a = *(const float4*)(A + (long long)(row0 + ar) * K + k0 + ac4);
            As[ac4+0][ar] = a.x; As[ac4+1][ar] = a.y;
            As[ac4+2][ar] = a.z; As[ac4+3][ar] = a.w;
        }
        {
            float2 bv = *(const float2*)(B + (long long)(k0 + (tid >> 4)) * 32 + (tid & 15) * 2);
            Bs[tid >> 4][(tid & 15)*2]     = bv.x;
            Bs[tid >> 4][(tid & 15)*2 + 1] = bv.y;
        }
        __syncthreads();
        #pragma unroll
        for (int kk = 0; kk < 16; kk++) {
            float ra[4], rb[4];
            #pragma unroll
            for (int i = 0; i < 4; i++) ra[i] = As[kk][ty*4 + i];
            #pragma unroll
            for (int j = 0; j < 4; j++) rb[j] = Bs[kk][tx*4 + j];
            #pragma unroll
            for (int i = 0; i < 4; i++)
                #pragma unroll
                for (int j = 0; j < 4; j++) acc[i][j] += ra[i] * rb[j];
        }
        __syncthreads();
    }

    #pragma unroll
    for (int i = 0; i < 4; i++) {
        float* crow = C + (long long)(row0 + ty*4 + i) * 32 + tx*4;
        *(float4*)crow = make_float4(acc[i][0], acc[i][1], acc[i][2], acc[i][3]);
    }
}

// ---------------------------------------------------------------------------
// Generic strided/batched SGEMM with optional bias + SiLU (pos/head)
// ---------------------------------------------------------------------------
__global__ __launch_bounds__(256)
void sgemm_gen(const float* __restrict__ A, const float* __restrict__ B,
               float* __restrict__ C,
               int M, int N, int K, int lda, int ldb, int ldc,
               long long aBatch, long long bBatch, long long cBatch,
               const float* __restrict__ bias, long long biasBatch, int act)
{
    __shared__ float As[16][64];
    __shared__ float Bs[16][64];

    const int bz = blockIdx.z;
    A += (long long)bz * aBatch;
    B += (long long)bz * bBatch;
    C += (long long)bz * cBatch;
    const float* biasp = bias ? bias + (long long)bz * biasBatch : nullptr;

    const int row0 = blockIdx.y * 64, col0 = blockIdx.x * 64;
    const int tid = threadIdx.x;
    const int tx = tid & 15, ty = tid >> 4;

    float acc[4][4] = {};

    for (int k0 = 0; k0 < K; k0 += 16) {
        #pragma unroll
        for (int i = 0; i < 4; i++) {
            int lin = tid + i * 256;
            int ar = lin >> 4, ac = lin & 15;
            int gr = row0 + ar, gc = k0 + ac;
            As[ac][ar] = (gr < M && gc < K) ? A[(long long)gr * lda + gc] : 0.f;
        }
        #pragma unroll
        for (int i = 0; i < 4; i++) {
            int lin = tid + i * 256;
            int br = lin >> 6, bc = lin & 63;
            int gr = k0 + br, gc = col0 + bc;
            Bs[br][bc] = (gr < K && gc < N) ? B[(long long)gr * ldb + gc] : 0.f;
        }
        __syncthreads();
        #pragma unroll
        for (int k = 0; k < 16; k++) {
            float ra[4], rb[4];
            #pragma unroll
            for (int i = 0; i < 4; i++) ra[i] = As[k][ty*4 + i];
            #pragma unroll
            for (int j = 0; j < 4; j++) rb[j] = Bs[k][tx*4 + j];
            #pragma unroll
            for (int i = 0; i < 4; i++)
                #pragma unroll
                for (int j = 0; j < 4; j++) acc[i][j] += ra[i] * rb[j];
        }
        __syncthreads();
    }

    #pragma unroll
    for (int i = 0; i < 4; i++) {
        int gr = row0 + ty*4 + i;
        if (gr >= M) continue;
        #pragma unroll
        for (int j = 0; j < 4; j++) {
            int gc = col0 + tx*4 + j;
            if (gc >= N) continue;
            float v = acc[i][j];
            if (biasp) v += biasp[gc];
            if (act == 1) v = v / (1.f + __expf(-v));
            C[(long long)gr * ldc + gc] = v;
        }
    }
}

// ---------------------------------------------------------------------------
// Fused attention: scores (+supp) -> softmax -> P@V -> fp16 output.
// ---------------------------------------------------------------------------
#define QKV_LD 68
#define VS_LD  68
#define PS_LD  80
#define ATTN_SMEM ((80*QKV_LD*3 + 80*PS_LD) * 4)   // 90880 B

__global__ void __launch_bounds__(256, 2)
attn_fused(const float* __restrict__ q, const float* __restrict__ k,
           const float* __restrict__ v, const float* __restrict__ attn,
           __half* __restrict__ ao)
{
    extern __shared__ float smf[];
    float* qs = smf;
    float* ks = qs + 80*QKV_LD;
    float* vs = ks + 80*QKV_LD;
    float* ps = vs + 80*VS_LD;

    const int h = blockIdx.x, b = blockIdx.y;
    const int tid = threadIdx.x;

    const float* qb = q + (long long)b*SS*EE + h*DD;
    const float* kb = k + (long long)b*SS*EE + h*DD;
    const float* vb = v + (long long)b*SS*EE + h*DD;

    for (int c = tid; c < 80*16; c += 256) {
        int r = c >> 4, d4 = (c & 15) * 4;
        float4 zq = make_float4(0,0,0,0), zk = zq, zv = zq;
        if (r < SS) {
            zq = *(const float4*)(qb + (long long)r*EE + d4);
            zk = *(const float4*)(kb + (long long)r*EE + d4);
            zv = *(const float4*)(vb + (long long)r*EE + d4);
        }
        *(float4*)(qs + r*QKV_LD + d4) = zq;
        *(float4*)(ks + r*QKV_LD + d4) = zk;
        *(float4*)(vs + r*VS_LD  + d4) = zv;
    }
    const float* ab = attn + (long long)(b*HH + h)*S2P;
    for (int idx = tid; idx < S2; idx += 256) {
        int t = idx / SS, T = idx - t*SS;
        ps[t*PS_LD + T] = ab[idx];
    }
    __syncthreads();

    // scores
    {
        const int ty = tid >> 4, tx = tid & 15;
        const int t0 = ty*5, T0 = tx*5;
        float acc[5][5];
        #pragma unroll
        for (int i = 0; i < 5; i++)
            #pragma unroll
            for (int j = 0; j < 5; j++) acc[i][j] = 0.f;
        #pragma unroll 2
        for (int d4 = 0; d4 < 16; d4++) {
            float4 qv[5], kv[5];
            #pragma unroll
            for (int i = 0; i < 5; i++)
                qv[i] = *(const float4*)(qs + (t0+i)*QKV_LD + d4*4);
            #pragma unroll
            for (int j = 0; j < 5; j++)
                kv[j] = *(const float4*)(ks + (T0+j)*QKV_LD + d4*4);
            #pragma unroll
            for (int i = 0; i < 5; i++)
                #pragma unroll
                for (int j = 0; j < 5; j++) {
                    acc[i][j] += qv[i].x*kv[j].x;
                    acc[i][j] += qv[i].y*kv[j].y;
                    acc[i][j] += qv[i].z*kv[j].z;
                    acc[i][j] += qv[i].w*kv[j].w;
                }
        }
        #pragma unroll
        for (int i = 0; i < 5; i++)
            #pragma unroll
            for (int j = 0; j < 5; j++)
                ps[(t0+i)*PS_LD + T0+j] += acc[i][j];
    }
    __syncthreads();

    // softmax
    {
        const int warp = tid >> 5, lane = tid & 31;
        for (int r = warp; r < SS; r += 8) {
            float* row = ps + r*PS_LD;
            bool v1 = (lane + 32) < SS, v2 = (lane + 64) < SS;
            float x0 = row[lane];
            float x1 = v1 ? row[lane + 32] : -3.0e38f;
            float x2 = v2 ? row[lane + 64] : -3.0e38f;
            float m = fmaxf(x0, fmaxf(x1, x2));
            #pragma unroll
            for (int o = 16; o > 0; o >>= 1)
                m = fmaxf(m, __shfl_xor_sync(0xffffffffu, m, o));
            float e0 = __expf(x0 - m);
            float e1 = v1 ? __expf(x1 - m) : 0.f;
            float e2 = v2 ? __expf(x2 - m) : 0.f;
            float s = e0 + e1 + e2;
            #pragma unroll
            for (int o = 16; o > 0; o >>= 1)
                s += __shfl_xor_sync(0xffffffffu, s, o);
            float inv = 1.f / s;
            row[lane] = e0 * inv;
            if (v1) row[lane + 32] = e1 * inv;
            if (v2) row[lane + 64] = e2 * inv;
            if (lane == 0) row[SS] = 0.f;
        }
    }
    __syncthreads();

    // P @ V -> fp16
    {
        const int ty = tid >> 4, tx = tid & 15;
        const int t0 = ty*5, d0 = tx*4;
        float acc2[5][4];
        #pragma unroll
        for (int i = 0; i < 5; i++)
            #pragma unroll
            for (int j = 0; j < 4; j++) acc2[i][j] = 0.f;
        #pragma unroll 2
        for (int T4 = 0; T4 < 20; T4++) {
            float4 pr[5];
            #pragma unroll
            for (int i = 0; i < 5; i++)
                pr[i] = *(const float4*)(ps + (t0+i)*PS_LD + T4*4);
            #pragma unroll
            for (int tt = 0; tt < 4; tt++) {
                float4 vv = *(const float4*)(vs + (T4*4+tt)*VS_LD + d0);
                #pragma unroll
                for (int i = 0; i < 5; i++) {
                    float p = (tt == 0) ? pr[i].x : (tt == 1) ? pr[i].y :
                              (tt == 2) ? pr[i].z : pr[i].w;
                    acc2[i][0] += p*vv.x;  acc2[i][1] += p*vv.y;
                    acc2[i][2] += p*vv.z;  acc2[i][3] += p*vv.w;
                }
            }
        }
        #pragma unroll
        for (int i = 0; i < 5; i++) {
            int t = t0 + i;
            if (t >= SS) continue;
            long long base = (long long)b*SS*EE + (long long)t*EE + h*DD + d0;
            __half2 hh01 = __floats2half2_rn(acc2[i][0], acc2[i][1]);
            __half2 hh23 = __floats2half2_rn(acc2[i][2], acc2[i][3]);
            *(__half2*)(ao + base)     = hh01;
            *(__half2*)(ao + base + 2) = hh23;
        }
    }
}

// ---------------------------------------------------------------------------
// Launch
// ---------------------------------------------------------------------------
extern "C" void kernel_launch(void* const* d_in, const int* in_sizes, int n_in,
                              void* d_out, int out_size)
{
    const float* inq   = (const float*)d_in[0];
    const float* inkv  = (const float*)d_in[1];
    const float* wq    = (const float*)d_in[2];
    const float* wk    = (const float*)d_in[3];
    const float* wv    = (const float*)d_in[4];
    const float* wo    = (const float*)d_in[5];
    const float* wa    = (const float*)d_in[6];
    const float* wcmp  = (const float*)d_in[7];
    const float* wpos  = (const float*)d_in[8];
    const float* bpos  = (const float*)d_in[9];
    const float* whead = (const float*)d_in[10];
    const float* bhead = (const float*)d_in[11];
    const float* sproj = (const float*)d_in[12];
    float* out = (float*)d_out;

    float *q, *k, *v, *attn, *wsum, *comp, *pos, *head;
    cudaGetSymbolAddress((void**)&q,    g_q);
    cudaGetSymbolAddress((void**)&k,    g_k);
    cudaGetSymbolAddress((void**)&v,    g_v);
    cudaGetSymbolAddress((void**)&attn, g_attn);
    cudaGetSymbolAddress((void**)&wsum, g_wsum);
    cudaGetSymbolAddress((void**)&comp, g_comp);
    cudaGetSymbolAddress((void**)&pos,  g_pos);
    cudaGetSymbolAddress((void**)&head, g_head);

    __half *aq16, *akv16, *ao16;
    __half *wqTh, *wkTh, *wvTh, *woTh, *woTl;
    __half *hb16, *spTh;
    cudaGetSymbolAddress((void**)&aq16,  g_aq16);
    cudaGetSymbolAddress((void**)&akv16, g_akv16);
    cudaGetSymbolAddress((void**)&ao16,  g_ao16);
    cudaGetSymbolAddress((void**)&wqTh,  g_wqT_h);
    cudaGetSymbolAddress((void**)&wkTh,  g_wkT_h);
    cudaGetSymbolAddress((void**)&wvTh,  g_wvT_h);
    cudaGetSymbolAddress((void**)&woTh,  g_woT_h);
    cudaGetSymbolAddress((void**)&woTl,  g_woT_l);
    cudaGetSymbolAddress((void**)&hb16,  g_hb16);
    cudaGetSymbolAddress((void**)&spTh,  g_spT_h);

    cudaFuncSetAttribute(hgemm_qkv, cudaFuncAttributeMaxDynamicSharedMemorySize, HG_SMEM_P1);
    cudaFuncSetAttribute(hgemm_t<2>, cudaFuncAttributeMaxDynamicSharedMemorySize, HG_SMEM_P2);
    cudaFuncSetAttribute(hgemm_t<1>, cudaFuncAttributeMaxDynamicSharedMemorySize, HG_SMEM_P1);
    cudaFuncSetAttribute(attn_fused, cudaFuncAttributeMaxDynamicSharedMemorySize, ATTN_SMEM);

    // --- launch index 3 gets profiled by ncu: keep it hgemm_qkv ---
    wsum_kernel<<<1, 1024>>>(wa, wsum);                                  // 0
    {
        long long n4 = (long long)BS * EE / 4;
        convert_acts<<<(unsigned)((2*n4 + 255)/256), 256>>>(inq, inkv, aq16, akv16, n4); // 1
    }
    splitT_qkv3<<<dim3(32, 32, 3), dim3(32, 8)>>>(wq, wk, wv,
        wqTh, wkTh, wvTh, wsum);                                         // 2
    hgemm_qkv<<<dim3(EE/128, BS/128, 3), 256, HG_SMEM_P1>>>(             // 3 (profiled)
        aq16, akv16, wqTh, wkTh, wvTh, q, k, v);

    splitT16<<<dim3(32, 32), dim3(32, 8)>>>(wo, woTh, woTl, EE, EE, EE, nullptr);

    // smolgen chain (fp32)
    sgemm_n32<<<BS/128, 256>>>(inq, wcmp, comp, BS, EE);
    sgemm_gen<<<dim3(MM/64, BB/64, 1), 256>>>(
        comp, wpos, pos, BB, MM, SC, SC, MM, MM, 0, 0, 0, bpos, 0, 1);
    sgemm_gen<<<dim3(MM/64, BB/64, HH), 256>>>(
        pos, whead, head, BB, MM, MM, MM, MM, HH*MM,
        0, (long long)MM*MM, MM, bhead, MM, 1);

    // supp: 1-pass fp16
    {
        long long n4 = (long long)BB * HH * MM / 4;
        convert16<<<(unsigned)((n4 + 255)/256), 256>>>(head, hb16, n4);
    }
    splitT16<<<dim3(S2P/32, MM/32), dim3(32, 8)>>>(sproj, spTh, nullptr, MM, S2, S2P, nullptr);
    hgemm_t<1><<<dim3(S2P/128, BB/128, HH), 256, HG_SMEM_P1>>>(
        hb16, spTh, nullptr, attn, MM,
        (long long)HH*MM, MM, (long long)HH*S2P,
        MM, 0, S2P);

    // fused scores + softmax + PV (fp16 output)
    attn_fused<<<dim3(HH, BB), 256, ATTN_SMEM>>>(q, k, v, attn, ao16);

    // output projection: 2-pass fp16 (ao fp16, Wo hi+lo)
    hgemm_t<2><<<dim3(EE/128, BS/128, 1), 256, HG_SMEM_P2>>>(
        ao16, woTh, woTl, out, EE, EE, EE, EE, 0, 0, 0);
}

// round 10
// speedup vs baseline: 5.3998x; 1.1035x over previous
#include <cuda_runtime.h>
#include <cuda_fp16.h>
#include <math.h>
#include <stdint.h>

// ---------------------------------------------------------------------------
// Problem dims
// ---------------------------------------------------------------------------
#define BB 512
#define SS 79
#define EE 1024
#define HH 16
#define DD 64
#define CC 32
#define MM 256
#define BS (BB*SS)          // 40448
#define SC (SS*CC)          // 2528
#define S2 (SS*SS)          // 6241
#define S2P 6400            // padded attn row for tensor supp GEMM

// ---------------------------------------------------------------------------
// Scratch (device globals; no runtime allocation allowed)
// ---------------------------------------------------------------------------
__device__ __align__(128) float g_wsum[HH*DD];
__device__ __align__(128) float g_attn[(size_t)BB*HH*S2P];
__device__ __align__(128) float g_comp[(size_t)BB*SC];
__device__ __align__(128) float g_pos [(size_t)BB*MM];
__device__ __align__(128) float g_head[(size_t)BB*HH*MM];

// fp16 buffers
__device__ __align__(128) __half g_q16  [(size_t)BS*EE];
__device__ __align__(128) __half g_k16  [(size_t)BS*EE];
__device__ __align__(128) __half g_v16  [(size_t)BS*EE];
__device__ __align__(128) __half g_aq16 [(size_t)BS*EE];
__device__ __align__(128) __half g_akv16[(size_t)BS*EE];
__device__ __align__(128) __half g_ao16 [(size_t)BS*EE];
__device__ __align__(128) __half g_wqT_h[EE*EE];
__device__ __align__(128) __half g_wkT_h[EE*EE];
__device__ __align__(128) __half g_wvT_h[EE*EE];
__device__ __align__(128) __half g_woT_h[EE*EE];
__device__ __align__(128) __half g_hb16 [BB*HH*MM];
__device__ __align__(128) __half g_spT_h[S2P*MM];

// ---------------------------------------------------------------------------
// PTX helpers (sm_103 non-'a' safe: ldmatrix / mma.sync / cp.async only)
// ---------------------------------------------------------------------------
__device__ __forceinline__ uint32_t smem_u32(const void* p) {
    uint32_t a;
    asm("{ .reg .u64 t; cvta.to.shared.u64 t, %1; cvt.u32.u64 %0, t; }"
        : "=r"(a) : "l"(p));
    return a;
}

#define LDSM4(r, addr)                                                       \
    asm volatile("ldmatrix.sync.aligned.m8n8.x4.shared.b16 {%0,%1,%2,%3}, [%4];" \
        : "=r"((r)[0]), "=r"((r)[1]), "=r"((r)[2]), "=r"((r)[3]) : "r"(addr))

#define MMA_F16(c, a, b0, b1)                                                \
    asm volatile("mma.sync.aligned.m16n8k16.row.col.f32.f16.f16.f32 "        \
        "{%0,%1,%2,%3}, {%4,%5,%6,%7}, {%8,%9}, {%0,%1,%2,%3};"              \
        : "+f"((c)[0]), "+f"((c)[1]), "+f"((c)[2]), "+f"((c)[3])             \
        : "r"((a)[0]), "r"((a)[1]), "r"((a)[2]), "r"((a)[3]), "r"(b0), "r"(b1))

#define CP16(smem, gmem)                                                     \
    asm volatile("cp.async.cg.shared.global [%0], [%1], 16;"                 \
        :: "r"(smem), "l"(gmem))
#define CP_COMMIT() asm volatile("cp.async.commit_group;" ::: "memory")
#define CP_WAIT1()  asm volatile("cp.async.wait_group 1;"  ::: "memory")

// typed pair stores for the GEMM epilogue
__device__ __forceinline__ void store2(float* p, float a, float b) {
    *(float2*)p = make_float2(a, b);
}
__device__ __forceinline__ void store2(__half* p, float a, float b) {
    *(__half2*)p = __floats2half2_rn(a, b);
}

// ---------------------------------------------------------------------------
// HMMA fp16 GEMM core:  C[128,128] tile of A[M,K] @ B_T[N,K]
//   PASSES==1: C = Ah @ Bh^T       PASSES==2: C = Ah @ (Bh+Bl)^T
// TC = float or __half output. 3-stage cp.async pipeline.
// ---------------------------------------------------------------------------
template<int PASSES, typename TC>
__device__ __forceinline__ void
hgemm_core(const __half* __restrict__ Ah, const __half* __restrict__ Bh,
           const __half* __restrict__ Bl, TC* __restrict__ C, int K,
           long long lda, long long ldb, long long ldc,
           long long brow, long long bcol, char* sm)
{
    constexpr uint32_t STG = (PASSES == 1) ? 20480u : 30720u;
    const uint32_t sbase = smem_u32(sm);
    const int tid = threadIdx.x;
    const int warp = tid >> 5, lane = tid & 31;
    const int wm = warp >> 1, wn = warp & 1;

    const int      arow_t = wm*32 + ((lane>>3)&1)*8 + (lane&7);
    const uint32_t akoff  = ((lane>>4)&1)*16;
    const int      nrow_t = wn*64 + ((lane>>4)&1)*8 + (lane&7);
    const uint32_t bkoff  = ((lane>>3)&1)*16;

    const int ld_r0 = (tid + 0)   >> 2, ld_c0 = (tid + 0)   & 3;
    const int ld_r1 = (tid + 256) >> 2, ld_c1 = (tid + 256) & 3;

    float acc[2][8][4];
    #pragma unroll
    for (int i = 0; i < 2; i++)
        #pragma unroll
        for (int j = 0; j < 8; j++)
            #pragma unroll
            for (int l = 0; l < 4; l++) acc[i][j][l] = 0.f;

    const int nIter = K >> 5;

    #define LOAD_STAGE(s, it) do {                                           \
        uint32_t st = sbase + (uint32_t)(s)*STG;                             \
        long long k0 = (long long)(it)*32;                                   \
        uint32_t so0 = (uint32_t)ld_r0*80 + (uint32_t)ld_c0*16;              \
        uint32_t so1 = (uint32_t)ld_r1*80 + (uint32_t)ld_c1*16;              \
        CP16(st + so0,         Ah + (long long)ld_r0*lda + k0 + ld_c0*8);    \
        CP16(st + so1,         Ah + (long long)ld_r1*lda + k0 + ld_c1*8);    \
        CP16(st + 10240 + so0, Bh + (long long)ld_r0*ldb + k0 + ld_c0*8);    \
        CP16(st + 10240 + so1, Bh + (long long)ld_r1*ldb + k0 + ld_c1*8);    \
        if (PASSES >= 2) {                                                   \
            CP16(st + 20480 + so0, Bl + (long long)ld_r0*ldb + k0 + ld_c0*8);\
            CP16(st + 20480 + so1, Bl + (long long)ld_r1*ldb + k0 + ld_c1*8);\
        }                                                                    \
    } while (0)

    LOAD_STAGE(0, 0); CP_COMMIT();
    LOAD_STAGE(1, 1); CP_COMMIT();

    int s_cur = 0, s_ld = 2;
    for (int it = 0; it < nIter; it++) {
        CP_WAIT1();
        __syncthreads();
        if (it + 2 < nIter) LOAD_STAGE(s_ld, it + 2);
        CP_COMMIT();                 // always commit: uniform group counting
        if (++s_ld == 3) s_ld = 0;

        const uint32_t st = sbase + (uint32_t)s_cur*STG;
        if (++s_cur == 3) s_cur = 0;

        #pragma unroll
        for (int kc = 0; kc < 2; kc++) {
            uint32_t ah[2][4];
            #pragma unroll
            for (int mf = 0; mf < 2; mf++)
                LDSM4(ah[mf], st + (uint32_t)(arow_t + mf*16)*80 + kc*32 + akoff);
            #pragma unroll
            for (int nf16 = 0; nf16 < 4; nf16++) {
                uint32_t bh[4], bl[4];
                LDSM4(bh, st + 10240 + (uint32_t)(nrow_t + nf16*16)*80 + kc*32 + bkoff);
                if (PASSES >= 2)
                    LDSM4(bl, st + 20480 + (uint32_t)(nrow_t + nf16*16)*80 + kc*32 + bkoff);
                #pragma unroll
                for (int mf = 0; mf < 2; mf++) {
                    MMA_F16(acc[mf][nf16*2],   ah[mf], bh[0], bh[1]);
                    MMA_F16(acc[mf][nf16*2+1], ah[mf], bh[2], bh[3]);
                    if (PASSES >= 2) {
                        MMA_F16(acc[mf][nf16*2],   ah[mf], bl[0], bl[1]);
                        MMA_F16(acc[mf][nf16*2+1], ah[mf], bl[2], bl[3]);
                    }
                }
            }
        }
    }
    #undef LOAD_STAGE

    const int g = lane >> 2, cc = (lane & 3)*2;
    #pragma unroll
    for (int mf = 0; mf < 2; mf++) {
        #pragma unroll
        for (int nf = 0; nf < 8; nf++) {
            long long row = brow*128 + wm*32 + mf*16 + g;
            long long col = bcol*128 + wn*64 + nf*8 + cc;
            store2(C + row*ldc + col,     acc[mf][nf][0], acc[mf][nf][1]);
            store2(C + (row+8)*ldc + col, acc[mf][nf][2], acc[mf][nf][3]);
        }
    }
}

// batched wrapper
template<int PASSES, typename TC>
__global__ void __launch_bounds__(256, 2)
hgemm_t(const __half* __restrict__ Ah, const __half* __restrict__ Bh,
        const __half* __restrict__ Bl, TC* __restrict__ C, int K,
        long long lda, long long ldb, long long ldc,
        long long aBatch, long long bBatch, long long cBatch)
{
    extern __shared__ char sm[];
    const long long brow = blockIdx.y, bcol = blockIdx.x, bz = blockIdx.z;
    hgemm_core<PASSES, TC>(Ah + bz*aBatch + brow*128*lda,
                           Bh + bz*bBatch + bcol*128*ldb,
                           (PASSES >= 2) ? (Bl + bz*bBatch + bcol*128*ldb)
                                         : (const __half*)nullptr,
                           C + bz*cBatch, K, lda, ldb, ldc, brow, bcol, sm);
}

// fused Q/K/V projections (1-pass fp16, fp16 output)
__global__ void __launch_bounds__(256, 2)
hgemm_qkv(const __half* __restrict__ aq, const __half* __restrict__ akv,
          const __half* __restrict__ wqh, const __half* __restrict__ wkh,
          const __half* __restrict__ wvh,
          __half* __restrict__ qo, __half* __restrict__ ko, __half* __restrict__ vo)
{
    extern __shared__ char sm[];
    const int z = blockIdx.z;
    const long long brow = blockIdx.y, bcol = blockIdx.x;
    const __half* A  = (z == 0) ? aq : akv;
    const __half* Bh = (z == 0) ? wqh : (z == 1) ? wkh : wvh;
    __half* C = (z == 0) ? qo : (z == 1) ? ko : vo;
    hgemm_core<1, __half>(A + brow*128*EE, Bh + bcol*128*EE, nullptr,
                          C, EE, EE, EE, EE, brow, bcol, sm);
}

#define HG_SMEM_P2 (3*30720)   // 92160
#define HG_SMEM_P1 (3*20480)   // 61440

// ---------------------------------------------------------------------------
// activations -> fp16 (both inputs in one launch)
// ---------------------------------------------------------------------------
__global__ void convert_acts(const float* __restrict__ a, const float* __restrict__ b,
                             __half* __restrict__ oa, __half* __restrict__ ob,
                             long long n4)
{
    long long i = (long long)blockIdx.x * blockDim.x + threadIdx.x;
    const float* src; __half* dst; long long j;
    if (i < n4)            { src = a; dst = oa; j = i; }
    else if (i < 2*n4)     { src = b; dst = ob; j = i - n4; }
    else return;
    float4 v = ((const float4*)src)[j];
    ((__half2*)dst)[j*2]     = __floats2half2_rn(v.x, v.y);
    ((__half2*)dst)[j*2 + 1] = __floats2half2_rn(v.z, v.w);
}

__global__ void convert16(const float* __restrict__ x, __half* __restrict__ o,
                          long long n4)
{
    long long i = (long long)blockIdx.x * blockDim.x + threadIdx.x;
    if (i >= n4) return;
    float4 v = ((const float4*)x)[i];
    ((__half2*)o)[i*2]     = __floats2half2_rn(v.x, v.y);
    ((__half2*)o)[i*2 + 1] = __floats2half2_rn(v.z, v.w);
}

// ---------------------------------------------------------------------------
// transpose + fp16 convert (+ optional per-col scale): w[K,N] -> hiT[NT,K]
// ---------------------------------------------------------------------------
__device__ __forceinline__ void
splitT16_body(const float* __restrict__ w, __half* __restrict__ hiT,
              int K, int N, int NT, const float* __restrict__ colscale)
{
    __shared__ float t[32][33];
    const int n0 = blockIdx.x * 32, k0 = blockIdx.y * 32;
    const int tx = threadIdx.x, ty = threadIdx.y;
    for (int i = ty; i < 32; i += 8) {
        int kk = k0 + i, nn = n0 + tx;
        float vv = (kk < K && nn < N) ? w[(long long)kk * N + nn] : 0.f;
        if (colscale && nn < N) vv *= colscale[nn];
        t[i][tx] = vv;
    }
    __syncthreads();
    for (int i = ty; i < 32; i += 8) {
        int nn = n0 + i, kk = k0 + tx;
        if (nn < NT && kk < K)
            hiT[(long long)nn * K + kk] = __float2half(t[tx][i]);
    }
}

__global__ void splitT16(const float* __restrict__ w, __half* __restrict__ hiT,
                         int K, int N, int NT, const float* __restrict__ colscale)
{
    splitT16_body(w, hiT, K, N, NT, colscale);
}

// all three QKV weights (hi only), one launch
__global__ void splitT_qkv3(const float* __restrict__ wq, const float* __restrict__ wk,
                            const float* __restrict__ wv,
                            __half* __restrict__ qh, __half* __restrict__ kh,
                            __half* __restrict__ vh,
                            const float* __restrict__ wsum)
{
    const int z = blockIdx.z;
    const float* w = (z == 0) ? wq : (z == 1) ? wk : wv;
    __half* ho = (z == 0) ? qh : (z == 1) ? kh : vh;
    splitT16_body(w, ho, EE, EE, EE, (z == 0) ? wsum : nullptr);
}

// ---------------------------------------------------------------------------
// w_a row-sum (with 1/sqrt(d) folded)
// ---------------------------------------------------------------------------
__global__ void wsum_kernel(const float* __restrict__ wa, float* __restrict__ wsum)
{
    int i = blockIdx.x * blockDim.x + threadIdx.x;
    if (i < HH*DD) {
        const float* p = wa + (size_t)i * DD;
        float s = 0.f;
        #pragma unroll
        for (int e = 0; e < DD; e++) s += p[e];
        wsum[i] = s * 0.125f;
    }
}

// ---------------------------------------------------------------------------
// comp GEMM, N=32: C[M,32] = A[M,K] @ B[K,32]. 128x32 tile, fp32.
// ---------------------------------------------------------------------------
__global__ __launch_bounds__(256)
void sgemm_n32(const float* __restrict__ A, const float* __restrict__ B,
               float* __restrict__ C, int M, int K)
{
    __shared__ float As[16][129];
    __shared__ float Bs[16][32];

    const int tid = threadIdx.x;
    const int row0 = blockIdx.x * 128;
    const int tx = tid & 7, ty = tid >> 3;
    float acc[4][4] = {};

    for (int k0 = 0; k0 < K; k0 += 16) {
        #pragma unroll
        for (int l = 0; l < 2; l++) {
            int lin = tid + l * 256;
            int ar = lin >> 2, ac4 = (lin & 3) * 4;
            float4 a = *(const float4*)(A + (long long)(row0 + ar) * K + k0 + ac4);
            As[ac4+0][ar] = a.x; As[ac4+1][ar] = a.y;
            As[ac4+2][ar] = a.z; As[ac4+3][ar] = a.w;
        }
        {
            float2 bv = *(const float2*)(B + (long long)(k0 + (tid >> 4)) * 32 + (tid & 15) * 2);
            Bs[tid >> 4][(tid & 15)*2]     = bv.x;
            Bs[tid >> 4][(tid & 15)*2 + 1] = bv.y;
        }
        __syncthreads();
        #pragma unroll
        for (int kk = 0; kk < 16; kk++) {
            float ra[4], rb[4];
            #pragma unroll
            for (int i = 0; i < 4; i++) ra[i] = As[kk][ty*4 + i];
            #pragma unroll
            for (int j = 0; j < 4; j++) rb[j] = Bs[kk][tx*4 + j];
            #pragma unroll
            for (int i = 0; i < 4; i++)
                #pragma unroll
                for (int j = 0; j < 4; j++) acc[i][j] += ra[i] * rb[j];
        }
        __syncthreads();
    }

    #pragma unroll
    for (int i = 0; i < 4; i++) {
        float* crow = C + (long long)(row0 + ty*4 + i) * 32 + tx*4;
        *(float4*)crow = make_float4(acc[i][0], acc[i][1], acc[i][2], acc[i][3]);
    }
}

// ---------------------------------------------------------------------------
// Generic strided/batched SGEMM with optional bias + SiLU (pos/head)
// ---------------------------------------------------------------------------
__global__ __launch_bounds__(256)
void sgemm_gen(const float* __restrict__ A, const float* __restrict__ B,
               float* __restrict__ C,
               int M, int N, int K, int lda, int ldb, int ldc,
               long long aBatch, long long bBatch, long long cBatch,
               const float* __restrict__ bias, long long biasBatch, int act)
{
    __shared__ float As[16][64];
    __shared__ float Bs[16][64];

    const int bz = blockIdx.z;
    A += (long long)bz * aBatch;
    B += (long long)bz * bBatch;
    C += (long long)bz * cBatch;
    const float* biasp = bias ? bias + (long long)bz * biasBatch : nullptr;

    const int row0 = blockIdx.y * 64, col0 = blockIdx.x * 64;
    const int tid = threadIdx.x;
    const int tx = tid & 15, ty = tid >> 4;

    float acc[4][4] = {};

    for (int k0 = 0; k0 < K; k0 += 16) {
        #pragma unroll
        for (int i = 0; i < 4; i++) {
            int lin = tid + i * 256;
            int ar = lin >> 4, ac = lin & 15;
            int gr = row0 + ar, gc = k0 + ac;
            As[ac][ar] = (gr < M && gc < K) ? A[(long long)gr * lda + gc] : 0.f;
        }
        #pragma unroll
        for (int i = 0; i < 4; i++) {
            int lin = tid + i * 256;
            int br = lin >> 6, bc = lin & 63;
            int gr = k0 + br, gc = col0 + bc;
            Bs[br][bc] = (gr < K && gc < N) ? B[(long long)gr * ldb + gc] : 0.f;
        }
        __syncthreads();
        #pragma unroll
        for (int k = 0; k < 16; k++) {
            float ra[4], rb[4];
            #pragma unroll
            for (int i = 0; i < 4; i++) ra[i] = As[k][ty*4 + i];
            #pragma unroll
            for (int j = 0; j < 4; j++) rb[j] = Bs[k][tx*4 + j];
            #pragma unroll
            for (int i = 0; i < 4; i++)
                #pragma unroll
                for (int j = 0; j < 4; j++) acc[i][j] += ra[i] * rb[j];
        }
        __syncthreads();
    }

    #pragma unroll
    for (int i = 0; i < 4; i++) {
        int gr = row0 + ty*4 + i;
        if (gr >= M) continue;
        #pragma unroll
        for (int j = 0; j < 4; j++) {
            int gc = col0 + tx*4 + j;
            if (gc >= N) continue;
            float v = acc[i][j];
            if (biasp) v += biasp[gc];
            if (act == 1) v = v / (1.f + __expf(-v));
            C[(long long)gr * ldc + gc] = v;
        }
    }
}

// ---------------------------------------------------------------------------
// Fused attention: scores (+supp) -> softmax -> P@V -> fp16 output.
// q/k/v inputs are fp16; all compute fp32 in smem/registers.
// ---------------------------------------------------------------------------
#define QKV_LD 68
#define VS_LD  68
#define PS_LD  80
#define ATTN_SMEM ((80*QKV_LD*3 + 80*PS_LD) * 4)   // 90880 B

__global__ void __launch_bounds__(256, 2)
attn_fused(const __half* __restrict__ q, const __half* __restrict__ k,
           const __half* __restrict__ v, const float* __restrict__ attn,
           __half* __restrict__ ao)
{
    extern __shared__ float smf[];
    float* qs = smf;
    float* ks = qs + 80*QKV_LD;
    float* vs = ks + 80*QKV_LD;
    float* ps = vs + 80*VS_LD;

    const int h = blockIdx.x, b = blockIdx.y;
    const int tid = threadIdx.x;

    const __half* qb = q + (long long)b*SS*EE + h*DD;
    const __half* kb = k + (long long)b*SS*EE + h*DD;
    const __half* vb = v + (long long)b*SS*EE + h*DD;

    for (int c = tid; c < 80*16; c += 256) {
        int r = c >> 4, d4 = (c & 15) * 4;
        float4 fq = make_float4(0,0,0,0), fk = fq, fv = fq;
        if (r < SS) {
            __half2 q01 = *(const __half2*)(qb + (long long)r*EE + d4);
            __half2 q23 = *(const __half2*)(qb + (long long)r*EE + d4 + 2);
            __half2 k01 = *(const __half2*)(kb + (long long)r*EE + d4);
            __half2 k23 = *(const __half2*)(kb + (long long)r*EE + d4 + 2);
            __half2 v01 = *(const __half2*)(vb + (long long)r*EE + d4);
            __half2 v23 = *(const __half2*)(vb + (long long)r*EE + d4 + 2);
            float2 a, bb;
            a = __half22float2(q01); bb = __half22float2(q23);
            fq = make_float4(a.x, a.y, bb.x, bb.y);
            a = __half22float2(k01); bb = __half22float2(k23);
            fk = make_float4(a.x, a.y, bb.x, bb.y);
            a = __half22float2(v01); bb = __half22float2(v23);
            fv = make_float4(a.x, a.y, bb.x, bb.y);
        }
        *(float4*)(qs + r*QKV_LD + d4) = fq;
        *(float4*)(ks + r*QKV_LD + d4) = fk;
        *(float4*)(vs + r*VS_LD  + d4) = fv;
    }
    const float* ab = attn + (long long)(b*HH + h)*S2P;
    for (int idx = tid; idx < S2; idx += 256) {
        int t = idx / SS, T = idx - t*SS;
        ps[t*PS_LD + T] = ab[idx];
    }
    __syncthreads();

    // scores
    {
        const int ty = tid >> 4, tx = tid & 15;
        const int t0 = ty*5, T0 = tx*5;
        float acc[5][5];
        #pragma unroll
        for (int i = 0; i < 5; i++)
            #pragma unroll
            for (int j = 0; j < 5; j++) acc[i][j] = 0.f;
        #pragma unroll 2
        for (int d4 = 0; d4 < 16; d4++) {
            float4 qv[5], kv[5];
            #pragma unroll
            for (int i = 0; i < 5; i++)
                qv[i] = *(const float4*)(qs + (t0+i)*QKV_LD + d4*4);
            #pragma unroll
            for (int j = 0; j < 5; j++)
                kv[j] = *(const float4*)(ks + (T0+j)*QKV_LD + d4*4);
            #pragma unroll
            for (int i = 0; i < 5; i++)
                #pragma unroll
                for (int j = 0; j < 5; j++) {
                    acc[i][j] += qv[i].x*kv[j].x;
                    acc[i][j] += qv[i].y*kv[j].y;
                    acc[i][j] += qv[i].z*kv[j].z;
                    acc[i][j] += qv[i].w*kv[j].w;
                }
        }
        #pragma unroll
        for (int i = 0; i < 5; i++)
            #pragma unroll
            for (int j = 0; j < 5; j++)
                ps[(t0+i)*PS_LD + T0+j] += acc[i][j];
    }
    __syncthreads();

    // softmax
    {
        const int warp = tid >> 5, lane = tid & 31;
        for (int r = warp; r < SS; r += 8) {
            float* row = ps + r*PS_LD;
            bool v1 = (lane + 32) < SS, v2 = (lane + 64) < SS;
            float x0 = row[lane];
            float x1 = v1 ? row[lane + 32] : -3.0e38f;
            float x2 = v2 ? row[lane + 64] : -3.0e38f;
            float m = fmaxf(x0, fmaxf(x1, x2));
            #pragma unroll
            for (int o = 16; o > 0; o >>= 1)
                m = fmaxf(m, __shfl_xor_sync(0xffffffffu, m, o));
            float e0 = __expf(x0 - m);
            float e1 = v1 ? __expf(x1 - m) : 0.f;
            float e2 = v2 ? __expf(x2 - m) : 0.f;
            float s = e0 + e1 + e2;
            #pragma unroll
            for (int o = 16; o > 0; o >>= 1)
                s += __shfl_xor_sync(0xffffffffu, s, o);
            float inv = 1.f / s;
            row[lane] = e0 * inv;
            if (v1) row[lane + 32] = e1 * inv;
            if (v2) row[lane + 64] = e2 * inv;
            if (lane == 0) row[SS] = 0.f;
        }
    }
    __syncthreads();

    // P @ V -> fp16
    {
        const int ty = tid >> 4, tx = tid & 15;
        const int t0 = ty*5, d0 = tx*4;
        float acc2[5][4];
        #pragma unroll
        for (int i = 0; i < 5; i++)
            #pragma unroll
            for (int j = 0; j < 4; j++) acc2[i][j] = 0.f;
        #pragma unroll 2
        for (int T4 = 0; T4 < 20; T4++) {
            float4 pr[5];
            #pragma unroll
            for (int i = 0; i < 5; i++)
                pr[i] = *(const float4*)(ps + (t0+i)*PS_LD + T4*4);
            #pragma unroll
            for (int tt = 0; tt < 4; tt++) {
                float4 vv = *(const float4*)(vs + (T4*4+tt)*VS_LD + d0);
                #pragma unroll
                for (int i = 0; i < 5; i++) {
                    float p = (tt == 0) ? pr[i].x : (tt == 1) ? pr[i].y :
                              (tt == 2) ? pr[i].z : pr[i].w;
                    acc2[i][0] += p*vv.x;  acc2[i][1] += p*vv.y;
                    acc2[i][2] += p*vv.z;  acc2[i][3] += p*vv.w;
                }
            }
        }
        #pragma unroll
        for (int i = 0; i < 5; i++) {
            int t = t0 + i;
            if (t >= SS) continue;
            long long base = (long long)b*SS*EE + (long long)t*EE + h*DD + d0;
            __half2 hh01 = __floats2half2_rn(acc2[i][0], acc2[i][1]);
            __half2 hh23 = __floats2half2_rn(acc2[i][2], acc2[i][3]);
            *(__half2*)(ao + base)     = hh01;
            *(__half2*)(ao + base + 2) = hh23;
        }
    }
}

// ---------------------------------------------------------------------------
// Launch
// ---------------------------------------------------------------------------
extern "C" void kernel_launch(void* const* d_in, const int* in_sizes, int n_in,
                              void* d_out, int out_size)
{
    const float* inq   = (const float*)d_in[0];
    const float* inkv  = (const float*)d_in[1];
    const float* wq    = (const float*)d_in[2];
    const float* wk    = (const float*)d_in[3];
    const float* wv    = (const float*)d_in[4];
    const float* wo    = (const float*)d_in[5];
    const float* wa    = (const float*)d_in[6];
    const float* wcmp  = (const float*)d_in[7];
    const float* wpos  = (const float*)d_in[8];
    const float* bpos  = (const float*)d_in[9];
    const float* whead = (const float*)d_in[10];
    const float* bhead = (const float*)d_in[11];
    const float* sproj = (const float*)d_in[12];
    float* out = (float*)d_out;

    float *attn, *wsum, *comp, *pos, *head;
    cudaGetSymbolAddress((void**)&attn, g_attn);
    cudaGetSymbolAddress((void**)&wsum, g_wsum);
    cudaGetSymbolAddress((void**)&comp, g_comp);
    cudaGetSymbolAddress((void**)&pos,  g_pos);
    cudaGetSymbolAddress((void**)&head, g_head);

    __half *q16, *k16, *v16, *aq16, *akv16, *ao16;
    __half *wqTh, *wkTh, *wvTh, *woTh;
    __half *hb16, *spTh;
    cudaGetSymbolAddress((void**)&q16,   g_q16);
    cudaGetSymbolAddress((void**)&k16,   g_k16);
    cudaGetSymbolAddress((void**)&v16,   g_v16);
    cudaGetSymbolAddress((void**)&aq16,  g_aq16);
    cudaGetSymbolAddress((void**)&akv16, g_akv16);
    cudaGetSymbolAddress((void**)&ao16,  g_ao16);
    cudaGetSymbolAddress((void**)&wqTh,  g_wqT_h);
    cudaGetSymbolAddress((void**)&wkTh,  g_wkT_h);
    cudaGetSymbolAddress((void**)&wvTh,  g_wvT_h);
    cudaGetSymbolAddress((void**)&woTh,  g_woT_h);
    cudaGetSymbolAddress((void**)&hb16,  g_hb16);
    cudaGetSymbolAddress((void**)&spTh,  g_spT_h);

    cudaFuncSetAttribute(hgemm_qkv, cudaFuncAttributeMaxDynamicSharedMemorySize, HG_SMEM_P1);
    cudaFuncSetAttribute((const void*)hgemm_t<1,float>,
                         cudaFuncAttributeMaxDynamicSharedMemorySize, HG_SMEM_P1);
    cudaFuncSetAttribute(attn_fused, cudaFuncAttributeMaxDynamicSharedMemorySize, ATTN_SMEM);

    // --- launch index 3 gets profiled by ncu: keep it hgemm_qkv ---
    wsum_kernel<<<1, 1024>>>(wa, wsum);                                  // 0
    {
        long long n4 = (long long)BS * EE / 4;
        convert_acts<<<(unsigned)((2*n4 + 255)/256), 256>>>(inq, inkv, aq16, akv16, n4); // 1
    }
    splitT_qkv3<<<dim3(32, 32, 3), dim3(32, 8)>>>(wq, wk, wv,
        wqTh, wkTh, wvTh, wsum);                                         // 2
    hgemm_qkv<<<dim3(EE/128, BS/128, 3), 256, HG_SMEM_P1>>>(             // 3 (profiled)
        aq16, akv16, wqTh, wkTh, wvTh, q16, k16, v16);

    splitT16<<<dim3(32, 32), dim3(32, 8)>>>(wo, woTh, EE, EE, EE, nullptr);

    // smolgen chain (fp32)
    sgemm_n32<<<BS/128, 256>>>(inq, wcmp, comp, BS, EE);
    sgemm_gen<<<dim3(MM/64, BB/64, 1), 256>>>(
        comp, wpos, pos, BB, MM, SC, SC, MM, MM, 0, 0, 0, bpos, 0, 1);
    sgemm_gen<<<dim3(MM/64, BB/64, HH), 256>>>(
        pos, whead, head, BB, MM, MM, MM, MM, HH*MM,
        0, (long long)MM*MM, MM, bhead, MM, 1);

    // supp: 1-pass fp16
    {
        long long n4 = (long long)BB * HH * MM / 4;
        convert16<<<(unsigned)((n4 + 255)/256), 256>>>(head, hb16, n4);
    }
    splitT16<<<dim3(S2P/32, MM/32), dim3(32, 8)>>>(sproj, spTh, MM, S2, S2P, nullptr);
    hgemm_t<1, float><<<dim3(S2P/128, BB/128, HH), 256, HG_SMEM_P1>>>(
        hb16, spTh, nullptr, attn, MM,
        (long long)HH*MM, MM, (long long)HH*S2P,
        MM, 0, S2P);

    // fused scores + softmax + PV (fp16 in, fp16 out)
    attn_fused<<<dim3(HH, BB), 256, ATTN_SMEM>>>(q16, k16, v16, attn, ao16);

    // output projection: 1-pass fp16
    hgemm_t<1, float><<<dim3(EE/128, BS/128, 1), 256, HG_SMEM_P1>>>(
        ao16, woTh, nullptr, out, EE, EE, EE, EE, 0, 0, 0);
}